// round 1
// baseline (speedup 1.0000x reference)
#include <cuda_runtime.h>
#include <math.h>

#define HIDDEN   1280
#define HEADS    16
#define HDIM     80
#define HALF     40
#define BATCH    2
#define SEQ      2048
#define ROWS     (BATCH*SEQ)        /* 4096 */
#define QKV_COLS (3*HIDDEN)         /* 3840 */

// Scratch (device globals; no runtime allocation allowed)
__device__ float g_qkv[(size_t)ROWS * QKV_COLS];   // 62.9 MB
__device__ float g_attn[(size_t)ROWS * HIDDEN];    // 21.0 MB

// ---------------------------------------------------------------------------
// Tiled fp32 GEMM + bias:  C[M,N] = A[M,K] @ B[K,N] + bias[N]
// BM=BN=64, BK=16, 256 threads, 4x4 micro-tile. M,N,K all divisible here.
// ---------------------------------------------------------------------------
template<int BM, int BN, int BK, int TM, int TN>
__global__ void gemm_bias_kernel(const float* __restrict__ A,
                                 const float* __restrict__ B,
                                 const float* __restrict__ bias,
                                 float* __restrict__ C,
                                 int M, int N, int K)
{
    __shared__ float As[BK][BM + 1];   // +1 pad: conflict-free transposed store
    __shared__ float Bs[BK][BN];

    const int tid  = threadIdx.x;                 // 0..255
    const int tr   = tid / (BN / TN);             // 0..15
    const int tc   = tid % (BN / TN);             // 0..15
    const int rowB = blockIdx.y * BM;
    const int colB = blockIdx.x * BN;

    float acc[TM][TN];
    #pragma unroll
    for (int i = 0; i < TM; i++)
        #pragma unroll
        for (int j = 0; j < TN; j++) acc[i][j] = 0.f;

    for (int k0 = 0; k0 < K; k0 += BK) {
        // Load A tile (BM x BK) transposed into smem
        #pragma unroll
        for (int i = tid; i < BM * BK; i += 256) {
            int r = i / BK, c = i % BK;
            As[c][r] = A[(size_t)(rowB + r) * K + k0 + c];
        }
        // Load B tile (BK x BN)
        #pragma unroll
        for (int i = tid; i < BK * BN; i += 256) {
            int r = i / BN, c = i % BN;
            Bs[r][c] = B[(size_t)(k0 + r) * N + colB + c];
        }
        __syncthreads();

        #pragma unroll
        for (int kk = 0; kk < BK; kk++) {
            float a[TM], b[TN];
            #pragma unroll
            for (int i = 0; i < TM; i++) a[i] = As[kk][tr * TM + i];
            #pragma unroll
            for (int j = 0; j < TN; j++) b[j] = Bs[kk][tc * TN + j];
            #pragma unroll
            for (int i = 0; i < TM; i++)
                #pragma unroll
                for (int j = 0; j < TN; j++) acc[i][j] += a[i] * b[j];
        }
        __syncthreads();
    }

    #pragma unroll
    for (int i = 0; i < TM; i++) {
        int r = rowB + tr * TM + i;
        #pragma unroll
        for (int j = 0; j < TN; j++) {
            int c = colB + tc * TN + j;
            C[(size_t)r * N + c] = acc[i][j] + bias[c];
        }
    }
}

// ---------------------------------------------------------------------------
// RoPE applied in-place to Q and K slices of g_qkv.
// One thread per (b, n, q/k, head, d<HALF) pair; writes both halves.
// ---------------------------------------------------------------------------
__global__ void rope_kernel(float* __restrict__ qkv,
                            const float* __restrict__ cosp,
                            const float* __restrict__ sinp)
{
    int idx = blockIdx.x * blockDim.x + threadIdx.x;
    const int total = BATCH * SEQ * 2 * HEADS * HALF;
    if (idx >= total) return;

    int d  = idx % HALF;  idx /= HALF;
    int h  = idx % HEADS; idx /= HEADS;
    int qk = idx % 2;     idx /= 2;
    int n  = idx % SEQ;
    int b  = idx / SEQ;

    float* row = qkv + (size_t)(b * SEQ + n) * QKV_COLS + qk * HIDDEN + h * HDIM;
    float lo = row[d];
    float hi = row[d + HALF];
    float cl = cosp[n * HDIM + d];
    float ch = cosp[n * HDIM + d + HALF];
    float sl = sinp[n * HDIM + d];
    float sh = sinp[n * HDIM + d + HALF];
    // rotate_half: rot[d] = -x[d+HALF] (d<HALF), rot[d] = x[d-HALF] (d>=HALF)
    row[d]        = lo * cl - hi * sl;
    row[d + HALF] = hi * ch + lo * sh;
}

// ---------------------------------------------------------------------------
// Attention: one block per (b, h, q) row. 128 threads.
// Pass 1: scores over all 2048 keys (K tiles of 128 rows through padded smem),
//         scores live in 16 registers/thread.
// Softmax: two block reductions.
// Pass 2: out[d] = sum_k p_k * v[k][d], V tiles through smem, 80 active lanes.
// ---------------------------------------------------------------------------
__global__ void attn_kernel(const float* __restrict__ qkv,
                            float* __restrict__ out)
{
    constexpr int TILE = 128;
    constexpr int NT   = SEQ / TILE;   // 16
    constexpr int LDT  = 81;           // padded row stride (coprime with 32)

    __shared__ float qs[HDIM];
    __shared__ float tile[TILE * LDT]; // 41.5 KB
    __shared__ float red[128];
    __shared__ float ps[TILE];

    const int tid = threadIdx.x;
    const int qi  = blockIdx.x & (SEQ - 1);
    const int bh  = blockIdx.x >> 11;
    const int h   = bh & (HEADS - 1);
    const int b   = bh >> 4;

    const float* base = qkv + (size_t)(b * SEQ) * QKV_COLS;
    const float* qrow = base + (size_t)qi * QKV_COLS + h * HDIM;
    if (tid < HDIM) qs[tid] = qrow[tid];

    const float scale = rsqrtf((float)HDIM);
    float s[NT];

    // ---- scores ----
    for (int t = 0; t < NT; t++) {
        __syncthreads();   // protects qs (t==0) and tile reuse
        const float* kbase = base + (size_t)(t * TILE) * QKV_COLS + HIDDEN + h * HDIM;
        for (int i = tid; i < TILE * HDIM; i += 128) {
            int r = i / HDIM, c = i - r * HDIM;
            tile[r * LDT + c] = kbase[(size_t)r * QKV_COLS + c];
        }
        __syncthreads();
        float acc = 0.f;
        #pragma unroll
        for (int d = 0; d < HDIM; d++)
            acc += qs[d] * tile[tid * LDT + d];
        s[t] = acc * scale;
    }

    // ---- softmax ----
    float m = -INFINITY;
    #pragma unroll
    for (int t = 0; t < NT; t++) m = fmaxf(m, s[t]);
    red[tid] = m;
    __syncthreads();
    for (int o = 64; o > 0; o >>= 1) {
        if (tid < o) red[tid] = fmaxf(red[tid], red[tid + o]);
        __syncthreads();
    }
    m = red[0];
    __syncthreads();

    float lsum = 0.f;
    #pragma unroll
    for (int t = 0; t < NT; t++) {
        s[t] = __expf(s[t] - m);
        lsum += s[t];
    }
    red[tid] = lsum;
    __syncthreads();
    for (int o = 64; o > 0; o >>= 1) {
        if (tid < o) red[tid] += red[tid + o];
        __syncthreads();
    }
    const float inv = 1.f / red[0];

    // ---- V accumulation ----
    float acc = 0.f;
    for (int t = 0; t < NT; t++) {
        __syncthreads();   // protect tile + ps reuse
        const float* vbase = base + (size_t)(t * TILE) * QKV_COLS + 2 * HIDDEN + h * HDIM;
        for (int i = tid; i < TILE * HDIM; i += 128) {
            int r = i / HDIM, c = i - r * HDIM;
            tile[r * LDT + c] = vbase[(size_t)r * QKV_COLS + c];
        }
        ps[tid] = s[t];
        __syncthreads();
        if (tid < HDIM) {
            #pragma unroll 8
            for (int r = 0; r < TILE; r++)
                acc += ps[r] * tile[r * LDT + tid];
        }
    }

    if (tid < HDIM)
        out[(size_t)(b * SEQ + qi) * HIDDEN + h * HDIM + tid] = acc * inv;
}

// ---------------------------------------------------------------------------
extern "C" void kernel_launch(void* const* d_in, const int* in_sizes, int n_in,
                              void* d_out, int out_size)
{
    const float* x      = (const float*)d_in[0];
    const float* cosp   = (const float*)d_in[1];
    const float* sinp   = (const float*)d_in[2];
    const float* qkv_w  = (const float*)d_in[3];
    const float* qkv_b  = (const float*)d_in[4];
    const float* proj_w = (const float*)d_in[5];
    const float* proj_b = (const float*)d_in[6];
    float* out = (float*)d_out;

    float *qkv_buf, *attn_buf;
    cudaGetSymbolAddress((void**)&qkv_buf,  g_qkv);
    cudaGetSymbolAddress((void**)&attn_buf, g_attn);

    // 1) QKV GEMM: [4096,1280] @ [1280,3840] + bias
    {
        dim3 grid(QKV_COLS / 64, ROWS / 64);   // (60, 64)
        gemm_bias_kernel<64, 64, 16, 4, 4><<<grid, 256>>>(
            x, qkv_w, qkv_b, qkv_buf, ROWS, QKV_COLS, HIDDEN);
    }

    // 2) RoPE on Q and K
    {
        int total = BATCH * SEQ * 2 * HEADS * HALF;   // 5,242,880
        rope_kernel<<<(total + 255) / 256, 256>>>(qkv_buf, cosp, sinp);
    }

    // 3) Attention: one block per (b,h,q)
    {
        dim3 grid(BATCH * HEADS * SEQ);   // 65536
        attn_kernel<<<grid, 128>>>(qkv_buf, attn_buf);
    }

    // 4) Proj GEMM: [4096,1280] @ [1280,1280] + bias -> d_out
    {
        dim3 grid(HIDDEN / 64, ROWS / 64);     // (20, 64)
        gemm_bias_kernel<64, 64, 16, 4, 4><<<grid, 256>>>(
            attn_buf, proj_w, proj_b, out, ROWS, HIDDEN, HIDDEN);
    }
}

// round 2
// speedup vs baseline: 9.0032x; 9.0032x over previous
#include <cuda_runtime.h>
#include <math.h>

#define HIDDEN   1280
#define HEADS    16
#define HDIM     80
#define HALF     40
#define BATCH    2
#define SEQ      2048
#define ROWS     (BATCH*SEQ)        /* 4096 */
#define QKV_COLS (3*HIDDEN)         /* 3840 */

// Scratch (device globals; no runtime allocation allowed)
__device__ float g_qkv[(size_t)ROWS * QKV_COLS];   // 62.9 MB
__device__ float g_attn[(size_t)ROWS * HIDDEN];    // 21.0 MB

// ---------------------------------------------------------------------------
// Tiled fp32 GEMM + bias:  C[M,N] = A[M,K] @ B[K,N] + bias[N]
// ---------------------------------------------------------------------------
template<int BM, int BN, int BK, int TM, int TN>
__global__ __launch_bounds__(256)
void gemm_bias_kernel(const float* __restrict__ A,
                      const float* __restrict__ B,
                      const float* __restrict__ bias,
                      float* __restrict__ C,
                      int M, int N, int K)
{
    __shared__ float As[BK][BM + 1];
    __shared__ float Bs[BK][BN];

    const int tid  = threadIdx.x;
    const int tr   = tid / (BN / TN);
    const int tc   = tid % (BN / TN);
    const int rowB = blockIdx.y * BM;
    const int colB = blockIdx.x * BN;

    float acc[TM][TN];
    #pragma unroll
    for (int i = 0; i < TM; i++)
        #pragma unroll
        for (int j = 0; j < TN; j++) acc[i][j] = 0.f;

    for (int k0 = 0; k0 < K; k0 += BK) {
        #pragma unroll
        for (int i = tid; i < BM * BK; i += 256) {
            int r = i / BK, c = i % BK;
            As[c][r] = A[(size_t)(rowB + r) * K + k0 + c];
        }
        #pragma unroll
        for (int i = tid; i < BK * BN; i += 256) {
            int r = i / BN, c = i % BN;
            Bs[r][c] = B[(size_t)(k0 + r) * N + colB + c];
        }
        __syncthreads();

        #pragma unroll
        for (int kk = 0; kk < BK; kk++) {
            float a[TM], b[TN];
            #pragma unroll
            for (int i = 0; i < TM; i++) a[i] = As[kk][tr * TM + i];
            #pragma unroll
            for (int j = 0; j < TN; j++) b[j] = Bs[kk][tc * TN + j];
            #pragma unroll
            for (int i = 0; i < TM; i++)
                #pragma unroll
                for (int j = 0; j < TN; j++) acc[i][j] += a[i] * b[j];
        }
        __syncthreads();
    }

    #pragma unroll
    for (int i = 0; i < TM; i++) {
        int r = rowB + tr * TM + i;
        #pragma unroll
        for (int j = 0; j < TN; j++) {
            int c = colB + tc * TN + j;
            C[(size_t)r * N + c] = acc[i][j] + bias[c];
        }
    }
}

// ---------------------------------------------------------------------------
// RoPE applied in-place to Q and K slices of g_qkv.
// ---------------------------------------------------------------------------
__global__ void rope_kernel(float* __restrict__ qkv,
                            const float* __restrict__ cosp,
                            const float* __restrict__ sinp)
{
    int idx = blockIdx.x * blockDim.x + threadIdx.x;
    const int total = BATCH * SEQ * 2 * HEADS * HALF;
    if (idx >= total) return;

    int d  = idx % HALF;  idx /= HALF;
    int h  = idx % HEADS; idx /= HEADS;
    int qk = idx % 2;     idx /= 2;
    int n  = idx % SEQ;
    int b  = idx / SEQ;

    float* row = qkv + (size_t)(b * SEQ + n) * QKV_COLS + qk * HIDDEN + h * HDIM;
    float lo = row[d];
    float hi = row[d + HALF];
    float cl = cosp[n * HDIM + d];
    float ch = cosp[n * HDIM + d + HALF];
    float sl = sinp[n * HDIM + d];
    float sh = sinp[n * HDIM + d + HALF];
    row[d]        = lo * cl - hi * sl;
    row[d + HALF] = hi * ch + lo * sh;
}

// ---------------------------------------------------------------------------
// Flash attention: one block per (b, h, 64-query tile). 256 threads.
// Q tile (64x80) loaded once; loop over 32 K/V tiles of 64 keys.
// S = Q.K^T via 4x4 register tiles; online softmax; O (4x5 regs) += P.V.
// ---------------------------------------------------------------------------
#define BQ   64
#define BKT  64
#define LDQ  65   /* padded stride for transposed Q/K tiles */
#define LDP  65   /* padded stride for P tile */

// dynamic smem layout (floats):
//   Qt  [HDIM][LDQ]     80*65 = 5200
//   Kt  [HDIM][LDQ]     80*65 = 5200
//   Vs  [BKT][HDIM]     64*80 = 5120
//   Ps  [BQ][LDP]       64*65 = 4160
//   pmax[4][64]                  256
//   psum[4][64]                  256
//   m_s [64], l_s[64], al_s[64]  192
#define SM_FLOATS (5200 + 5200 + 5120 + 4160 + 256 + 256 + 192)

__global__ __launch_bounds__(256, 2)
void flash_attn_kernel(const float* __restrict__ qkv,
                       float* __restrict__ out)
{
    extern __shared__ float sm[];
    float* Qt   = sm;
    float* Kt   = Qt + HDIM * LDQ;
    float* Vs   = Kt + HDIM * LDQ;
    float* Ps   = Vs + BKT * HDIM;
    float* pmax = Ps + BQ * LDP;
    float* psum = pmax + 4 * 64;
    float* m_s  = psum + 4 * 64;
    float* l_s  = m_s + 64;
    float* al_s = l_s + 64;

    const int tid = threadIdx.x;
    const int tr  = tid >> 4;       // 0..15  (4 query rows each)
    const int tc  = tid & 15;       // 0..15
    const int q0  = blockIdx.x * BQ;
    const int h   = blockIdx.y & (HEADS - 1);
    const int b   = blockIdx.y >> 4;

    const float* base = qkv + (size_t)(b * SEQ) * QKV_COLS;
    const float scale = rsqrtf((float)HDIM);

    // Load Q tile transposed (k-major), pre-scaled. Reused for all K tiles.
    for (int i = tid; i < BQ * HDIM; i += 256) {
        int r = i / HDIM, d = i - r * HDIM;
        Qt[d * LDQ + r] = base[(size_t)(q0 + r) * QKV_COLS + h * HDIM + d] * scale;
    }
    if (tid < 64) { m_s[tid] = -INFINITY; l_s[tid] = 0.f; }

    float acc[4][5];
    #pragma unroll
    for (int i = 0; i < 4; i++)
        #pragma unroll
        for (int j = 0; j < 5; j++) acc[i][j] = 0.f;

    for (int t = 0; t < SEQ / BKT; t++) {
        __syncthreads();   // previous PV done; Qt ready on t==0

        // Load K tile transposed + V tile natural
        const float* kb = base + (size_t)(t * BKT) * QKV_COLS + HIDDEN + h * HDIM;
        const float* vb = base + (size_t)(t * BKT) * QKV_COLS + 2 * HIDDEN + h * HDIM;
        for (int i = tid; i < BKT * HDIM; i += 256) {
            int r = i / HDIM, d = i - r * HDIM;
            Kt[d * LDQ + r]  = kb[(size_t)r * QKV_COLS + d];
            Vs[r * HDIM + d] = vb[(size_t)r * QKV_COLS + d];
        }
        __syncthreads();

        // ---- S = Q.K^T (64x64), 4x4 per thread ----
        float s[4][4];
        #pragma unroll
        for (int i = 0; i < 4; i++)
            #pragma unroll
            for (int j = 0; j < 4; j++) s[i][j] = 0.f;

        #pragma unroll 8
        for (int k = 0; k < HDIM; k++) {
            float a[4], bb[4];
            #pragma unroll
            for (int i = 0; i < 4; i++) a[i]  = Qt[k * LDQ + tr * 4 + i];
            #pragma unroll
            for (int j = 0; j < 4; j++) bb[j] = Kt[k * LDQ + tc * 4 + j];
            #pragma unroll
            for (int i = 0; i < 4; i++)
                #pragma unroll
                for (int j = 0; j < 4; j++) s[i][j] += a[i] * bb[j];
        }
        #pragma unroll
        for (int i = 0; i < 4; i++)
            #pragma unroll
            for (int j = 0; j < 4; j++)
                Ps[(tr * 4 + i) * LDP + tc * 4 + j] = s[i][j];
        __syncthreads();

        // ---- online softmax: partial row max (4 threads per row) ----
        {
            int srow = tid & 63, sch = tid >> 6;
            const float* pr = Ps + srow * LDP + sch * 16;
            float mx = pr[0];
            #pragma unroll
            for (int c = 1; c < 16; c++) mx = fmaxf(mx, pr[c]);
            pmax[sch * 64 + srow] = mx;
        }
        __syncthreads();
        if (tid < 64) {
            float mt = fmaxf(fmaxf(pmax[tid], pmax[64 + tid]),
                             fmaxf(pmax[128 + tid], pmax[192 + tid]));
            float mo = m_s[tid];
            float mn = fmaxf(mo, mt);
            m_s[tid]  = mn;
            al_s[tid] = __expf(mo - mn);
        }
        __syncthreads();
        {
            int srow = tid & 63, sch = tid >> 6;
            float mn = m_s[srow];
            float* pr = Ps + srow * LDP + sch * 16;
            float sum = 0.f;
            #pragma unroll
            for (int c = 0; c < 16; c++) {
                float p = __expf(pr[c] - mn);
                pr[c] = p;
                sum += p;
            }
            psum[sch * 64 + srow] = sum;
        }
        __syncthreads();
        if (tid < 64) {
            l_s[tid] = l_s[tid] * al_s[tid]
                     + psum[tid] + psum[64 + tid] + psum[128 + tid] + psum[192 + tid];
        }

        // ---- rescale O, then O += P.V ----
        #pragma unroll
        for (int i = 0; i < 4; i++) {
            float al = al_s[tr * 4 + i];
            #pragma unroll
            for (int j = 0; j < 5; j++) acc[i][j] *= al;
        }
        #pragma unroll 8
        for (int k = 0; k < BKT; k++) {
            float p[4], v[5];
            #pragma unroll
            for (int i = 0; i < 4; i++) p[i] = Ps[(tr * 4 + i) * LDP + k];
            #pragma unroll
            for (int j = 0; j < 5; j++) v[j] = Vs[k * HDIM + tc * 5 + j];
            #pragma unroll
            for (int i = 0; i < 4; i++)
                #pragma unroll
                for (int j = 0; j < 5; j++) acc[i][j] += p[i] * v[j];
        }
    }
    __syncthreads();   // l_s final

    #pragma unroll
    for (int i = 0; i < 4; i++) {
        float invl = 1.f / l_s[tr * 4 + i];
        int r = q0 + tr * 4 + i;
        #pragma unroll
        for (int j = 0; j < 5; j++)
            out[(size_t)(b * SEQ + r) * HIDDEN + h * HDIM + tc * 5 + j] = acc[i][j] * invl;
    }
}

// ---------------------------------------------------------------------------
extern "C" void kernel_launch(void* const* d_in, const int* in_sizes, int n_in,
                              void* d_out, int out_size)
{
    const float* x      = (const float*)d_in[0];
    const float* cosp   = (const float*)d_in[1];
    const float* sinp   = (const float*)d_in[2];
    const float* qkv_w  = (const float*)d_in[3];
    const float* qkv_b  = (const float*)d_in[4];
    const float* proj_w = (const float*)d_in[5];
    const float* proj_b = (const float*)d_in[6];
    float* out = (float*)d_out;

    float *qkv_buf, *attn_buf;
    cudaGetSymbolAddress((void**)&qkv_buf,  g_qkv);
    cudaGetSymbolAddress((void**)&attn_buf, g_attn);

    // 1) QKV GEMM: [4096,1280] @ [1280,3840] + bias
    {
        dim3 grid(QKV_COLS / 64, ROWS / 64);
        gemm_bias_kernel<64, 64, 16, 4, 4><<<grid, 256>>>(
            x, qkv_w, qkv_b, qkv_buf, ROWS, QKV_COLS, HIDDEN);
    }

    // 2) RoPE on Q and K
    {
        int total = BATCH * SEQ * 2 * HEADS * HALF;
        rope_kernel<<<(total + 255) / 256, 256>>>(qkv_buf, cosp, sinp);
    }

    // 3) Flash attention: one block per (b,h, 64-query tile)
    {
        static int smem_set = 0;
        if (!smem_set) {
            cudaFuncSetAttribute(flash_attn_kernel,
                                 cudaFuncAttributeMaxDynamicSharedMemorySize,
                                 SM_FLOATS * sizeof(float));
            smem_set = 1;
        }
        dim3 grid(SEQ / BQ, BATCH * HEADS);   // (32, 32)
        flash_attn_kernel<<<grid, 256, SM_FLOATS * sizeof(float)>>>(qkv_buf, attn_buf);
    }

    // 4) Proj GEMM: [4096,1280] @ [1280,1280] + bias -> d_out
    {
        dim3 grid(HIDDEN / 64, ROWS / 64);
        gemm_bias_kernel<64, 64, 16, 4, 4><<<grid, 256>>>(
            attn_buf, proj_w, proj_b, out, ROWS, HIDDEN, HIDDEN);
    }
}

// round 3
// speedup vs baseline: 13.4811x; 1.4974x over previous
#include <cuda_runtime.h>
#include <math.h>
#include <stdint.h>

#define HIDDEN   1280
#define HEADS    16
#define HDIM     80
#define HALF     40
#define BATCH    2
#define SEQ      2048
#define ROWS     (BATCH*SEQ)        /* 4096 */
#define QKV_COLS (3*HIDDEN)         /* 3840 */

// Scratch (device globals; no runtime allocation allowed)
__device__ float g_qkv[(size_t)ROWS * QKV_COLS];   // 62.9 MB
__device__ float g_attn[(size_t)ROWS * HIDDEN];    // 21.0 MB

// ---------------------------------------------------------------------------
// Tiled fp32 GEMM + bias:  C[M,N] = A[M,K] @ B[K,N] + bias[N]   (unchanged)
// ---------------------------------------------------------------------------
template<int BM, int BN, int BK, int TM, int TN>
__global__ __launch_bounds__(256)
void gemm_bias_kernel(const float* __restrict__ A,
                      const float* __restrict__ B,
                      const float* __restrict__ bias,
                      float* __restrict__ C,
                      int M, int N, int K)
{
    __shared__ float As[BK][BM + 1];
    __shared__ float Bs[BK][BN];

    const int tid  = threadIdx.x;
    const int tr   = tid / (BN / TN);
    const int tc   = tid % (BN / TN);
    const int rowB = blockIdx.y * BM;
    const int colB = blockIdx.x * BN;

    float acc[TM][TN];
    #pragma unroll
    for (int i = 0; i < TM; i++)
        #pragma unroll
        for (int j = 0; j < TN; j++) acc[i][j] = 0.f;

    for (int k0 = 0; k0 < K; k0 += BK) {
        #pragma unroll
        for (int i = tid; i < BM * BK; i += 256) {
            int r = i / BK, c = i % BK;
            As[c][r] = A[(size_t)(rowB + r) * K + k0 + c];
        }
        #pragma unroll
        for (int i = tid; i < BK * BN; i += 256) {
            int r = i / BN, c = i % BN;
            Bs[r][c] = B[(size_t)(k0 + r) * N + colB + c];
        }
        __syncthreads();

        #pragma unroll
        for (int kk = 0; kk < BK; kk++) {
            float a[TM], b[TN];
            #pragma unroll
            for (int i = 0; i < TM; i++) a[i] = As[kk][tr * TM + i];
            #pragma unroll
            for (int j = 0; j < TN; j++) b[j] = Bs[kk][tc * TN + j];
            #pragma unroll
            for (int i = 0; i < TM; i++)
                #pragma unroll
                for (int j = 0; j < TN; j++) acc[i][j] += a[i] * b[j];
        }
        __syncthreads();
    }

    #pragma unroll
    for (int i = 0; i < TM; i++) {
        int r = rowB + tr * TM + i;
        #pragma unroll
        for (int j = 0; j < TN; j++) {
            int c = colB + tc * TN + j;
            C[(size_t)r * N + c] = acc[i][j] + bias[c];
        }
    }
}

// ---------------------------------------------------------------------------
// RoPE applied in-place to Q and K slices of g_qkv.  (unchanged)
// ---------------------------------------------------------------------------
__global__ void rope_kernel(float* __restrict__ qkv,
                            const float* __restrict__ cosp,
                            const float* __restrict__ sinp)
{
    int idx = blockIdx.x * blockDim.x + threadIdx.x;
    const int total = BATCH * SEQ * 2 * HEADS * HALF;
    if (idx >= total) return;

    int d  = idx % HALF;  idx /= HALF;
    int h  = idx % HEADS; idx /= HEADS;
    int qk = idx % 2;     idx /= 2;
    int n  = idx % SEQ;
    int b  = idx / SEQ;

    float* row = qkv + (size_t)(b * SEQ + n) * QKV_COLS + qk * HIDDEN + h * HDIM;
    float lo = row[d];
    float hi = row[d + HALF];
    float cl = cosp[n * HDIM + d];
    float ch = cosp[n * HDIM + d + HALF];
    float sl = sinp[n * HDIM + d];
    float sh = sinp[n * HDIM + d + HALF];
    row[d]        = lo * cl - hi * sl;
    row[d + HALF] = hi * ch + lo * sh;
}

// ---------------------------------------------------------------------------
// TF32 tensor-core flash attention.
// Block: 128 queries, 8 warps, 256 threads. Warp w owns query rows
// [w*16, w*16+16) -> softmax entirely warp-private.
// Per iter (64 keys): S(16x64) = Qfrag x K via mma.sync tf32; online softmax
// in registers; P through warp-private smem strip; O(16x80) += P x V.
// K/V tiles double-buffered with cp.async.
// ---------------------------------------------------------------------------
#define BQ      128
#define BKT     64
#define NITER   (SEQ / BKT)         /* 32 */
#define LDK     84                  /* K/V tile row stride (floats) */
#define LDP     68                  /* P strip row stride */
#define QS_FLOATS   (BQ * LDK)      /* 10752, aliased by P strips */
#define KT_FLOATS   (BKT * LDK)     /* 5376 per buffer */
#define ATTN_SMEM_FLOATS (QS_FLOATS + 4 * KT_FLOATS)   /* 32256 -> 129 KB */

__device__ __forceinline__ void mma_tf32(float* d,
                                         const float* a, const float* b,
                                         const float* c)
{
    asm volatile(
        "mma.sync.aligned.m16n8k8.row.col.f32.tf32.tf32.f32 "
        "{%0,%1,%2,%3}, {%4,%5,%6,%7}, {%8,%9}, {%10,%11,%12,%13};\n"
        : "=f"(d[0]), "=f"(d[1]), "=f"(d[2]), "=f"(d[3])
        : "r"(__float_as_uint(a[0])), "r"(__float_as_uint(a[1])),
          "r"(__float_as_uint(a[2])), "r"(__float_as_uint(a[3])),
          "r"(__float_as_uint(b[0])), "r"(__float_as_uint(b[1])),
          "f"(c[0]), "f"(c[1]), "f"(c[2]), "f"(c[3]));
}

__device__ __forceinline__ void cp_async16(void* smem_dst, const void* gmem_src)
{
    uint32_t s = (uint32_t)__cvta_generic_to_shared(smem_dst);
    asm volatile("cp.async.cg.shared.global [%0], [%1], 16;\n"
                 :: "r"(s), "l"(gmem_src) : "memory");
}
__device__ __forceinline__ void cp_commit()
{
    asm volatile("cp.async.commit_group;\n" ::: "memory");
}

__global__ __launch_bounds__(256, 1)
void flash_attn_tc_kernel(const float* __restrict__ qkv,
                          float* __restrict__ out)
{
    extern __shared__ float sm[];
    float* Qs = sm;                       // [BQ][LDK], aliased by P strips later
    float* Ks = sm + QS_FLOATS;           // 2 x [BKT][LDK]
    float* Vs = Ks + 2 * KT_FLOATS;       // 2 x [BKT][LDK]

    const int tid  = threadIdx.x;
    const int w    = tid >> 5;
    const int lane = tid & 31;
    const int g    = lane >> 2;           // group id (row within tile)
    const int t    = lane & 3;            // thread-in-group

    const int q0 = blockIdx.x * BQ;
    const int h  = blockIdx.y & (HEADS - 1);
    const int b  = blockIdx.y >> 4;

    const float* base = qkv + (size_t)(b * SEQ) * QKV_COLS;
    // fold 1/sqrt(HDIM) and log2(e) into Q so softmax uses exp2
    const float SCL = rsqrtf((float)HDIM) * 1.44269504f;

    // ---- load Q tile (scaled) into smem ----
    {
        const float* qb = base + h * HDIM;
        for (int i = tid; i < BQ * (HDIM / 4); i += 256) {
            int r = i / (HDIM / 4), c4 = i - r * (HDIM / 4);
            float4 v = *(const float4*)(qb + (size_t)(q0 + r) * QKV_COLS + c4 * 4);
            v.x *= SCL; v.y *= SCL; v.z *= SCL; v.w *= SCL;
            *(float4*)(Qs + r * LDK + c4 * 4) = v;
        }
    }
    __syncthreads();

    // ---- hoist Q fragments into registers (10 k-steps x 4 regs) ----
    float qf[10][4];
    {
        const int r0 = w * 16 + g;
        #pragma unroll
        for (int ks = 0; ks < 10; ks++) {
            int c = ks * 8 + t;
            qf[ks][0] = Qs[r0 * LDK + c];
            qf[ks][1] = Qs[(r0 + 8) * LDK + c];
            qf[ks][2] = Qs[r0 * LDK + c + 4];
            qf[ks][3] = Qs[(r0 + 8) * LDK + c + 4];
        }
    }
    __syncthreads();   // Qs now dead -> reuse as P strips

    float* Pw = Qs + w * 16 * LDP;        // warp-private P strip [16][LDP]

    float of[10][4];
    #pragma unroll
    for (int i = 0; i < 10; i++)
        #pragma unroll
        for (int j = 0; j < 4; j++) of[i][j] = 0.f;
    float m1 = -INFINITY, m2 = -INFINITY, l1 = 0.f, l2 = 0.f;

    const float* kb0 = base + HIDDEN + h * HDIM;
    const float* vb0 = base + 2 * HIDDEN + h * HDIM;

    // prefetch tile 0
    {
        const float* kb = kb0;
        const float* vb = vb0;
        #pragma unroll
        for (int j = 0; j < 10; j++) {
            int idx = tid + j * 256;
            if (idx < 1280) {
                int r = idx / 20, c = idx - r * 20;
                cp_async16(Ks + r * LDK + c * 4, kb + (size_t)r * QKV_COLS + c * 4);
            } else {
                int i2 = idx - 1280;
                int r = i2 / 20, c = i2 - r * 20;
                cp_async16(Vs + r * LDK + c * 4, vb + (size_t)r * QKV_COLS + c * 4);
            }
        }
        cp_commit();
    }

    for (int it = 0; it < NITER; it++) {
        // prefetch next tile into alternate buffer
        if (it + 1 < NITER) {
            float* Kd = Ks + ((it + 1) & 1) * KT_FLOATS;
            float* Vd = Vs + ((it + 1) & 1) * KT_FLOATS;
            const float* kb = kb0 + (size_t)((it + 1) * BKT) * QKV_COLS;
            const float* vb = vb0 + (size_t)((it + 1) * BKT) * QKV_COLS;
            #pragma unroll
            for (int j = 0; j < 10; j++) {
                int idx = tid + j * 256;
                if (idx < 1280) {
                    int r = idx / 20, c = idx - r * 20;
                    cp_async16(Kd + r * LDK + c * 4, kb + (size_t)r * QKV_COLS + c * 4);
                } else {
                    int i2 = idx - 1280;
                    int r = i2 / 20, c = i2 - r * 20;
                    cp_async16(Vd + r * LDK + c * 4, vb + (size_t)r * QKV_COLS + c * 4);
                }
            }
            cp_commit();
            asm volatile("cp.async.wait_group 1;\n" ::: "memory");
        } else {
            asm volatile("cp.async.wait_group 0;\n" ::: "memory");
        }
        __syncthreads();

        const float* Kt = Ks + (it & 1) * KT_FLOATS;
        const float* Vt = Vs + (it & 1) * KT_FLOATS;

        // ---- S = Q x K^T : 8 n-tiles x 10 k-steps ----
        float sacc[8][4];
        #pragma unroll
        for (int nt = 0; nt < 8; nt++)
            #pragma unroll
            for (int j = 0; j < 4; j++) sacc[nt][j] = 0.f;

        #pragma unroll
        for (int ks = 0; ks < 10; ks++) {
            #pragma unroll
            for (int nt = 0; nt < 8; nt++) {
                float bf[2];
                bf[0] = Kt[(nt * 8 + g) * LDK + ks * 8 + t];
                bf[1] = Kt[(nt * 8 + g) * LDK + ks * 8 + t + 4];
                mma_tf32(sacc[nt], qf[ks], bf, sacc[nt]);
            }
        }

        // ---- online softmax (warp-private; rows r1 = w*16+g, r2 = r1+8) ----
        float mx1 = -INFINITY, mx2 = -INFINITY;
        #pragma unroll
        for (int nt = 0; nt < 8; nt++) {
            mx1 = fmaxf(mx1, fmaxf(sacc[nt][0], sacc[nt][1]));
            mx2 = fmaxf(mx2, fmaxf(sacc[nt][2], sacc[nt][3]));
        }
        mx1 = fmaxf(mx1, __shfl_xor_sync(0xffffffff, mx1, 1));
        mx1 = fmaxf(mx1, __shfl_xor_sync(0xffffffff, mx1, 2));
        mx2 = fmaxf(mx2, __shfl_xor_sync(0xffffffff, mx2, 1));
        mx2 = fmaxf(mx2, __shfl_xor_sync(0xffffffff, mx2, 2));

        float mn1 = fmaxf(m1, mx1);
        float mn2 = fmaxf(m2, mx2);
        float a1 = exp2f(m1 - mn1);
        float a2 = exp2f(m2 - mn2);
        m1 = mn1; m2 = mn2;

        float s1 = 0.f, s2 = 0.f;
        #pragma unroll
        for (int nt = 0; nt < 8; nt++) {
            sacc[nt][0] = exp2f(sacc[nt][0] - mn1);
            sacc[nt][1] = exp2f(sacc[nt][1] - mn1);
            sacc[nt][2] = exp2f(sacc[nt][2] - mn2);
            sacc[nt][3] = exp2f(sacc[nt][3] - mn2);
            s1 += sacc[nt][0] + sacc[nt][1];
            s2 += sacc[nt][2] + sacc[nt][3];
        }
        s1 += __shfl_xor_sync(0xffffffff, s1, 1);
        s1 += __shfl_xor_sync(0xffffffff, s1, 2);
        s2 += __shfl_xor_sync(0xffffffff, s2, 1);
        s2 += __shfl_xor_sync(0xffffffff, s2, 2);
        l1 = l1 * a1 + s1;
        l2 = l2 * a2 + s2;

        // rescale O
        #pragma unroll
        for (int nt = 0; nt < 10; nt++) {
            of[nt][0] *= a1; of[nt][1] *= a1;
            of[nt][2] *= a2; of[nt][3] *= a2;
        }

        // ---- P -> warp-private smem strip ----
        __syncwarp();   // WAR: previous iter's P reads done
        #pragma unroll
        for (int nt = 0; nt < 8; nt++) {
            *(float2*)(Pw + g * LDP + nt * 8 + 2 * t)       = make_float2(sacc[nt][0], sacc[nt][1]);
            *(float2*)(Pw + (g + 8) * LDP + nt * 8 + 2 * t) = make_float2(sacc[nt][2], sacc[nt][3]);
        }
        __syncwarp();

        // ---- O += P x V : 8 k-steps (keys) x 10 n-tiles (dims) ----
        #pragma unroll
        for (int ks = 0; ks < 8; ks++) {
            float af[4];
            af[0] = Pw[g * LDP + ks * 8 + t];
            af[1] = Pw[(g + 8) * LDP + ks * 8 + t];
            af[2] = Pw[g * LDP + ks * 8 + t + 4];
            af[3] = Pw[(g + 8) * LDP + ks * 8 + t + 4];
            #pragma unroll
            for (int nt = 0; nt < 10; nt++) {
                float bf[2];
                bf[0] = Vt[(ks * 8 + t) * LDK + nt * 8 + g];
                bf[1] = Vt[(ks * 8 + t + 4) * LDK + nt * 8 + g];
                mma_tf32(of[nt], af, bf, of[nt]);
            }
        }
        __syncthreads();   // done with this K/V buffer before it's overwritten
    }

    // ---- epilogue: O /= l, store ----
    const float inv1 = 1.f / l1;
    const float inv2 = 1.f / l2;
    const int r1 = q0 + w * 16 + g;
    float* ob = out + (size_t)(b * SEQ) * HIDDEN + h * HDIM;
    #pragma unroll
    for (int nt = 0; nt < 10; nt++) {
        int c = nt * 8 + 2 * t;
        *(float2*)(ob + (size_t)r1 * HIDDEN + c)       = make_float2(of[nt][0] * inv1, of[nt][1] * inv1);
        *(float2*)(ob + (size_t)(r1 + 8) * HIDDEN + c) = make_float2(of[nt][2] * inv2, of[nt][3] * inv2);
    }
}

// ---------------------------------------------------------------------------
extern "C" void kernel_launch(void* const* d_in, const int* in_sizes, int n_in,
                              void* d_out, int out_size)
{
    const float* x      = (const float*)d_in[0];
    const float* cosp   = (const float*)d_in[1];
    const float* sinp   = (const float*)d_in[2];
    const float* qkv_w  = (const float*)d_in[3];
    const float* qkv_b  = (const float*)d_in[4];
    const float* proj_w = (const float*)d_in[5];
    const float* proj_b = (const float*)d_in[6];
    float* out = (float*)d_out;

    float *qkv_buf, *attn_buf;
    cudaGetSymbolAddress((void**)&qkv_buf,  g_qkv);
    cudaGetSymbolAddress((void**)&attn_buf, g_attn);

    // 1) QKV GEMM: [4096,1280] @ [1280,3840] + bias
    {
        dim3 grid(QKV_COLS / 64, ROWS / 64);
        gemm_bias_kernel<64, 64, 16, 4, 4><<<grid, 256>>>(
            x, qkv_w, qkv_b, qkv_buf, ROWS, QKV_COLS, HIDDEN);
    }

    // 2) RoPE on Q and K
    {
        int total = BATCH * SEQ * 2 * HEADS * HALF;
        rope_kernel<<<(total + 255) / 256, 256>>>(qkv_buf, cosp, sinp);
    }

    // 3) TF32 tensor-core flash attention
    {
        static int smem_set = 0;
        if (!smem_set) {
            cudaFuncSetAttribute(flash_attn_tc_kernel,
                                 cudaFuncAttributeMaxDynamicSharedMemorySize,
                                 ATTN_SMEM_FLOATS * sizeof(float));
            smem_set = 1;
        }
        dim3 grid(SEQ / BQ, BATCH * HEADS);   // (16, 32)
        flash_attn_tc_kernel<<<grid, 256, ATTN_SMEM_FLOATS * sizeof(float)>>>(
            qkv_buf, attn_buf);
    }

    // 4) Proj GEMM: [4096,1280] @ [1280,1280] + bias -> d_out
    {
        dim3 grid(HIDDEN / 64, ROWS / 64);
        gemm_bias_kernel<64, 64, 16, 4, 4><<<grid, 256>>>(
            attn_buf, proj_w, proj_b, out, ROWS, HIDDEN, HIDDEN);
    }
}

// round 4
// speedup vs baseline: 30.1807x; 2.2387x over previous
#include <cuda_runtime.h>
#include <math.h>
#include <stdint.h>

#define HIDDEN   1280
#define HEADS    16
#define HDIM     80
#define HALF     40
#define BATCH    2
#define SEQ      2048
#define ROWS     (BATCH*SEQ)        /* 4096 */
#define QKV_COLS (3*HIDDEN)         /* 3840 */

// Scratch (device globals; no runtime allocation allowed)
__device__ float g_qkv[(size_t)ROWS * QKV_COLS];   // 62.9 MB
__device__ float g_attn[(size_t)ROWS * HIDDEN];    // 21.0 MB

// Round fp32 to nearest TF32 (HW truncates at bit 13; add half-ulp first).
__device__ __forceinline__ float rtf(float x)
{
    return __uint_as_float(__float_as_uint(x) + 0x1000u);
}

__device__ __forceinline__ void mma_tf32(float* d,
                                         const float* a, const float* b,
                                         const float* c)
{
    asm volatile(
        "mma.sync.aligned.m16n8k8.row.col.f32.tf32.tf32.f32 "
        "{%0,%1,%2,%3}, {%4,%5,%6,%7}, {%8,%9}, {%10,%11,%12,%13};\n"
        : "=f"(d[0]), "=f"(d[1]), "=f"(d[2]), "=f"(d[3])
        : "r"(__float_as_uint(a[0])), "r"(__float_as_uint(a[1])),
          "r"(__float_as_uint(a[2])), "r"(__float_as_uint(a[3])),
          "r"(__float_as_uint(b[0])), "r"(__float_as_uint(b[1])),
          "f"(c[0]), "f"(c[1]), "f"(c[2]), "f"(c[3]));
}

__device__ __forceinline__ void cp_async16(void* smem_dst, const void* gmem_src)
{
    uint32_t s = (uint32_t)__cvta_generic_to_shared(smem_dst);
    asm volatile("cp.async.cg.shared.global [%0], [%1], 16;\n"
                 :: "r"(s), "l"(gmem_src) : "memory");
}
__device__ __forceinline__ void cp_commit()
{
    asm volatile("cp.async.commit_group;\n" ::: "memory");
}

// ---------------------------------------------------------------------------
// TF32 tensor-core GEMM + bias: C[M,N] = A[M,K] @ B[K,N] + bias[N]
// Block 128x128, BK=16, 256 threads (8 warps as 4m x 2n; warp tile 32x64).
// A staged [m][k] (LDA=20 pad), B staged [k][n] (LDB=136 pad) — both layouts
// are conflict-free for the m16n8k8 fragment access patterns.
// Requires M%128==0, N%128==0, K%16==0 (true for all uses here).
// ---------------------------------------------------------------------------
#define LDA 20
#define LDB 136

__global__ __launch_bounds__(256, 2)
void gemm_tf32_kernel(const float* __restrict__ A,
                      const float* __restrict__ B,
                      const float* __restrict__ bias,
                      float* __restrict__ C,
                      int M, int N, int K)
{
    __shared__ float As[2][128 * LDA];
    __shared__ float Bs[2][16 * LDB];

    const int tid  = threadIdx.x;
    const int w    = tid >> 5;
    const int lane = tid & 31;
    const int g    = lane >> 2;
    const int t    = lane & 3;
    const int wm   = w >> 1;            // 0..3 -> m offset wm*32
    const int wn   = w & 1;             // 0..1 -> n offset wn*64
    const int rowB = blockIdx.y * 128;
    const int colB = blockIdx.x * 128;

    const float* Ag = A + (size_t)rowB * K;
    const float* Bg = B + colB;

    float acc[2][8][4];
    #pragma unroll
    for (int mt = 0; mt < 2; mt++)
        #pragma unroll
        for (int nt = 0; nt < 8; nt++)
            #pragma unroll
            for (int j = 0; j < 4; j++) acc[mt][nt][j] = 0.f;

    const int KT = K >> 4;   // K/16 iterations

    // prefetch tile 0
    {
        #pragma unroll
        for (int j = 0; j < 2; j++) {
            int idx = tid + j * 256;
            int r = idx >> 2, c = idx & 3;
            cp_async16(&As[0][r * LDA + c * 4], Ag + (size_t)r * K + c * 4);
        }
        #pragma unroll
        for (int j = 0; j < 2; j++) {
            int idx = tid + j * 256;
            int r = idx >> 5, c = idx & 31;
            cp_async16(&Bs[0][r * LDB + c * 4], Bg + (size_t)r * N + c * 4);
        }
        cp_commit();
    }

    for (int it = 0; it < KT; it++) {
        if (it + 1 < KT) {
            int nb = (it + 1) & 1;
            int k0 = (it + 1) << 4;
            #pragma unroll
            for (int j = 0; j < 2; j++) {
                int idx = tid + j * 256;
                int r = idx >> 2, c = idx & 3;
                cp_async16(&As[nb][r * LDA + c * 4], Ag + (size_t)r * K + k0 + c * 4);
            }
            #pragma unroll
            for (int j = 0; j < 2; j++) {
                int idx = tid + j * 256;
                int r = idx >> 5, c = idx & 31;
                cp_async16(&Bs[nb][r * LDB + c * 4], Bg + (size_t)(k0 + r) * N + c * 4);
            }
            cp_commit();
            asm volatile("cp.async.wait_group 1;\n" ::: "memory");
        } else {
            asm volatile("cp.async.wait_group 0;\n" ::: "memory");
        }
        __syncthreads();

        const float* At = As[it & 1];
        const float* Bt = Bs[it & 1];

        #pragma unroll
        for (int ks = 0; ks < 2; ks++) {
            float af[2][4];
            #pragma unroll
            for (int mt = 0; mt < 2; mt++) {
                int m = wm * 32 + mt * 16 + g;
                int c = ks * 8 + t;
                af[mt][0] = rtf(At[m * LDA + c]);
                af[mt][1] = rtf(At[(m + 8) * LDA + c]);
                af[mt][2] = rtf(At[m * LDA + c + 4]);
                af[mt][3] = rtf(At[(m + 8) * LDA + c + 4]);
            }
            #pragma unroll
            for (int nt = 0; nt < 8; nt++) {
                int n = wn * 64 + nt * 8 + g;
                float bf[2];
                bf[0] = rtf(Bt[(ks * 8 + t) * LDB + n]);
                bf[1] = rtf(Bt[(ks * 8 + t + 4) * LDB + n]);
                mma_tf32(acc[0][nt], af[0], bf, acc[0][nt]);
                mma_tf32(acc[1][nt], af[1], bf, acc[1][nt]);
            }
        }
        __syncthreads();
    }

    // epilogue: + bias, store
    #pragma unroll
    for (int mt = 0; mt < 2; mt++) {
        int m = rowB + wm * 32 + mt * 16 + g;
        #pragma unroll
        for (int nt = 0; nt < 8; nt++) {
            int n = colB + wn * 64 + nt * 8 + 2 * t;
            float2 bv = *(const float2*)(bias + n);
            *(float2*)(C + (size_t)m * N + n) =
                make_float2(acc[mt][nt][0] + bv.x, acc[mt][nt][1] + bv.y);
            *(float2*)(C + (size_t)(m + 8) * N + n) =
                make_float2(acc[mt][nt][2] + bv.x, acc[mt][nt][3] + bv.y);
        }
    }
}

// ---------------------------------------------------------------------------
// RoPE applied in-place to Q and K slices of g_qkv.
// ---------------------------------------------------------------------------
__global__ void rope_kernel(float* __restrict__ qkv,
                            const float* __restrict__ cosp,
                            const float* __restrict__ sinp)
{
    int idx = blockIdx.x * blockDim.x + threadIdx.x;
    const int total = BATCH * SEQ * 2 * HEADS * HALF;
    if (idx >= total) return;

    int d  = idx % HALF;  idx /= HALF;
    int h  = idx % HEADS; idx /= HEADS;
    int qk = idx % 2;     idx /= 2;
    int n  = idx % SEQ;
    int b  = idx / SEQ;

    float* row = qkv + (size_t)(b * SEQ + n) * QKV_COLS + qk * HIDDEN + h * HDIM;
    float lo = row[d];
    float hi = row[d + HALF];
    float cl = cosp[n * HDIM + d];
    float ch = cosp[n * HDIM + d + HALF];
    float sl = sinp[n * HDIM + d];
    float sh = sinp[n * HDIM + d + HALF];
    row[d]        = lo * cl - hi * sl;
    row[d + HALF] = hi * ch + lo * sh;
}

// ---------------------------------------------------------------------------
// TF32 tensor-core flash attention (RN-rounded TF32 operands).
// ---------------------------------------------------------------------------
#define BQ      128
#define BKT     64
#define NITER   (SEQ / BKT)         /* 32 */
#define LDK     84
#define LDP     68
#define QS_FLOATS   (BQ * LDK)
#define KT_FLOATS   (BKT * LDK)
#define ATTN_SMEM_FLOATS (QS_FLOATS + 4 * KT_FLOATS)

__global__ __launch_bounds__(256, 1)
void flash_attn_tc_kernel(const float* __restrict__ qkv,
                          float* __restrict__ out)
{
    extern __shared__ float sm[];
    float* Qs = sm;
    float* Ks = sm + QS_FLOATS;
    float* Vs = Ks + 2 * KT_FLOATS;

    const int tid  = threadIdx.x;
    const int w    = tid >> 5;
    const int lane = tid & 31;
    const int g    = lane >> 2;
    const int t    = lane & 3;

    const int q0 = blockIdx.x * BQ;
    const int h  = blockIdx.y & (HEADS - 1);
    const int b  = blockIdx.y >> 4;

    const float* base = qkv + (size_t)(b * SEQ) * QKV_COLS;
    const float SCL = rsqrtf((float)HDIM) * 1.44269504f;

    // load Q tile (scaled + rounded to tf32)
    {
        const float* qb = base + h * HDIM;
        for (int i = tid; i < BQ * (HDIM / 4); i += 256) {
            int r = i / (HDIM / 4), c4 = i - r * (HDIM / 4);
            float4 v = *(const float4*)(qb + (size_t)(q0 + r) * QKV_COLS + c4 * 4);
            v.x = rtf(v.x * SCL); v.y = rtf(v.y * SCL);
            v.z = rtf(v.z * SCL); v.w = rtf(v.w * SCL);
            *(float4*)(Qs + r * LDK + c4 * 4) = v;
        }
    }
    __syncthreads();

    float qf[10][4];
    {
        const int r0 = w * 16 + g;
        #pragma unroll
        for (int ks = 0; ks < 10; ks++) {
            int c = ks * 8 + t;
            qf[ks][0] = Qs[r0 * LDK + c];
            qf[ks][1] = Qs[(r0 + 8) * LDK + c];
            qf[ks][2] = Qs[r0 * LDK + c + 4];
            qf[ks][3] = Qs[(r0 + 8) * LDK + c + 4];
        }
    }
    __syncthreads();   // Qs dead -> P strips

    float* Pw = Qs + w * 16 * LDP;

    float of[10][4];
    #pragma unroll
    for (int i = 0; i < 10; i++)
        #pragma unroll
        for (int j = 0; j < 4; j++) of[i][j] = 0.f;
    float m1 = -INFINITY, m2 = -INFINITY, l1 = 0.f, l2 = 0.f;

    const float* kb0 = base + HIDDEN + h * HDIM;
    const float* vb0 = base + 2 * HIDDEN + h * HDIM;

    {
        #pragma unroll
        for (int j = 0; j < 10; j++) {
            int idx = tid + j * 256;
            if (idx < 1280) {
                int r = idx / 20, c = idx - r * 20;
                cp_async16(Ks + r * LDK + c * 4, kb0 + (size_t)r * QKV_COLS + c * 4);
            } else {
                int i2 = idx - 1280;
                int r = i2 / 20, c = i2 - r * 20;
                cp_async16(Vs + r * LDK + c * 4, vb0 + (size_t)r * QKV_COLS + c * 4);
            }
        }
        cp_commit();
    }

    for (int it = 0; it < NITER; it++) {
        if (it + 1 < NITER) {
            float* Kd = Ks + ((it + 1) & 1) * KT_FLOATS;
            float* Vd = Vs + ((it + 1) & 1) * KT_FLOATS;
            const float* kb = kb0 + (size_t)((it + 1) * BKT) * QKV_COLS;
            const float* vb = vb0 + (size_t)((it + 1) * BKT) * QKV_COLS;
            #pragma unroll
            for (int j = 0; j < 10; j++) {
                int idx = tid + j * 256;
                if (idx < 1280) {
                    int r = idx / 20, c = idx - r * 20;
                    cp_async16(Kd + r * LDK + c * 4, kb + (size_t)r * QKV_COLS + c * 4);
                } else {
                    int i2 = idx - 1280;
                    int r = i2 / 20, c = i2 - r * 20;
                    cp_async16(Vd + r * LDK + c * 4, vb + (size_t)r * QKV_COLS + c * 4);
                }
            }
            cp_commit();
            asm volatile("cp.async.wait_group 1;\n" ::: "memory");
        } else {
            asm volatile("cp.async.wait_group 0;\n" ::: "memory");
        }
        __syncthreads();

        const float* Kt = Ks + (it & 1) * KT_FLOATS;
        const float* Vt = Vs + (it & 1) * KT_FLOATS;

        float sacc[8][4];
        #pragma unroll
        for (int nt = 0; nt < 8; nt++)
            #pragma unroll
            for (int j = 0; j < 4; j++) sacc[nt][j] = 0.f;

        #pragma unroll
        for (int ks = 0; ks < 10; ks++) {
            #pragma unroll
            for (int nt = 0; nt < 8; nt++) {
                float bf[2];
                bf[0] = rtf(Kt[(nt * 8 + g) * LDK + ks * 8 + t]);
                bf[1] = rtf(Kt[(nt * 8 + g) * LDK + ks * 8 + t + 4]);
                mma_tf32(sacc[nt], qf[ks], bf, sacc[nt]);
            }
        }

        float mx1 = -INFINITY, mx2 = -INFINITY;
        #pragma unroll
        for (int nt = 0; nt < 8; nt++) {
            mx1 = fmaxf(mx1, fmaxf(sacc[nt][0], sacc[nt][1]));
            mx2 = fmaxf(mx2, fmaxf(sacc[nt][2], sacc[nt][3]));
        }
        mx1 = fmaxf(mx1, __shfl_xor_sync(0xffffffff, mx1, 1));
        mx1 = fmaxf(mx1, __shfl_xor_sync(0xffffffff, mx1, 2));
        mx2 = fmaxf(mx2, __shfl_xor_sync(0xffffffff, mx2, 1));
        mx2 = fmaxf(mx2, __shfl_xor_sync(0xffffffff, mx2, 2));

        float mn1 = fmaxf(m1, mx1);
        float mn2 = fmaxf(m2, mx2);
        float a1 = exp2f(m1 - mn1);
        float a2 = exp2f(m2 - mn2);
        m1 = mn1; m2 = mn2;

        float s1 = 0.f, s2 = 0.f;
        #pragma unroll
        for (int nt = 0; nt < 8; nt++) {
            sacc[nt][0] = exp2f(sacc[nt][0] - mn1);
            sacc[nt][1] = exp2f(sacc[nt][1] - mn1);
            sacc[nt][2] = exp2f(sacc[nt][2] - mn2);
            sacc[nt][3] = exp2f(sacc[nt][3] - mn2);
            s1 += sacc[nt][0] + sacc[nt][1];
            s2 += sacc[nt][2] + sacc[nt][3];
        }
        s1 += __shfl_xor_sync(0xffffffff, s1, 1);
        s1 += __shfl_xor_sync(0xffffffff, s1, 2);
        s2 += __shfl_xor_sync(0xffffffff, s2, 1);
        s2 += __shfl_xor_sync(0xffffffff, s2, 2);
        l1 = l1 * a1 + s1;
        l2 = l2 * a2 + s2;

        #pragma unroll
        for (int nt = 0; nt < 10; nt++) {
            of[nt][0] *= a1; of[nt][1] *= a1;
            of[nt][2] *= a2; of[nt][3] *= a2;
        }

        __syncwarp();
        #pragma unroll
        for (int nt = 0; nt < 8; nt++) {
            *(float2*)(Pw + g * LDP + nt * 8 + 2 * t) =
                make_float2(rtf(sacc[nt][0]), rtf(sacc[nt][1]));
            *(float2*)(Pw + (g + 8) * LDP + nt * 8 + 2 * t) =
                make_float2(rtf(sacc[nt][2]), rtf(sacc[nt][3]));
        }
        __syncwarp();

        #pragma unroll
        for (int ks = 0; ks < 8; ks++) {
            float af[4];
            af[0] = Pw[g * LDP + ks * 8 + t];
            af[1] = Pw[(g + 8) * LDP + ks * 8 + t];
            af[2] = Pw[g * LDP + ks * 8 + t + 4];
            af[3] = Pw[(g + 8) * LDP + ks * 8 + t + 4];
            #pragma unroll
            for (int nt = 0; nt < 10; nt++) {
                float bf[2];
                bf[0] = rtf(Vt[(ks * 8 + t) * LDK + nt * 8 + g]);
                bf[1] = rtf(Vt[(ks * 8 + t + 4) * LDK + nt * 8 + g]);
                mma_tf32(of[nt], af, bf, of[nt]);
            }
        }
        __syncthreads();
    }

    const float inv1 = 1.f / l1;
    const float inv2 = 1.f / l2;
    const int r1 = q0 + w * 16 + g;
    float* ob = out + (size_t)(b * SEQ) * HIDDEN + h * HDIM;
    #pragma unroll
    for (int nt = 0; nt < 10; nt++) {
        int c = nt * 8 + 2 * t;
        *(float2*)(ob + (size_t)r1 * HIDDEN + c)       = make_float2(of[nt][0] * inv1, of[nt][1] * inv1);
        *(float2*)(ob + (size_t)(r1 + 8) * HIDDEN + c) = make_float2(of[nt][2] * inv2, of[nt][3] * inv2);
    }
}

// ---------------------------------------------------------------------------
extern "C" void kernel_launch(void* const* d_in, const int* in_sizes, int n_in,
                              void* d_out, int out_size)
{
    const float* x      = (const float*)d_in[0];
    const float* cosp   = (const float*)d_in[1];
    const float* sinp   = (const float*)d_in[2];
    const float* qkv_w  = (const float*)d_in[3];
    const float* qkv_b  = (const float*)d_in[4];
    const float* proj_w = (const float*)d_in[5];
    const float* proj_b = (const float*)d_in[6];
    float* out = (float*)d_out;

    float *qkv_buf, *attn_buf;
    cudaGetSymbolAddress((void**)&qkv_buf,  g_qkv);
    cudaGetSymbolAddress((void**)&attn_buf, g_attn);

    // 1) QKV GEMM (TF32 TC): [4096,1280] @ [1280,3840] + bias
    {
        dim3 grid(QKV_COLS / 128, ROWS / 128);   // (30, 32)
        gemm_tf32_kernel<<<grid, 256>>>(x, qkv_w, qkv_b, qkv_buf,
                                        ROWS, QKV_COLS, HIDDEN);
    }

    // 2) RoPE on Q and K
    {
        int total = BATCH * SEQ * 2 * HEADS * HALF;
        rope_kernel<<<(total + 255) / 256, 256>>>(qkv_buf, cosp, sinp);
    }

    // 3) TF32 tensor-core flash attention
    {
        static int smem_set = 0;
        if (!smem_set) {
            cudaFuncSetAttribute(flash_attn_tc_kernel,
                                 cudaFuncAttributeMaxDynamicSharedMemorySize,
                                 ATTN_SMEM_FLOATS * sizeof(float));
            smem_set = 1;
        }
        dim3 grid(SEQ / BQ, BATCH * HEADS);   // (16, 32)
        flash_attn_tc_kernel<<<grid, 256, ATTN_SMEM_FLOATS * sizeof(float)>>>(
            qkv_buf, attn_buf);
    }

    // 4) Proj GEMM (TF32 TC): [4096,1280] @ [1280,1280] + bias -> d_out
    {
        dim3 grid(HIDDEN / 128, ROWS / 128);   // (10, 32)
        gemm_tf32_kernel<<<grid, 256>>>(attn_buf, proj_w, proj_b, out,
                                        ROWS, HIDDEN, HIDDEN);
    }
}

// round 5
// speedup vs baseline: 31.0399x; 1.0285x over previous
#include <cuda_runtime.h>
#include <math.h>
#include <stdint.h>

#define HIDDEN   1280
#define HEADS    16
#define HDIM     80
#define HALF     40
#define BATCH    2
#define SEQ      2048
#define ROWS     (BATCH*SEQ)        /* 4096 */
#define QKV_COLS (3*HIDDEN)         /* 3840 */

__device__ float g_qkv[(size_t)ROWS * QKV_COLS];   // 62.9 MB
__device__ float g_attn[(size_t)ROWS * HIDDEN];    // 21.0 MB

// Round fp32 to nearest TF32 (HW truncates at bit 13; add half-ulp first).
__device__ __forceinline__ float rtf(float x)
{
    return __uint_as_float(__float_as_uint(x) + 0x1000u);
}

__device__ __forceinline__ void mma_tf32(float* d,
                                         const float* a, const float* b,
                                         const float* c)
{
    asm volatile(
        "mma.sync.aligned.m16n8k8.row.col.f32.tf32.tf32.f32 "
        "{%0,%1,%2,%3}, {%4,%5,%6,%7}, {%8,%9}, {%10,%11,%12,%13};\n"
        : "=f"(d[0]), "=f"(d[1]), "=f"(d[2]), "=f"(d[3])
        : "r"(__float_as_uint(a[0])), "r"(__float_as_uint(a[1])),
          "r"(__float_as_uint(a[2])), "r"(__float_as_uint(a[3])),
          "r"(__float_as_uint(b[0])), "r"(__float_as_uint(b[1])),
          "f"(c[0]), "f"(c[1]), "f"(c[2]), "f"(c[3]));
}

__device__ __forceinline__ void cp_async16(void* smem_dst, const void* gmem_src)
{
    uint32_t s = (uint32_t)__cvta_generic_to_shared(smem_dst);
    asm volatile("cp.async.cg.shared.global [%0], [%1], 16;\n"
                 :: "r"(s), "l"(gmem_src) : "memory");
}
__device__ __forceinline__ void cp_commit()
{
    asm volatile("cp.async.commit_group;\n" ::: "memory");
}

// ---------------------------------------------------------------------------
// TF32 tensor-core GEMM + bias, 4-stage cp.async pipeline.
// Block 128x128, BK=16, 256 threads (8 warps 4m x 2n; warp tile 32x64).
// Dynamic smem: As[4][128*20] + Bs[4][16*136] = 75.8 KB -> 2 blocks/SM.
// Requires M%128==0, N%128==0, K%16==0, K/16 >= 3.
// ---------------------------------------------------------------------------
#define LDA 20
#define LDB 136
#define GSTG 4
#define A_STG (128 * LDA)   /* 2560 */
#define B_STG (16 * LDB)    /* 2176 */
#define GEMM_SMEM_FLOATS (GSTG * (A_STG + B_STG))   /* 18944 -> 75776 B */

__global__ __launch_bounds__(256, 2)
void gemm_tf32_kernel(const float* __restrict__ A,
                      const float* __restrict__ B,
                      const float* __restrict__ bias,
                      float* __restrict__ C,
                      int M, int N, int K)
{
    extern __shared__ float gsm[];
    float* Asm = gsm;                  // [GSTG][A_STG]
    float* Bsm = gsm + GSTG * A_STG;   // [GSTG][B_STG]

    const int tid  = threadIdx.x;
    const int w    = tid >> 5;
    const int lane = tid & 31;
    const int g    = lane >> 2;
    const int t    = lane & 3;
    const int wm   = w >> 1;
    const int wn   = w & 1;
    const int rowB = blockIdx.y * 128;
    const int colB = blockIdx.x * 128;

    const float* Ag = A + (size_t)rowB * K;
    const float* Bg = B + colB;

    float acc[2][8][4];
    #pragma unroll
    for (int mt = 0; mt < 2; mt++)
        #pragma unroll
        for (int nt = 0; nt < 8; nt++)
            #pragma unroll
            for (int j = 0; j < 4; j++) acc[mt][nt][j] = 0.f;

    const int KT = K >> 4;

    // stage loader
    auto load_stage = [&](int slot, int k0) {
        float* As = Asm + slot * A_STG;
        float* Bs = Bsm + slot * B_STG;
        #pragma unroll
        for (int j = 0; j < 2; j++) {
            int idx = tid + j * 256;
            int r = idx >> 2, c = idx & 3;
            cp_async16(&As[r * LDA + c * 4], Ag + (size_t)r * K + k0 + c * 4);
        }
        #pragma unroll
        for (int j = 0; j < 2; j++) {
            int idx = tid + j * 256;
            int r = idx >> 5, c = idx & 31;
            cp_async16(&Bs[r * LDB + c * 4], Bg + (size_t)(k0 + r) * N + c * 4);
        }
    };

    // prologue: stages 0..2
    #pragma unroll
    for (int s = 0; s < GSTG - 1; s++) {
        load_stage(s, s << 4);
        cp_commit();
    }

    for (int it = 0; it < KT; it++) {
        asm volatile("cp.async.wait_group %0;\n" :: "n"(GSTG - 2) : "memory");
        __syncthreads();

        // prefetch stage it+3 (slot (it+3)%4 == slot (it-1)%4, free after sync)
        if (it + GSTG - 1 < KT)
            load_stage((it + GSTG - 1) & (GSTG - 1), (it + GSTG - 1) << 4);
        cp_commit();   // unconditional: keeps wait_group arithmetic exact

        const float* At = Asm + (it & (GSTG - 1)) * A_STG;
        const float* Bt = Bsm + (it & (GSTG - 1)) * B_STG;

        #pragma unroll
        for (int ks = 0; ks < 2; ks++) {
            float af[2][4];
            #pragma unroll
            for (int mt = 0; mt < 2; mt++) {
                int m = wm * 32 + mt * 16 + g;
                int c = ks * 8 + t;
                af[mt][0] = rtf(At[m * LDA + c]);
                af[mt][1] = rtf(At[(m + 8) * LDA + c]);
                af[mt][2] = rtf(At[m * LDA + c + 4]);
                af[mt][3] = rtf(At[(m + 8) * LDA + c + 4]);
            }
            #pragma unroll
            for (int nt = 0; nt < 8; nt++) {
                int n = wn * 64 + nt * 8 + g;
                float bf[2];
                bf[0] = rtf(Bt[(ks * 8 + t) * LDB + n]);
                bf[1] = rtf(Bt[(ks * 8 + t + 4) * LDB + n]);
                mma_tf32(acc[0][nt], af[0], bf, acc[0][nt]);
                mma_tf32(acc[1][nt], af[1], bf, acc[1][nt]);
            }
        }
    }

    #pragma unroll
    for (int mt = 0; mt < 2; mt++) {
        int m = rowB + wm * 32 + mt * 16 + g;
        #pragma unroll
        for (int nt = 0; nt < 8; nt++) {
            int n = colB + wn * 64 + nt * 8 + 2 * t;
            float2 bv = *(const float2*)(bias + n);
            *(float2*)(C + (size_t)m * N + n) =
                make_float2(acc[mt][nt][0] + bv.x, acc[mt][nt][1] + bv.y);
            *(float2*)(C + (size_t)(m + 8) * N + n) =
                make_float2(acc[mt][nt][2] + bv.x, acc[mt][nt][3] + bv.y);
        }
    }
}

// ---------------------------------------------------------------------------
// RoPE applied in-place to Q and K slices of g_qkv.
// ---------------------------------------------------------------------------
__global__ void rope_kernel(float* __restrict__ qkv,
                            const float* __restrict__ cosp,
                            const float* __restrict__ sinp)
{
    int idx = blockIdx.x * blockDim.x + threadIdx.x;
    const int total = BATCH * SEQ * 2 * HEADS * HALF;
    if (idx >= total) return;

    int d  = idx % HALF;  idx /= HALF;
    int h  = idx % HEADS; idx /= HEADS;
    int qk = idx % 2;     idx /= 2;
    int n  = idx % SEQ;
    int b  = idx / SEQ;

    float* row = qkv + (size_t)(b * SEQ + n) * QKV_COLS + qk * HIDDEN + h * HDIM;
    float lo = row[d];
    float hi = row[d + HALF];
    float cl = cosp[n * HDIM + d];
    float ch = cosp[n * HDIM + d + HALF];
    float sl = sinp[n * HDIM + d];
    float sh = sinp[n * HDIM + d + HALF];
    row[d]        = lo * cl - hi * sl;
    row[d + HALF] = hi * ch + lo * sh;
}

// ---------------------------------------------------------------------------
// TF32 tensor-core flash attention, occ=2 variant.
// smem: P strips (128*68) | K double-buffer (2*64*84) | V single (64*84)
// Q staging aliases the K double-buffer (used before first K prefetch).
// 97 KB -> 2 blocks/SM.
// ---------------------------------------------------------------------------
#define BQ      128
#define BKT     64
#define NITER   (SEQ / BKT)         /* 32 */
#define LDK     84
#define LDP     68
#define P_FLOATS    (BQ * LDP)      /* 8704 */
#define KT_FLOATS   (BKT * LDK)     /* 5376 */
#define ATTN_SMEM_FLOATS (P_FLOATS + 3 * KT_FLOATS)   /* 24832 -> 99328 B */

__global__ __launch_bounds__(256, 2)
void flash_attn_tc_kernel(const float* __restrict__ qkv,
                          float* __restrict__ out)
{
    extern __shared__ float sm[];
    float* Pbase = sm;                         // [128][LDP]
    float* Ks    = sm + P_FLOATS;              // 2 x [BKT][LDK]
    float* Vs    = Ks + 2 * KT_FLOATS;         // 1 x [BKT][LDK]
    float* Qs    = Ks;                         // alias (transient)

    const int tid  = threadIdx.x;
    const int w    = tid >> 5;
    const int lane = tid & 31;
    const int g    = lane >> 2;
    const int t    = lane & 3;

    const int q0 = blockIdx.x * BQ;
    const int h  = blockIdx.y & (HEADS - 1);
    const int b  = blockIdx.y >> 4;

    const float* base = qkv + (size_t)(b * SEQ) * QKV_COLS;
    const float SCL = rsqrtf((float)HDIM) * 1.44269504f;

    // ---- load Q tile into aliased staging, hoist fragments ----
    {
        const float* qb = base + h * HDIM;
        for (int i = tid; i < BQ * (HDIM / 4); i += 256) {
            int r = i / (HDIM / 4), c4 = i - r * (HDIM / 4);
            float4 v = *(const float4*)(qb + (size_t)(q0 + r) * QKV_COLS + c4 * 4);
            v.x = rtf(v.x * SCL); v.y = rtf(v.y * SCL);
            v.z = rtf(v.z * SCL); v.w = rtf(v.w * SCL);
            *(float4*)(Qs + r * LDK + c4 * 4) = v;
        }
    }
    __syncthreads();

    float qf[10][4];
    {
        const int r0 = w * 16 + g;
        #pragma unroll
        for (int ks = 0; ks < 10; ks++) {
            int c = ks * 8 + t;
            qf[ks][0] = Qs[r0 * LDK + c];
            qf[ks][1] = Qs[(r0 + 8) * LDK + c];
            qf[ks][2] = Qs[r0 * LDK + c + 4];
            qf[ks][3] = Qs[(r0 + 8) * LDK + c + 4];
        }
    }
    __syncthreads();   // Qs dead -> K buffers may be written

    float* Pw = Pbase + w * 16 * LDP;

    float of[10][4];
    #pragma unroll
    for (int i = 0; i < 10; i++)
        #pragma unroll
        for (int j = 0; j < 4; j++) of[i][j] = 0.f;
    float m1 = -INFINITY, m2 = -INFINITY, l1 = 0.f, l2 = 0.f;

    const float* kb0 = base + HIDDEN + h * HDIM;
    const float* vb0 = base + 2 * HIDDEN + h * HDIM;

    auto load_tile = [&](float* dst, const float* src) {
        #pragma unroll
        for (int j = 0; j < 5; j++) {
            int idx = tid + j * 256;
            int r = idx / 20, c = idx - r * 20;
            cp_async16(dst + r * LDK + c * 4, src + (size_t)r * QKV_COLS + c * 4);
        }
    };

    // prologue: K tile 0
    load_tile(Ks, kb0);
    cp_commit();                                   // G0

    for (int it = 0; it < NITER; it++) {
        // issue V[it] and K[it+1]
        load_tile(Vs, vb0 + (size_t)(it * BKT) * QKV_COLS);
        cp_commit();                               // V_it
        if (it + 1 < NITER)
            load_tile(Ks + ((it + 1) & 1) * KT_FLOATS,
                      kb0 + (size_t)((it + 1) * BKT) * QKV_COLS);
        cp_commit();                               // K_{it+1} (possibly empty)

        asm volatile("cp.async.wait_group 1;\n" ::: "memory");  // K_it + V_it ready
        __syncthreads();

        const float* Kt = Ks + (it & 1) * KT_FLOATS;

        // ---- S = Q x K^T ----
        float sacc[8][4];
        #pragma unroll
        for (int nt = 0; nt < 8; nt++)
            #pragma unroll
            for (int j = 0; j < 4; j++) sacc[nt][j] = 0.f;

        #pragma unroll
        for (int ks = 0; ks < 10; ks++) {
            #pragma unroll
            for (int nt = 0; nt < 8; nt++) {
                float bf[2];
                bf[0] = rtf(Kt[(nt * 8 + g) * LDK + ks * 8 + t]);
                bf[1] = rtf(Kt[(nt * 8 + g) * LDK + ks * 8 + t + 4]);
                mma_tf32(sacc[nt], qf[ks], bf, sacc[nt]);
            }
        }

        // ---- online softmax (warp-private) ----
        float mx1 = -INFINITY, mx2 = -INFINITY;
        #pragma unroll
        for (int nt = 0; nt < 8; nt++) {
            mx1 = fmaxf(mx1, fmaxf(sacc[nt][0], sacc[nt][1]));
            mx2 = fmaxf(mx2, fmaxf(sacc[nt][2], sacc[nt][3]));
        }
        mx1 = fmaxf(mx1, __shfl_xor_sync(0xffffffff, mx1, 1));
        mx1 = fmaxf(mx1, __shfl_xor_sync(0xffffffff, mx1, 2));
        mx2 = fmaxf(mx2, __shfl_xor_sync(0xffffffff, mx2, 1));
        mx2 = fmaxf(mx2, __shfl_xor_sync(0xffffffff, mx2, 2));

        float mn1 = fmaxf(m1, mx1);
        float mn2 = fmaxf(m2, mx2);
        float a1 = exp2f(m1 - mn1);
        float a2 = exp2f(m2 - mn2);
        m1 = mn1; m2 = mn2;

        float s1 = 0.f, s2 = 0.f;
        #pragma unroll
        for (int nt = 0; nt < 8; nt++) {
            sacc[nt][0] = exp2f(sacc[nt][0] - mn1);
            sacc[nt][1] = exp2f(sacc[nt][1] - mn1);
            sacc[nt][2] = exp2f(sacc[nt][2] - mn2);
            sacc[nt][3] = exp2f(sacc[nt][3] - mn2);
            s1 += sacc[nt][0] + sacc[nt][1];
            s2 += sacc[nt][2] + sacc[nt][3];
        }
        s1 += __shfl_xor_sync(0xffffffff, s1, 1);
        s1 += __shfl_xor_sync(0xffffffff, s1, 2);
        s2 += __shfl_xor_sync(0xffffffff, s2, 1);
        s2 += __shfl_xor_sync(0xffffffff, s2, 2);
        l1 = l1 * a1 + s1;
        l2 = l2 * a2 + s2;

        #pragma unroll
        for (int nt = 0; nt < 10; nt++) {
            of[nt][0] *= a1; of[nt][1] *= a1;
            of[nt][2] *= a2; of[nt][3] *= a2;
        }

        // ---- P -> warp-private strip ----
        __syncwarp();
        #pragma unroll
        for (int nt = 0; nt < 8; nt++) {
            *(float2*)(Pw + g * LDP + nt * 8 + 2 * t) =
                make_float2(rtf(sacc[nt][0]), rtf(sacc[nt][1]));
            *(float2*)(Pw + (g + 8) * LDP + nt * 8 + 2 * t) =
                make_float2(rtf(sacc[nt][2]), rtf(sacc[nt][3]));
        }
        __syncwarp();

        // ---- O += P x V ----
        #pragma unroll
        for (int ks = 0; ks < 8; ks++) {
            float af[4];
            af[0] = Pw[g * LDP + ks * 8 + t];
            af[1] = Pw[(g + 8) * LDP + ks * 8 + t];
            af[2] = Pw[g * LDP + ks * 8 + t + 4];
            af[3] = Pw[(g + 8) * LDP + ks * 8 + t + 4];
            #pragma unroll
            for (int nt = 0; nt < 10; nt++) {
                float bf[2];
                bf[0] = rtf(Vs[(ks * 8 + t) * LDK + nt * 8 + g]);
                bf[1] = rtf(Vs[(ks * 8 + t + 4) * LDK + nt * 8 + g]);
                mma_tf32(of[nt], af, bf, of[nt]);
            }
        }
        __syncthreads();   // all reads of Vs / K slot done before next iter's issues
    }

    const float inv1 = 1.f / l1;
    const float inv2 = 1.f / l2;
    const int r1 = q0 + w * 16 + g;
    float* ob = out + (size_t)(b * SEQ) * HIDDEN + h * HDIM;
    #pragma unroll
    for (int nt = 0; nt < 10; nt++) {
        int c = nt * 8 + 2 * t;
        *(float2*)(ob + (size_t)r1 * HIDDEN + c)       = make_float2(of[nt][0] * inv1, of[nt][1] * inv1);
        *(float2*)(ob + (size_t)(r1 + 8) * HIDDEN + c) = make_float2(of[nt][2] * inv2, of[nt][3] * inv2);
    }
}

// ---------------------------------------------------------------------------
extern "C" void kernel_launch(void* const* d_in, const int* in_sizes, int n_in,
                              void* d_out, int out_size)
{
    const float* x      = (const float*)d_in[0];
    const float* cosp   = (const float*)d_in[1];
    const float* sinp   = (const float*)d_in[2];
    const float* qkv_w  = (const float*)d_in[3];
    const float* qkv_b  = (const float*)d_in[4];
    const float* proj_w = (const float*)d_in[5];
    const float* proj_b = (const float*)d_in[6];
    float* out = (float*)d_out;

    float *qkv_buf, *attn_buf;
    cudaGetSymbolAddress((void**)&qkv_buf,  g_qkv);
    cudaGetSymbolAddress((void**)&attn_buf, g_attn);

    static int attr_set = 0;
    if (!attr_set) {
        cudaFuncSetAttribute(gemm_tf32_kernel,
                             cudaFuncAttributeMaxDynamicSharedMemorySize,
                             GEMM_SMEM_FLOATS * sizeof(float));
        cudaFuncSetAttribute(flash_attn_tc_kernel,
                             cudaFuncAttributeMaxDynamicSharedMemorySize,
                             ATTN_SMEM_FLOATS * sizeof(float));
        attr_set = 1;
    }

    // 1) QKV GEMM (TF32 TC, 4-stage): [4096,1280] @ [1280,3840] + bias
    {
        dim3 grid(QKV_COLS / 128, ROWS / 128);   // (30, 32)
        gemm_tf32_kernel<<<grid, 256, GEMM_SMEM_FLOATS * sizeof(float)>>>(
            x, qkv_w, qkv_b, qkv_buf, ROWS, QKV_COLS, HIDDEN);
    }

    // 2) RoPE on Q and K
    {
        int total = BATCH * SEQ * 2 * HEADS * HALF;
        rope_kernel<<<(total + 255) / 256, 256>>>(qkv_buf, cosp, sinp);
    }

    // 3) TF32 tensor-core flash attention (occ=2)
    {
        dim3 grid(SEQ / BQ, BATCH * HEADS);   // (16, 32)
        flash_attn_tc_kernel<<<grid, 256, ATTN_SMEM_FLOATS * sizeof(float)>>>(
            qkv_buf, attn_buf);
    }

    // 4) Proj GEMM (TF32 TC, 4-stage): [4096,1280] @ [1280,1280] + bias
    {
        dim3 grid(HIDDEN / 128, ROWS / 128);   // (10, 32)
        gemm_tf32_kernel<<<grid, 256, GEMM_SMEM_FLOATS * sizeof(float)>>>(
            attn_buf, proj_w, proj_b, out, ROWS, HIDDEN, HIDDEN);
    }
}

// round 7
// speedup vs baseline: 51.1479x; 1.6478x over previous
#include <cuda_runtime.h>
#include <cuda_fp16.h>
#include <math.h>
#include <stdint.h>

#define HIDDEN   1280
#define HEADS    16
#define HDIM     80
#define HALF     40
#define BATCH    2
#define SEQ      2048
#define ROWS     (BATCH*SEQ)        /* 4096 */
#define QKV_COLS (3*HIDDEN)         /* 3840 */

// Scratch (device globals; no runtime allocation allowed)
__device__ __half g_x_h[(size_t)ROWS * HIDDEN];            // 10.5 MB
__device__ __half g_qkv_h[(size_t)ROWS * QKV_COLS];        // 31.5 MB
__device__ __half g_vT_h[(size_t)BATCH * HEADS * HDIM * SEQ]; // 10.5 MB
__device__ __half g_attn_h[(size_t)ROWS * HIDDEN];         // 10.5 MB
__device__ __half g_wqkvT_h[(size_t)QKV_COLS * HIDDEN];    //  9.8 MB
__device__ __half g_wprojT_h[(size_t)HIDDEN * HIDDEN];     //  3.3 MB

__device__ __forceinline__ void cp_async16(void* smem_dst, const void* gmem_src)
{
    uint32_t s = (uint32_t)__cvta_generic_to_shared(smem_dst);
    asm volatile("cp.async.cg.shared.global [%0], [%1], 16;\n"
                 :: "r"(s), "l"(gmem_src) : "memory");
}
__device__ __forceinline__ void cp_commit()
{
    asm volatile("cp.async.commit_group;\n" ::: "memory");
}

// fp16 HMMA: D(16x8,f32) = A(16x16,f16) x B(16x8,f16) + C
__device__ __forceinline__ void mma_f16(float* d, const uint32_t* a,
                                        uint32_t b0, uint32_t b1,
                                        const float* c)
{
    asm volatile(
        "mma.sync.aligned.m16n8k16.row.col.f32.f16.f16.f32 "
        "{%0,%1,%2,%3}, {%4,%5,%6,%7}, {%8,%9}, {%10,%11,%12,%13};\n"
        : "=f"(d[0]), "=f"(d[1]), "=f"(d[2]), "=f"(d[3])
        : "r"(a[0]), "r"(a[1]), "r"(a[2]), "r"(a[3]),
          "r"(b0), "r"(b1),
          "f"(c[0]), "f"(c[1]), "f"(c[2]), "f"(c[3]));
}

// ---------------------------------------------------------------------------
// fp16 tensor-core GEMM + bias: C[M,N] = A[M,K] @ BT[N,K]^T + bias[N].
// A, BT: __half K-major. Block 128x128, BK=32, 256 threads (8 warps 4m x 2n,
// warp tile 32x64), 3-stage cp.async pipeline.
// LDA_H=40 halves (80B row): conflict-free for the half2 fragment pattern.
// OUT_HALF: C is __half (QKV); else C is float (proj output).
// ---------------------------------------------------------------------------
#define LDA_H   40
#define A_STG_H (128 * LDA_H)   /* 5120 halves */
#define GSTG3   3
#define GEMM_SMEM_BYTES (GSTG3 * 2 * A_STG_H * 2)   /* 61440 */

template<bool OUT_HALF>
__global__ __launch_bounds__(256, 2)
void gemm_h_kernel(const __half* __restrict__ A,
                   const __half* __restrict__ BT,
                   const float* __restrict__ bias,
                   void* __restrict__ Cv,
                   int M, int N, int K)
{
    extern __shared__ __half hsm[];
    __half* Asm = hsm;                       // [3][A_STG_H]
    __half* Bsm = hsm + GSTG3 * A_STG_H;     // [3][A_STG_H]

    const int tid  = threadIdx.x;
    const int w    = tid >> 5;
    const int lane = tid & 31;
    const int g    = lane >> 2;
    const int t    = lane & 3;
    const int wm   = w >> 1;
    const int wn   = w & 1;
    const int rowB = blockIdx.y * 128;
    const int colB = blockIdx.x * 128;

    const __half* Ag = A  + (size_t)rowB * K;
    const __half* Bg = BT + (size_t)colB * K;

    float acc[2][8][4];
    #pragma unroll
    for (int mt = 0; mt < 2; mt++)
        #pragma unroll
        for (int nt = 0; nt < 8; nt++)
            #pragma unroll
            for (int j = 0; j < 4; j++) acc[mt][nt][j] = 0.f;

    const int KT = K >> 5;   // K/32

    auto load_stage = [&](int slot, int k0) {
        __half* Ad = Asm + slot * A_STG_H;
        __half* Bd = Bsm + slot * A_STG_H;
        #pragma unroll
        for (int j = 0; j < 2; j++) {
            int idx = tid + j * 256;          // 0..511
            int r = idx >> 2, c = idx & 3;    // 128 rows x 4 chunks(16B=8 halves)
            cp_async16(Ad + r * LDA_H + c * 8, Ag + (size_t)r * K + k0 + c * 8);
            cp_async16(Bd + r * LDA_H + c * 8, Bg + (size_t)r * K + k0 + c * 8);
        }
    };

    load_stage(0, 0);  cp_commit();
    load_stage(1, 32); cp_commit();

    int slot = 0;
    for (int it = 0; it < KT; it++) {
        asm volatile("cp.async.wait_group 1;\n" ::: "memory");
        __syncthreads();

        // prefetch stage it+2 into slot (it+2)%3 (free since last iter's sync)
        {
            int ps = slot + 2; if (ps >= 3) ps -= 3;
            if (it + 2 < KT) load_stage(ps, (it + 2) << 5);
            cp_commit();   // unconditional: keeps wait_group arithmetic exact
        }

        const __half* At = Asm + slot * A_STG_H;
        const __half* Bt = Bsm + slot * A_STG_H;

        #pragma unroll
        for (int ks = 0; ks < 2; ks++) {
            uint32_t af[2][4];
            #pragma unroll
            for (int mt = 0; mt < 2; mt++) {
                int m = wm * 32 + mt * 16 + g;
                int c = ks * 16 + 2 * t;
                af[mt][0] = *(const uint32_t*)(At + m * LDA_H + c);
                af[mt][1] = *(const uint32_t*)(At + (m + 8) * LDA_H + c);
                af[mt][2] = *(const uint32_t*)(At + m * LDA_H + c + 8);
                af[mt][3] = *(const uint32_t*)(At + (m + 8) * LDA_H + c + 8);
            }
            #pragma unroll
            for (int nt = 0; nt < 8; nt++) {
                int n = wn * 64 + nt * 8 + g;
                int c = ks * 16 + 2 * t;
                uint32_t b0 = *(const uint32_t*)(Bt + n * LDA_H + c);
                uint32_t b1 = *(const uint32_t*)(Bt + n * LDA_H + c + 8);
                mma_f16(acc[0][nt], af[0], b0, b1, acc[0][nt]);
                mma_f16(acc[1][nt], af[1], b0, b1, acc[1][nt]);
            }
        }
        if (++slot == 3) slot = 0;
    }

    // epilogue
    #pragma unroll
    for (int mt = 0; mt < 2; mt++) {
        int m = rowB + wm * 32 + mt * 16 + g;
        #pragma unroll
        for (int nt = 0; nt < 8; nt++) {
            int n = colB + wn * 64 + nt * 8 + 2 * t;
            float2 bv = *(const float2*)(bias + n);
            if (OUT_HALF) {
                __half* C = (__half*)Cv;
                *(__half2*)(C + (size_t)m * N + n) =
                    __floats2half2_rn(acc[mt][nt][0] + bv.x, acc[mt][nt][1] + bv.y);
                *(__half2*)(C + (size_t)(m + 8) * N + n) =
                    __floats2half2_rn(acc[mt][nt][2] + bv.x, acc[mt][nt][3] + bv.y);
            } else {
                float* C = (float*)Cv;
                *(float2*)(C + (size_t)m * N + n) =
                    make_float2(acc[mt][nt][0] + bv.x, acc[mt][nt][1] + bv.y);
                *(float2*)(C + (size_t)(m + 8) * N + n) =
                    make_float2(acc[mt][nt][2] + bv.x, acc[mt][nt][3] + bv.y);
            }
        }
    }
}

// ---------------------------------------------------------------------------
// Pre-passes
// ---------------------------------------------------------------------------
__global__ void convert_half_kernel(const float* __restrict__ in,
                                    __half* __restrict__ out, int n)
{
    int i = blockIdx.x * blockDim.x + threadIdx.x;
    if (i < n) out[i] = __float2half_rn(in[i]);
}

// in[K][N] fp32 -> out[N][K] half (K, N multiples of 32)
__global__ void transpose_f2h_kernel(const float* __restrict__ in,
                                     __half* __restrict__ out,
                                     int K, int N)
{
    __shared__ float tsm[32][33];
    int xi = blockIdx.x * 32 + threadIdx.x;   // N
    int yi = blockIdx.y * 32 + threadIdx.y;   // K
    #pragma unroll
    for (int j = 0; j < 4; j++)
        tsm[threadIdx.y + j * 8][threadIdx.x] = in[(size_t)(yi + j * 8) * N + xi];
    __syncthreads();
    int xo = blockIdx.y * 32 + threadIdx.x;   // K
    int yo = blockIdx.x * 32 + threadIdx.y;   // N
    #pragma unroll
    for (int j = 0; j < 4; j++)
        out[(size_t)(yo + j * 8) * K + xo] =
            __float2half_rn(tsm[threadIdx.x][threadIdx.y + j * 8]);
}

// V slice of g_qkv_h -> per-head transposed g_vT_h[(b*16+h)][d][n]
__global__ void vtrans_kernel(const __half* __restrict__ qkv_h,
                              __half* __restrict__ vT)
{
    __shared__ __half tsm[32][33];
    const int bh = blockIdx.z;
    const int b  = bh >> 4, h = bh & 15;
    const int n0 = blockIdx.x * 32;
    const int d0 = blockIdx.y * 32;

    int n = n0 + threadIdx.x;
    #pragma unroll
    for (int j = 0; j < 4; j++) {
        int d = d0 + threadIdx.y + j * 8;
        if (d < HDIM)
            tsm[threadIdx.y + j * 8][threadIdx.x] =
                qkv_h[(size_t)(b * SEQ + n) * QKV_COLS + 2 * HIDDEN + h * HDIM + d];
    }
    __syncthreads();
    int dd = d0 + threadIdx.x;
    if (dd < HDIM) {
        #pragma unroll
        for (int j = 0; j < 4; j++) {
            int nn = n0 + threadIdx.y + j * 8;
            vT[((size_t)bh * HDIM + dd) * SEQ + nn] =
                tsm[threadIdx.x][threadIdx.y + j * 8];
        }
    }
}

// ---------------------------------------------------------------------------
// RoPE in half, applied in-place to Q and K slices of g_qkv_h.
// One thread per (b,n,qk,h,d2) with d2 = pair index (d = 2*d2).
// ---------------------------------------------------------------------------
__global__ void rope_h_kernel(__half* __restrict__ qkv,
                              const float* __restrict__ cosp,
                              const float* __restrict__ sinp)
{
    int idx = blockIdx.x * blockDim.x + threadIdx.x;
    const int total = BATCH * SEQ * 2 * HEADS * (HALF / 2);
    if (idx >= total) return;

    int d2 = idx % (HALF / 2);  idx /= (HALF / 2);
    int h  = idx % HEADS;       idx /= HEADS;
    int qk = idx % 2;           idx /= 2;
    int n  = idx % SEQ;
    int b  = idx / SEQ;
    int d  = 2 * d2;

    __half* row = qkv + (size_t)(b * SEQ + n) * QKV_COLS + qk * HIDDEN + h * HDIM;
    float2 lo = __half22float2(*(__half2*)(row + d));
    float2 hi = __half22float2(*(__half2*)(row + d + HALF));
    const float* cb = cosp + n * HDIM;
    const float* sb = sinp + n * HDIM;
    float cl0 = cb[d], cl1 = cb[d + 1], ch0 = cb[d + HALF], ch1 = cb[d + HALF + 1];
    float sl0 = sb[d], sl1 = sb[d + 1], sh0 = sb[d + HALF], sh1 = sb[d + HALF + 1];
    *(__half2*)(row + d) =
        __floats2half2_rn(lo.x * cl0 - hi.x * sl0, lo.y * cl1 - hi.y * sl1);
    *(__half2*)(row + d + HALF) =
        __floats2half2_rn(hi.x * ch0 + lo.x * sh0, hi.y * ch1 + lo.y * sh1);
}

// ---------------------------------------------------------------------------
// fp16 tensor-core flash attention.
// Block: 128 queries, 8 warps. Warp w owns rows [w*16, w*16+16).
// S (16x64) = Q x K^T via m16n8k16 (5 k-steps); online softmax in fp32 regs;
// P (half) via warp-private strip; O (16x80, fp32) += P x V (V pre-transposed).
// smem halves: P 8*16*72 | K 2*64*88 (aliased by Q staging) | V 80*72.
// ---------------------------------------------------------------------------
#define BQ      128
#define BKT     64
#define NITER   (SEQ / BKT)
#define LDK_H   88
#define LDP_H   72
#define LDV_H   72
#define P_H     (8 * 16 * LDP_H)    /* 9216 */
#define KBUF_H  (BKT * LDK_H)       /* 5632 */
#define V_H     (HDIM * LDV_H)      /* 5760 */
#define ATTN_SMEM_BYTES ((P_H + 2 * KBUF_H + V_H) * 2)   /* 52480 */

__global__ __launch_bounds__(256, 2)
void flash_attn_h_kernel(const __half* __restrict__ qkv,
                         const __half* __restrict__ vT,
                         __half* __restrict__ out)
{
    extern __shared__ __half hsm[];
    __half* Pbase = hsm;
    __half* Ks    = hsm + P_H;
    __half* Vs    = Ks + 2 * KBUF_H;
    __half* Qs    = Ks;   // alias (transient; 128*88 = 2*KBUF_H exactly)

    const int tid  = threadIdx.x;
    const int w    = tid >> 5;
    const int lane = tid & 31;
    const int g    = lane >> 2;
    const int t    = lane & 3;

    const int q0 = blockIdx.x * BQ;
    const int h  = blockIdx.y & (HEADS - 1);
    const int b  = blockIdx.y >> 4;
    const int bh = blockIdx.y;

    const __half* base = qkv + (size_t)(b * SEQ) * QKV_COLS;
    const __half* kb0  = base + HIDDEN + h * HDIM;
    const __half* vt0  = vT + (size_t)bh * HDIM * SEQ;
    const float SCLF = rsqrtf((float)HDIM) * 1.44269504f;

    // ---- stage Q tile (raw halves), hoist fragments ----
    {
        const __half* qb = base + h * HDIM;
        #pragma unroll
        for (int j = 0; j < 5; j++) {
            int idx = tid + j * 256;          // 0..1279
            int r = idx / 10, c = idx - r * 10;
            cp_async16(Qs + r * LDK_H + c * 8,
                       qb + (size_t)(q0 + r) * QKV_COLS + c * 8);
        }
        cp_commit();
        asm volatile("cp.async.wait_group 0;\n" ::: "memory");
        __syncthreads();
    }

    uint32_t qf[5][4];
    {
        const int r0 = w * 16 + g;
        #pragma unroll
        for (int ks = 0; ks < 5; ks++) {
            int c = ks * 16 + 2 * t;
            qf[ks][0] = *(const uint32_t*)(Qs + r0 * LDK_H + c);
            qf[ks][1] = *(const uint32_t*)(Qs + (r0 + 8) * LDK_H + c);
            qf[ks][2] = *(const uint32_t*)(Qs + r0 * LDK_H + c + 8);
            qf[ks][3] = *(const uint32_t*)(Qs + (r0 + 8) * LDK_H + c + 8);
        }
    }
    __syncthreads();   // Qs dead -> K buffers free

    __half* Pw = Pbase + w * 16 * LDP_H;

    float of[10][4];
    #pragma unroll
    for (int i = 0; i < 10; i++)
        #pragma unroll
        for (int j = 0; j < 4; j++) of[i][j] = 0.f;
    float m1 = -INFINITY, m2 = -INFINITY, l1 = 0.f, l2 = 0.f;

    auto load_k = [&](int it) {
        __half* dst = Ks + (it & 1) * KBUF_H;
        const __half* src = kb0 + (size_t)(it * BKT) * QKV_COLS;
        #pragma unroll
        for (int j = 0; j < 3; j++) {
            int idx = tid + j * 256;
            if (idx < BKT * 10) {
                int r = idx / 10, c = idx - r * 10;
                cp_async16(dst + r * LDK_H + c * 8, src + (size_t)r * QKV_COLS + c * 8);
            }
        }
    };
    auto load_v = [&](int it) {
        const __half* src = vt0 + it * BKT;
        #pragma unroll
        for (int j = 0; j < 3; j++) {
            int idx = tid + j * 256;
            if (idx < HDIM * 8) {
                int r = idx >> 3, c = idx & 7;
                cp_async16(Vs + r * LDV_H + c * 8, src + (size_t)r * SEQ + c * 8);
            }
        }
    };

    load_k(0);
    cp_commit();

    for (int it = 0; it < NITER; it++) {
        load_v(it);
        cp_commit();
        if (it + 1 < NITER) load_k(it + 1);
        cp_commit();

        asm volatile("cp.async.wait_group 1;\n" ::: "memory");   // K_it + V_it ready
        __syncthreads();

        const __half* Kt = Ks + (it & 1) * KBUF_H;

        // ---- S = Q x K^T ----
        float sacc[8][4];
        #pragma unroll
        for (int nt = 0; nt < 8; nt++)
            #pragma unroll
            for (int j = 0; j < 4; j++) sacc[nt][j] = 0.f;

        #pragma unroll
        for (int ks = 0; ks < 5; ks++) {
            int c = ks * 16 + 2 * t;
            #pragma unroll
            for (int nt = 0; nt < 8; nt++) {
                const __half* kr = Kt + (nt * 8 + g) * LDK_H + c;
                uint32_t b0 = *(const uint32_t*)(kr);
                uint32_t b1 = *(const uint32_t*)(kr + 8);
                mma_f16(sacc[nt], qf[ks], b0, b1, sacc[nt]);
            }
        }
        #pragma unroll
        for (int nt = 0; nt < 8; nt++) {
            sacc[nt][0] *= SCLF; sacc[nt][1] *= SCLF;
            sacc[nt][2] *= SCLF; sacc[nt][3] *= SCLF;
        }

        // ---- online softmax (warp-private) ----
        float mx1 = -INFINITY, mx2 = -INFINITY;
        #pragma unroll
        for (int nt = 0; nt < 8; nt++) {
            mx1 = fmaxf(mx1, fmaxf(sacc[nt][0], sacc[nt][1]));
            mx2 = fmaxf(mx2, fmaxf(sacc[nt][2], sacc[nt][3]));
        }
        mx1 = fmaxf(mx1, __shfl_xor_sync(0xffffffff, mx1, 1));
        mx1 = fmaxf(mx1, __shfl_xor_sync(0xffffffff, mx1, 2));
        mx2 = fmaxf(mx2, __shfl_xor_sync(0xffffffff, mx2, 1));
        mx2 = fmaxf(mx2, __shfl_xor_sync(0xffffffff, mx2, 2));

        float mn1 = fmaxf(m1, mx1);
        float mn2 = fmaxf(m2, mx2);
        float a1 = exp2f(m1 - mn1);
        float a2 = exp2f(m2 - mn2);
        m1 = mn1; m2 = mn2;

        float s1 = 0.f, s2 = 0.f;
        #pragma unroll
        for (int nt = 0; nt < 8; nt++) {
            sacc[nt][0] = exp2f(sacc[nt][0] - mn1);
            sacc[nt][1] = exp2f(sacc[nt][1] - mn1);
            sacc[nt][2] = exp2f(sacc[nt][2] - mn2);
            sacc[nt][3] = exp2f(sacc[nt][3] - mn2);
            s1 += sacc[nt][0] + sacc[nt][1];
            s2 += sacc[nt][2] + sacc[nt][3];
        }
        s1 += __shfl_xor_sync(0xffffffff, s1, 1);
        s1 += __shfl_xor_sync(0xffffffff, s1, 2);
        s2 += __shfl_xor_sync(0xffffffff, s2, 1);
        s2 += __shfl_xor_sync(0xffffffff, s2, 2);
        l1 = l1 * a1 + s1;
        l2 = l2 * a2 + s2;

        #pragma unroll
        for (int nt = 0; nt < 10; nt++) {
            of[nt][0] *= a1; of[nt][1] *= a1;
            of[nt][2] *= a2; of[nt][3] *= a2;
        }

        // ---- P -> warp-private half strip ----
        __syncwarp();
        #pragma unroll
        for (int nt = 0; nt < 8; nt++) {
            *(__half2*)(Pw + g * LDP_H + nt * 8 + 2 * t) =
                __floats2half2_rn(sacc[nt][0], sacc[nt][1]);
            *(__half2*)(Pw + (g + 8) * LDP_H + nt * 8 + 2 * t) =
                __floats2half2_rn(sacc[nt][2], sacc[nt][3]);
        }
        __syncwarp();

        // ---- O += P x V (V transposed: Vs[d][kk]) ----
        #pragma unroll
        for (int ks = 0; ks < 4; ks++) {
            int c = ks * 16 + 2 * t;
            uint32_t af[4];
            af[0] = *(const uint32_t*)(Pw + g * LDP_H + c);
            af[1] = *(const uint32_t*)(Pw + (g + 8) * LDP_H + c);
            af[2] = *(const uint32_t*)(Pw + g * LDP_H + c + 8);
            af[3] = *(const uint32_t*)(Pw + (g + 8) * LDP_H + c + 8);
            #pragma unroll
            for (int nt = 0; nt < 10; nt++) {
                const __half* vr = Vs + (nt * 8 + g) * LDV_H + c;
                uint32_t b0 = *(const uint32_t*)(vr);
                uint32_t b1 = *(const uint32_t*)(vr + 8);
                mma_f16(of[nt], af, b0, b1, of[nt]);
            }
        }
        __syncthreads();   // Vs / K slot reads done before next iter's issues
    }

    // ---- epilogue: O /= l, store half ----
    const float inv1 = 1.f / l1;
    const float inv2 = 1.f / l2;
    const int r1 = q0 + w * 16 + g;
    __half* ob = out + (size_t)(b * SEQ) * HIDDEN + h * HDIM;
    #pragma unroll
    for (int nt = 0; nt < 10; nt++) {
        int c = nt * 8 + 2 * t;
        *(__half2*)(ob + (size_t)r1 * HIDDEN + c) =
            __floats2half2_rn(of[nt][0] * inv1, of[nt][1] * inv1);
        *(__half2*)(ob + (size_t)(r1 + 8) * HIDDEN + c) =
            __floats2half2_rn(of[nt][2] * inv2, of[nt][3] * inv2);
    }
}

// ---------------------------------------------------------------------------
extern "C" void kernel_launch(void* const* d_in, const int* in_sizes, int n_in,
                              void* d_out, int out_size)
{
    const float* x      = (const float*)d_in[0];
    const float* cosp   = (const float*)d_in[1];
    const float* sinp   = (const float*)d_in[2];
    const float* qkv_w  = (const float*)d_in[3];
    const float* qkv_b  = (const float*)d_in[4];
    const float* proj_w = (const float*)d_in[5];
    const float* proj_b = (const float*)d_in[6];
    float* out = (float*)d_out;

    __half *x_h, *qkv_h, *vT_h, *attn_h, *wqkvT_h, *wprojT_h;
    cudaGetSymbolAddress((void**)&x_h,      g_x_h);
    cudaGetSymbolAddress((void**)&qkv_h,    g_qkv_h);
    cudaGetSymbolAddress((void**)&vT_h,     g_vT_h);
    cudaGetSymbolAddress((void**)&attn_h,   g_attn_h);
    cudaGetSymbolAddress((void**)&wqkvT_h,  g_wqkvT_h);
    cudaGetSymbolAddress((void**)&wprojT_h, g_wprojT_h);

    static int attr_set = 0;
    if (!attr_set) {
        cudaFuncSetAttribute(gemm_h_kernel<true>,
                             cudaFuncAttributeMaxDynamicSharedMemorySize, GEMM_SMEM_BYTES);
        cudaFuncSetAttribute(gemm_h_kernel<false>,
                             cudaFuncAttributeMaxDynamicSharedMemorySize, GEMM_SMEM_BYTES);
        cudaFuncSetAttribute(flash_attn_h_kernel,
                             cudaFuncAttributeMaxDynamicSharedMemorySize, ATTN_SMEM_BYTES);
        attr_set = 1;
    }

    // 0) pre-passes: x -> half; weights -> transposed half
    {
        int n = ROWS * HIDDEN;
        convert_half_kernel<<<(n + 255) / 256, 256>>>(x, x_h, n);
        dim3 blk(32, 8);
        transpose_f2h_kernel<<<dim3(QKV_COLS / 32, HIDDEN / 32), blk>>>(
            qkv_w, wqkvT_h, HIDDEN, QKV_COLS);
        transpose_f2h_kernel<<<dim3(HIDDEN / 32, HIDDEN / 32), blk>>>(
            proj_w, wprojT_h, HIDDEN, HIDDEN);
    }

    // 1) QKV GEMM (fp16 HMMA): [4096,1280] @ [1280,3840] + bias -> half
    {
        dim3 grid(QKV_COLS / 128, ROWS / 128);   // (30, 32)
        gemm_h_kernel<true><<<grid, 256, GEMM_SMEM_BYTES>>>(
            x_h, wqkvT_h, qkv_b, qkv_h, ROWS, QKV_COLS, HIDDEN);
    }

    // 2) RoPE (half)
    {
        int total = BATCH * SEQ * 2 * HEADS * (HALF / 2);
        rope_h_kernel<<<(total + 255) / 256, 256>>>(qkv_h, cosp, sinp);
    }

    // 3) V transpose per head: [n][d] -> [d][n]
    {
        dim3 blk(32, 8);
        vtrans_kernel<<<dim3(SEQ / 32, (HDIM + 31) / 32, BATCH * HEADS), blk>>>(
            qkv_h, vT_h);
    }

    // 4) fp16 flash attention
    {
        dim3 grid(SEQ / BQ, BATCH * HEADS);   // (16, 32)
        flash_attn_h_kernel<<<grid, 256, ATTN_SMEM_BYTES>>>(qkv_h, vT_h, attn_h);
    }

    // 5) Proj GEMM (fp16 HMMA): [4096,1280] @ [1280,1280] + bias -> fp32 out
    {
        dim3 grid(HIDDEN / 128, ROWS / 128);   // (10, 32)
        gemm_h_kernel<false><<<grid, 256, GEMM_SMEM_BYTES>>>(
            attn_h, wprojT_h, proj_b, out, ROWS, HIDDEN, HIDDEN);
    }
}

// round 8
// speedup vs baseline: 60.2153x; 1.1773x over previous
#include <cuda_runtime.h>
#include <cuda_fp16.h>
#include <math.h>
#include <stdint.h>

#define HIDDEN   1280
#define HEADS    16
#define HDIM     80
#define HALF     40
#define BATCH    2
#define SEQ      2048
#define ROWS     (BATCH*SEQ)        /* 4096 */
#define QKV_COLS (3*HIDDEN)         /* 3840 */

// Scratch (device globals; no runtime allocation allowed)
__device__ __half g_x_h[(size_t)ROWS * HIDDEN];            // 10.5 MB
__device__ __half g_qkv_h[(size_t)ROWS * QKV_COLS];        // 31.5 MB
__device__ __half g_attn_h[(size_t)ROWS * HIDDEN];         // 10.5 MB
__device__ __half g_wqkvT_h[(size_t)QKV_COLS * HIDDEN];    //  9.8 MB
__device__ __half g_wprojT_h[(size_t)HIDDEN * HIDDEN];     //  3.3 MB

__device__ __forceinline__ void cp_async16(void* smem_dst, const void* gmem_src)
{
    uint32_t s = (uint32_t)__cvta_generic_to_shared(smem_dst);
    asm volatile("cp.async.cg.shared.global [%0], [%1], 16;\n"
                 :: "r"(s), "l"(gmem_src) : "memory");
}
__device__ __forceinline__ void cp_commit()
{
    asm volatile("cp.async.commit_group;\n" ::: "memory");
}

__device__ __forceinline__ void ldmx4(uint32_t* r, uint32_t addr)
{
    asm volatile("ldmatrix.sync.aligned.m8n8.x4.shared.b16 {%0,%1,%2,%3}, [%4];"
                 : "=r"(r[0]), "=r"(r[1]), "=r"(r[2]), "=r"(r[3]) : "r"(addr));
}
__device__ __forceinline__ void ldmx4_t(uint32_t* r, uint32_t addr)
{
    asm volatile("ldmatrix.sync.aligned.m8n8.x4.trans.shared.b16 {%0,%1,%2,%3}, [%4];"
                 : "=r"(r[0]), "=r"(r[1]), "=r"(r[2]), "=r"(r[3]) : "r"(addr));
}

// fp16 HMMA: D(16x8,f32) = A(16x16,f16) x B(16x8,f16) + C
__device__ __forceinline__ void mma_f16(float* d, const uint32_t* a,
                                        uint32_t b0, uint32_t b1,
                                        const float* c)
{
    asm volatile(
        "mma.sync.aligned.m16n8k16.row.col.f32.f16.f16.f32 "
        "{%0,%1,%2,%3}, {%4,%5,%6,%7}, {%8,%9}, {%10,%11,%12,%13};\n"
        : "=f"(d[0]), "=f"(d[1]), "=f"(d[2]), "=f"(d[3])
        : "r"(a[0]), "r"(a[1]), "r"(a[2]), "r"(a[3]),
          "r"(b0), "r"(b1),
          "f"(c[0]), "f"(c[1]), "f"(c[2]), "f"(c[3]));
}

// ---------------------------------------------------------------------------
// fp16 tensor-core GEMM + bias: C[M,N] = A[M,K] @ BT[N,K]^T + bias[N].
// Block 128x128, BK=32, 256 threads (8 warps 4m x 2n), 3-stage cp.async,
// ldmatrix fragment loads. LDA_H=40 halves (80B rows, 16B-aligned,
// conflict-free for ldmatrix).
// ---------------------------------------------------------------------------
#define LDA_H   40
#define A_STG_H (128 * LDA_H)   /* 5120 halves */
#define GSTG3   3
#define GEMM_SMEM_BYTES (GSTG3 * 2 * A_STG_H * 2)   /* 61440 */

template<bool OUT_HALF>
__global__ __launch_bounds__(256, 2)
void gemm_h_kernel(const __half* __restrict__ A,
                   const __half* __restrict__ BT,
                   const float* __restrict__ bias,
                   void* __restrict__ Cv,
                   int M, int N, int K)
{
    extern __shared__ __half hsm[];
    __half* Asm = hsm;                       // [3][A_STG_H]
    __half* Bsm = hsm + GSTG3 * A_STG_H;     // [3][A_STG_H]

    const int tid  = threadIdx.x;
    const int w    = tid >> 5;
    const int lane = tid & 31;
    const int g    = lane >> 2;
    const int t    = lane & 3;
    const int wm   = w >> 1;
    const int wn   = w & 1;
    const int rowB = blockIdx.y * 128;
    const int colB = blockIdx.x * 128;

    // ldmatrix per-lane role: tile = lane/8, row-in-tile = lane%8
    const int frag_r = ((lane >> 3) & 1) * 8 + (lane & 7);
    const int frag_c = (lane >> 4) * 8;

    const uint32_t As_b = (uint32_t)__cvta_generic_to_shared(Asm);
    const uint32_t Bs_b = (uint32_t)__cvta_generic_to_shared(Bsm);

    const __half* Ag = A  + (size_t)rowB * K;
    const __half* Bg = BT + (size_t)colB * K;

    float acc[2][8][4];
    #pragma unroll
    for (int mt = 0; mt < 2; mt++)
        #pragma unroll
        for (int nt = 0; nt < 8; nt++)
            #pragma unroll
            for (int j = 0; j < 4; j++) acc[mt][nt][j] = 0.f;

    const int KT = K >> 5;

    auto load_stage = [&](int slot, int k0) {
        __half* Ad = Asm + slot * A_STG_H;
        __half* Bd = Bsm + slot * A_STG_H;
        #pragma unroll
        for (int j = 0; j < 2; j++) {
            int idx = tid + j * 256;
            int r = idx >> 2, c = idx & 3;
            cp_async16(Ad + r * LDA_H + c * 8, Ag + (size_t)r * K + k0 + c * 8);
            cp_async16(Bd + r * LDA_H + c * 8, Bg + (size_t)r * K + k0 + c * 8);
        }
    };

    load_stage(0, 0);  cp_commit();
    load_stage(1, 32); cp_commit();

    int slot = 0;
    for (int it = 0; it < KT; it++) {
        asm volatile("cp.async.wait_group 1;\n" ::: "memory");
        __syncthreads();

        {
            int ps = slot + 2; if (ps >= 3) ps -= 3;
            if (it + 2 < KT) load_stage(ps, (it + 2) << 5);
            cp_commit();
        }

        const uint32_t At = As_b + slot * A_STG_H * 2;
        const uint32_t Bt = Bs_b + slot * A_STG_H * 2;

        #pragma unroll
        for (int ks = 0; ks < 2; ks++) {
            const int col = ks * 16 + frag_c;
            uint32_t a[2][4];
            #pragma unroll
            for (int mt = 0; mt < 2; mt++) {
                int row = wm * 32 + mt * 16 + frag_r;
                ldmx4(a[mt], At + (row * LDA_H + col) * 2);
            }
            #pragma unroll
            for (int np = 0; np < 4; np++) {
                int row = wn * 64 + np * 16 + frag_r;
                uint32_t br[4];
                ldmx4(br, Bt + (row * LDA_H + col) * 2);
                mma_f16(acc[0][2 * np],     a[0], br[0], br[2], acc[0][2 * np]);
                mma_f16(acc[0][2 * np + 1], a[0], br[1], br[3], acc[0][2 * np + 1]);
                mma_f16(acc[1][2 * np],     a[1], br[0], br[2], acc[1][2 * np]);
                mma_f16(acc[1][2 * np + 1], a[1], br[1], br[3], acc[1][2 * np + 1]);
            }
        }
        if (++slot == 3) slot = 0;
    }

    #pragma unroll
    for (int mt = 0; mt < 2; mt++) {
        int m = rowB + wm * 32 + mt * 16 + g;
        #pragma unroll
        for (int nt = 0; nt < 8; nt++) {
            int n = colB + wn * 64 + nt * 8 + 2 * t;
            float2 bv = *(const float2*)(bias + n);
            if (OUT_HALF) {
                __half* C = (__half*)Cv;
                *(__half2*)(C + (size_t)m * N + n) =
                    __floats2half2_rn(acc[mt][nt][0] + bv.x, acc[mt][nt][1] + bv.y);
                *(__half2*)(C + (size_t)(m + 8) * N + n) =
                    __floats2half2_rn(acc[mt][nt][2] + bv.x, acc[mt][nt][3] + bv.y);
            } else {
                float* C = (float*)Cv;
                *(float2*)(C + (size_t)m * N + n) =
                    make_float2(acc[mt][nt][0] + bv.x, acc[mt][nt][1] + bv.y);
                *(float2*)(C + (size_t)(m + 8) * N + n) =
                    make_float2(acc[mt][nt][2] + bv.x, acc[mt][nt][3] + bv.y);
            }
        }
    }
}

// ---------------------------------------------------------------------------
// Pre-passes
// ---------------------------------------------------------------------------
__global__ void convert_half_kernel(const float* __restrict__ in,
                                    __half* __restrict__ out, int n)
{
    int i = blockIdx.x * blockDim.x + threadIdx.x;
    if (i < n) out[i] = __float2half_rn(in[i]);
}

__global__ void transpose_f2h_kernel(const float* __restrict__ in,
                                     __half* __restrict__ out,
                                     int K, int N)
{
    __shared__ float tsm[32][33];
    int xi = blockIdx.x * 32 + threadIdx.x;
    int yi = blockIdx.y * 32 + threadIdx.y;
    #pragma unroll
    for (int j = 0; j < 4; j++)
        tsm[threadIdx.y + j * 8][threadIdx.x] = in[(size_t)(yi + j * 8) * N + xi];
    __syncthreads();
    int xo = blockIdx.y * 32 + threadIdx.x;
    int yo = blockIdx.x * 32 + threadIdx.y;
    #pragma unroll
    for (int j = 0; j < 4; j++)
        out[(size_t)(yo + j * 8) * K + xo] =
            __float2half_rn(tsm[threadIdx.x][threadIdx.y + j * 8]);
}

// ---------------------------------------------------------------------------
// RoPE in half; Q rows additionally scaled by rsqrt(HDIM)*log2(e) so the
// attention kernel's scores come out in log2 units with no extra multiplies.
// ---------------------------------------------------------------------------
__global__ void rope_h_kernel(__half* __restrict__ qkv,
                              const float* __restrict__ cosp,
                              const float* __restrict__ sinp)
{
    int idx = blockIdx.x * blockDim.x + threadIdx.x;
    const int total = BATCH * SEQ * 2 * HEADS * (HALF / 2);
    if (idx >= total) return;

    int d2 = idx % (HALF / 2);  idx /= (HALF / 2);
    int h  = idx % HEADS;       idx /= HEADS;
    int qk = idx % 2;           idx /= 2;
    int n  = idx % SEQ;
    int b  = idx / SEQ;
    int d  = 2 * d2;

    const float SCLF = rsqrtf((float)HDIM) * 1.44269504f;
    const float s = (qk == 0) ? SCLF : 1.f;

    __half* row = qkv + (size_t)(b * SEQ + n) * QKV_COLS + qk * HIDDEN + h * HDIM;
    float2 lo = __half22float2(*(__half2*)(row + d));
    float2 hi = __half22float2(*(__half2*)(row + d + HALF));
    const float* cb = cosp + n * HDIM;
    const float* sb = sinp + n * HDIM;
    float cl0 = cb[d], cl1 = cb[d + 1], ch0 = cb[d + HALF], ch1 = cb[d + HALF + 1];
    float sl0 = sb[d], sl1 = sb[d + 1], sh0 = sb[d + HALF], sh1 = sb[d + HALF + 1];
    *(__half2*)(row + d) =
        __floats2half2_rn(s * (lo.x * cl0 - hi.x * sl0), s * (lo.y * cl1 - hi.y * sl1));
    *(__half2*)(row + d + HALF) =
        __floats2half2_rn(s * (hi.x * ch0 + lo.x * sh0), s * (hi.y * ch1 + lo.y * sh1));
}

// ---------------------------------------------------------------------------
// fp16 flash attention with ldmatrix fragments.
// K/V tiles loaded K-major from qkv; V B-fragments via ldmatrix.trans
// (no pre-transpose pass). P via warp-private strip + ldmatrix.
// ---------------------------------------------------------------------------
#define BQ      128
#define BKT     64
#define NITER   (SEQ / BKT)
#define LDK_H   88
#define LDP_H   72
#define P_H     (8 * 16 * LDP_H)    /* 9216 */
#define KBUF_H  (BKT * LDK_H)       /* 5632 */
#define ATTN_SMEM_BYTES ((P_H + 3 * KBUF_H) * 2)   /* 52224 */

__global__ __launch_bounds__(256, 2)
void flash_attn_h_kernel(const __half* __restrict__ qkv,
                         __half* __restrict__ out)
{
    extern __shared__ __half hsm[];
    __half* Pbase = hsm;
    __half* Ks    = hsm + P_H;          // 2 x [BKT][LDK_H]
    __half* Vs    = Ks + 2 * KBUF_H;    // 1 x [BKT][LDK_H]
    __half* Qs    = Ks;                 // alias (128*88 = 2*KBUF_H)

    const int tid  = threadIdx.x;
    const int w    = tid >> 5;
    const int lane = tid & 31;
    const int g    = lane >> 2;
    const int t    = lane & 3;
    const int frag_r = ((lane >> 3) & 1) * 8 + (lane & 7);
    const int frag_c = (lane >> 4) * 8;

    const uint32_t P_b = (uint32_t)__cvta_generic_to_shared(Pbase);
    const uint32_t K_b = (uint32_t)__cvta_generic_to_shared(Ks);
    const uint32_t V_b = (uint32_t)__cvta_generic_to_shared(Vs);
    const uint32_t Q_b = K_b;

    const int q0 = blockIdx.x * BQ;
    const int h  = blockIdx.y & (HEADS - 1);
    const int b  = blockIdx.y >> 4;

    const __half* base = qkv + (size_t)(b * SEQ) * QKV_COLS;
    const __half* kb0  = base + HIDDEN + h * HDIM;
    const __half* vb0  = base + 2 * HIDDEN + h * HDIM;

    // ---- stage Q tile, hoist fragments via ldmatrix ----
    {
        const __half* qb = base + h * HDIM;
        #pragma unroll
        for (int j = 0; j < 5; j++) {
            int idx = tid + j * 256;
            int r = idx / 10, c = idx - r * 10;
            cp_async16(Qs + r * LDK_H + c * 8,
                       qb + (size_t)(q0 + r) * QKV_COLS + c * 8);
        }
        cp_commit();
        asm volatile("cp.async.wait_group 0;\n" ::: "memory");
        __syncthreads();
    }

    uint32_t qf[5][4];
    {
        const int row = w * 16 + frag_r;
        #pragma unroll
        for (int ks = 0; ks < 5; ks++)
            ldmx4(qf[ks], Q_b + (row * LDK_H + ks * 16 + frag_c) * 2);
    }
    __syncthreads();   // Qs dead -> K buffers free

    __half* Pw = Pbase + w * 16 * LDP_H;
    const uint32_t Pw_b = P_b + w * 16 * LDP_H * 2;

    float of[10][4];
    #pragma unroll
    for (int i = 0; i < 10; i++)
        #pragma unroll
        for (int j = 0; j < 4; j++) of[i][j] = 0.f;
    float m1 = -INFINITY, m2 = -INFINITY, l1 = 0.f, l2 = 0.f;

    auto load_tile = [&](__half* dst, const __half* src) {
        #pragma unroll
        for (int j = 0; j < 3; j++) {
            int idx = tid + j * 256;
            if (idx < BKT * 10) {
                int r = idx / 10, c = idx - r * 10;
                cp_async16(dst + r * LDK_H + c * 8, src + (size_t)r * QKV_COLS + c * 8);
            }
        }
    };

    load_tile(Ks, kb0);
    cp_commit();

    for (int it = 0; it < NITER; it++) {
        load_tile(Vs, vb0 + (size_t)(it * BKT) * QKV_COLS);
        cp_commit();
        if (it + 1 < NITER)
            load_tile(Ks + ((it + 1) & 1) * KBUF_H,
                      kb0 + (size_t)((it + 1) * BKT) * QKV_COLS);
        cp_commit();

        asm volatile("cp.async.wait_group 1;\n" ::: "memory");
        __syncthreads();

        const uint32_t Kt = K_b + (it & 1) * KBUF_H * 2;

        // ---- S = Q x K^T ----
        float sacc[8][4];
        #pragma unroll
        for (int nt = 0; nt < 8; nt++)
            #pragma unroll
            for (int j = 0; j < 4; j++) sacc[nt][j] = 0.f;

        #pragma unroll
        for (int ks = 0; ks < 5; ks++) {
            const int col = ks * 16 + frag_c;
            #pragma unroll
            for (int np = 0; np < 4; np++) {
                uint32_t br[4];
                ldmx4(br, Kt + ((np * 16 + frag_r) * LDK_H + col) * 2);
                mma_f16(sacc[2 * np],     qf[ks], br[0], br[2], sacc[2 * np]);
                mma_f16(sacc[2 * np + 1], qf[ks], br[1], br[3], sacc[2 * np + 1]);
            }
        }

        // ---- online softmax (scores already in log2 units) ----
        float mx1 = -INFINITY, mx2 = -INFINITY;
        #pragma unroll
        for (int nt = 0; nt < 8; nt++) {
            mx1 = fmaxf(mx1, fmaxf(sacc[nt][0], sacc[nt][1]));
            mx2 = fmaxf(mx2, fmaxf(sacc[nt][2], sacc[nt][3]));
        }
        mx1 = fmaxf(mx1, __shfl_xor_sync(0xffffffff, mx1, 1));
        mx1 = fmaxf(mx1, __shfl_xor_sync(0xffffffff, mx1, 2));
        mx2 = fmaxf(mx2, __shfl_xor_sync(0xffffffff, mx2, 1));
        mx2 = fmaxf(mx2, __shfl_xor_sync(0xffffffff, mx2, 2));

        float mn1 = fmaxf(m1, mx1);
        float mn2 = fmaxf(m2, mx2);
        float a1 = exp2f(m1 - mn1);
        float a2 = exp2f(m2 - mn2);
        m1 = mn1; m2 = mn2;

        float s1 = 0.f, s2 = 0.f;
        #pragma unroll
        for (int nt = 0; nt < 8; nt++) {
            sacc[nt][0] = exp2f(sacc[nt][0] - mn1);
            sacc[nt][1] = exp2f(sacc[nt][1] - mn1);
            sacc[nt][2] = exp2f(sacc[nt][2] - mn2);
            sacc[nt][3] = exp2f(sacc[nt][3] - mn2);
            s1 += sacc[nt][0] + sacc[nt][1];
            s2 += sacc[nt][2] + sacc[nt][3];
        }
        s1 += __shfl_xor_sync(0xffffffff, s1, 1);
        s1 += __shfl_xor_sync(0xffffffff, s1, 2);
        s2 += __shfl_xor_sync(0xffffffff, s2, 1);
        s2 += __shfl_xor_sync(0xffffffff, s2, 2);
        l1 = l1 * a1 + s1;
        l2 = l2 * a2 + s2;

        #pragma unroll
        for (int nt = 0; nt < 10; nt++) {
            of[nt][0] *= a1; of[nt][1] *= a1;
            of[nt][2] *= a2; of[nt][3] *= a2;
        }

        // ---- P -> warp-private strip ----
        __syncwarp();
        #pragma unroll
        for (int nt = 0; nt < 8; nt++) {
            *(__half2*)(Pw + g * LDP_H + nt * 8 + 2 * t) =
                __floats2half2_rn(sacc[nt][0], sacc[nt][1]);
            *(__half2*)(Pw + (g + 8) * LDP_H + nt * 8 + 2 * t) =
                __floats2half2_rn(sacc[nt][2], sacc[nt][3]);
        }
        __syncwarp();

        // ---- O += P x V  (V fragments via ldmatrix.trans from K-major Vs) ----
        #pragma unroll
        for (int ks = 0; ks < 4; ks++) {
            uint32_t af[4];
            ldmx4(af, Pw_b + (frag_r * LDP_H + ks * 16 + frag_c) * 2);
            const int vrow = ks * 16 + frag_r;   // key index
            #pragma unroll
            for (int vp = 0; vp < 5; vp++) {
                uint32_t br[4];
                ldmx4_t(br, V_b + (vrow * LDK_H + vp * 16 + frag_c) * 2);
                mma_f16(of[2 * vp],     af, br[0], br[1], of[2 * vp]);
                mma_f16(of[2 * vp + 1], af, br[2], br[3], of[2 * vp + 1]);
            }
        }
        __syncthreads();
    }

    // ---- epilogue ----
    const float inv1 = 1.f / l1;
    const float inv2 = 1.f / l2;
    const int r1 = q0 + w * 16 + g;
    __half* ob = out + (size_t)(b * SEQ) * HIDDEN + h * HDIM;
    #pragma unroll
    for (int nt = 0; nt < 10; nt++) {
        int c = nt * 8 + 2 * t;
        *(__half2*)(ob + (size_t)r1 * HIDDEN + c) =
            __floats2half2_rn(of[nt][0] * inv1, of[nt][1] * inv1);
        *(__half2*)(ob + (size_t)(r1 + 8) * HIDDEN + c) =
            __floats2half2_rn(of[nt][2] * inv2, of[nt][3] * inv2);
    }
}

// ---------------------------------------------------------------------------
extern "C" void kernel_launch(void* const* d_in, const int* in_sizes, int n_in,
                              void* d_out, int out_size)
{
    const float* x      = (const float*)d_in[0];
    const float* cosp   = (const float*)d_in[1];
    const float* sinp   = (const float*)d_in[2];
    const float* qkv_w  = (const float*)d_in[3];
    const float* qkv_b  = (const float*)d_in[4];
    const float* proj_w = (const float*)d_in[5];
    const float* proj_b = (const float*)d_in[6];
    float* out = (float*)d_out;

    __half *x_h, *qkv_h, *attn_h, *wqkvT_h, *wprojT_h;
    cudaGetSymbolAddress((void**)&x_h,      g_x_h);
    cudaGetSymbolAddress((void**)&qkv_h,    g_qkv_h);
    cudaGetSymbolAddress((void**)&attn_h,   g_attn_h);
    cudaGetSymbolAddress((void**)&wqkvT_h,  g_wqkvT_h);
    cudaGetSymbolAddress((void**)&wprojT_h, g_wprojT_h);

    static int attr_set = 0;
    if (!attr_set) {
        cudaFuncSetAttribute(gemm_h_kernel<true>,
                             cudaFuncAttributeMaxDynamicSharedMemorySize, GEMM_SMEM_BYTES);
        cudaFuncSetAttribute(gemm_h_kernel<false>,
                             cudaFuncAttributeMaxDynamicSharedMemorySize, GEMM_SMEM_BYTES);
        cudaFuncSetAttribute(flash_attn_h_kernel,
                             cudaFuncAttributeMaxDynamicSharedMemorySize, ATTN_SMEM_BYTES);
        attr_set = 1;
    }

    // 0) pre-passes
    {
        int n = ROWS * HIDDEN;
        convert_half_kernel<<<(n + 255) / 256, 256>>>(x, x_h, n);
        dim3 blk(32, 8);
        transpose_f2h_kernel<<<dim3(QKV_COLS / 32, HIDDEN / 32), blk>>>(
            qkv_w, wqkvT_h, HIDDEN, QKV_COLS);
        transpose_f2h_kernel<<<dim3(HIDDEN / 32, HIDDEN / 32), blk>>>(
            proj_w, wprojT_h, HIDDEN, HIDDEN);
    }

    // 1) QKV GEMM (fp16 HMMA + ldmatrix)
    {
        dim3 grid(QKV_COLS / 128, ROWS / 128);
        gemm_h_kernel<true><<<grid, 256, GEMM_SMEM_BYTES>>>(
            x_h, wqkvT_h, qkv_b, qkv_h, ROWS, QKV_COLS, HIDDEN);
    }

    // 2) RoPE (half; Q pre-scaled)
    {
        int total = BATCH * SEQ * 2 * HEADS * (HALF / 2);
        rope_h_kernel<<<(total + 255) / 256, 256>>>(qkv_h, cosp, sinp);
    }

    // 3) fp16 flash attention (ldmatrix + trans-V)
    {
        dim3 grid(SEQ / BQ, BATCH * HEADS);
        flash_attn_h_kernel<<<grid, 256, ATTN_SMEM_BYTES>>>(qkv_h, attn_h);
    }

    // 4) Proj GEMM (fp16 HMMA + ldmatrix) -> fp32 out
    {
        dim3 grid(HIDDEN / 128, ROWS / 128);
        gemm_h_kernel<false><<<grid, 256, GEMM_SMEM_BYTES>>>(
            attn_h, wprojT_h, proj_b, out, ROWS, HIDDEN, HIDDEN);
    }
}

// round 9
// speedup vs baseline: 62.5600x; 1.0389x over previous
#include <cuda_runtime.h>
#include <cuda_fp16.h>
#include <math.h>
#include <stdint.h>

#define HIDDEN   1280
#define HEADS    16
#define HDIM     80
#define HALF     40
#define BATCH    2
#define SEQ      2048
#define ROWS     (BATCH*SEQ)        /* 4096 */
#define QKV_COLS (3*HIDDEN)         /* 3840 */

// Scratch (device globals; no runtime allocation allowed)
__device__ __half g_x_h[(size_t)ROWS * HIDDEN];            // 10.5 MB
__device__ __half g_qkv_h[(size_t)ROWS * QKV_COLS];        // 31.5 MB
__device__ __half g_attn_h[(size_t)ROWS * HIDDEN];         // 10.5 MB
__device__ __half g_wqkvT_h[(size_t)QKV_COLS * HIDDEN];    //  9.8 MB
__device__ __half g_wprojT_h[(size_t)HIDDEN * HIDDEN];     //  3.3 MB

__device__ __forceinline__ void cp_async16(void* smem_dst, const void* gmem_src)
{
    uint32_t s = (uint32_t)__cvta_generic_to_shared(smem_dst);
    asm volatile("cp.async.cg.shared.global [%0], [%1], 16;\n"
                 :: "r"(s), "l"(gmem_src) : "memory");
}
__device__ __forceinline__ void cp_commit()
{
    asm volatile("cp.async.commit_group;\n" ::: "memory");
}

__device__ __forceinline__ void ldmx4(uint32_t* r, uint32_t addr)
{
    asm volatile("ldmatrix.sync.aligned.m8n8.x4.shared.b16 {%0,%1,%2,%3}, [%4];"
                 : "=r"(r[0]), "=r"(r[1]), "=r"(r[2]), "=r"(r[3]) : "r"(addr));
}
__device__ __forceinline__ void ldmx4_t(uint32_t* r, uint32_t addr)
{
    asm volatile("ldmatrix.sync.aligned.m8n8.x4.trans.shared.b16 {%0,%1,%2,%3}, [%4];"
                 : "=r"(r[0]), "=r"(r[1]), "=r"(r[2]), "=r"(r[3]) : "r"(addr));
}

// fp16 HMMA: D(16x8,f32) = A(16x16,f16) x B(16x8,f16) + C
__device__ __forceinline__ void mma_f16(float* d, const uint32_t* a,
                                        uint32_t b0, uint32_t b1,
                                        const float* c)
{
    asm volatile(
        "mma.sync.aligned.m16n8k16.row.col.f32.f16.f16.f32 "
        "{%0,%1,%2,%3}, {%4,%5,%6,%7}, {%8,%9}, {%10,%11,%12,%13};\n"
        : "=f"(d[0]), "=f"(d[1]), "=f"(d[2]), "=f"(d[3])
        : "r"(a[0]), "r"(a[1]), "r"(a[2]), "r"(a[3]),
          "r"(b0), "r"(b1),
          "f"(c[0]), "f"(c[1]), "f"(c[2]), "f"(c[3]));
}

// ---------------------------------------------------------------------------
// fp16 tensor-core GEMM + bias: C[M,N] = A[M,K] @ BT[N,K]^T + bias[N].
// Block 128x128, BK=64, 256 threads (8 warps 4m x 2n), 3-stage cp.async,
// ONE wait+sync per 64-deep k-iter. LDA_H=72 halves (144 B rows; bank
// offset 4r mod 32 -> conflict-free ldmatrix).
// ---------------------------------------------------------------------------
#define LDA_H   72
#define A_STG_H (128 * LDA_H)   /* 9216 halves = 18432 B */
#define GSTG3   3
#define GEMM_SMEM_BYTES (GSTG3 * 2 * A_STG_H * 2)   /* 110592 B */

template<bool OUT_HALF>
__global__ __launch_bounds__(256, 2)
void gemm_h_kernel(const __half* __restrict__ A,
                   const __half* __restrict__ BT,
                   const float* __restrict__ bias,
                   void* __restrict__ Cv,
                   int M, int N, int K)
{
    extern __shared__ __half hsm[];
    __half* Asm = hsm;                       // [3][A_STG_H]
    __half* Bsm = hsm + GSTG3 * A_STG_H;     // [3][A_STG_H]

    const int tid  = threadIdx.x;
    const int w    = tid >> 5;
    const int lane = tid & 31;
    const int g    = lane >> 2;
    const int t    = lane & 3;
    const int wm   = w >> 1;
    const int wn   = w & 1;
    const int rowB = blockIdx.y * 128;
    const int colB = blockIdx.x * 128;

    const int frag_r = ((lane >> 3) & 1) * 8 + (lane & 7);
    const int frag_c = (lane >> 4) * 8;

    const uint32_t As_b = (uint32_t)__cvta_generic_to_shared(Asm);
    const uint32_t Bs_b = (uint32_t)__cvta_generic_to_shared(Bsm);

    const __half* Ag = A  + (size_t)rowB * K;
    const __half* Bg = BT + (size_t)colB * K;

    float acc[2][8][4];
    #pragma unroll
    for (int mt = 0; mt < 2; mt++)
        #pragma unroll
        for (int nt = 0; nt < 8; nt++)
            #pragma unroll
            for (int j = 0; j < 4; j++) acc[mt][nt][j] = 0.f;

    const int KT = K >> 6;   // K/64

    auto load_stage = [&](int slot, int k0) {
        __half* Ad = Asm + slot * A_STG_H;
        __half* Bd = Bsm + slot * A_STG_H;
        #pragma unroll
        for (int j = 0; j < 4; j++) {
            int idx = tid + j * 256;          // 0..1023
            int r = idx >> 3, c = idx & 7;    // 128 rows x 8 chunks (16B each)
            cp_async16(Ad + r * LDA_H + c * 8, Ag + (size_t)r * K + k0 + c * 8);
            cp_async16(Bd + r * LDA_H + c * 8, Bg + (size_t)r * K + k0 + c * 8);
        }
    };

    load_stage(0, 0);  cp_commit();
    load_stage(1, 64); cp_commit();

    int slot = 0;
    for (int it = 0; it < KT; it++) {
        asm volatile("cp.async.wait_group 1;\n" ::: "memory");
        __syncthreads();

        {
            int ps = slot + 2; if (ps >= 3) ps -= 3;
            if (it + 2 < KT) load_stage(ps, (it + 2) << 6);
            cp_commit();   // unconditional: keeps wait_group arithmetic exact
        }

        const uint32_t At = As_b + slot * A_STG_H * 2;
        const uint32_t Bt = Bs_b + slot * A_STG_H * 2;

        #pragma unroll
        for (int ks = 0; ks < 4; ks++) {
            const int col = ks * 16 + frag_c;
            uint32_t a[2][4];
            #pragma unroll
            for (int mt = 0; mt < 2; mt++) {
                int row = wm * 32 + mt * 16 + frag_r;
                ldmx4(a[mt], At + (row * LDA_H + col) * 2);
            }
            #pragma unroll
            for (int np = 0; np < 4; np++) {
                int row = wn * 64 + np * 16 + frag_r;
                uint32_t br[4];
                ldmx4(br, Bt + (row * LDA_H + col) * 2);
                mma_f16(acc[0][2 * np],     a[0], br[0], br[2], acc[0][2 * np]);
                mma_f16(acc[0][2 * np + 1], a[0], br[1], br[3], acc[0][2 * np + 1]);
                mma_f16(acc[1][2 * np],     a[1], br[0], br[2], acc[1][2 * np]);
                mma_f16(acc[1][2 * np + 1], a[1], br[1], br[3], acc[1][2 * np + 1]);
            }
        }
        if (++slot == 3) slot = 0;
    }

    #pragma unroll
    for (int mt = 0; mt < 2; mt++) {
        int m = rowB + wm * 32 + mt * 16 + g;
        #pragma unroll
        for (int nt = 0; nt < 8; nt++) {
            int n = colB + wn * 64 + nt * 8 + 2 * t;
            float2 bv = *(const float2*)(bias + n);
            if (OUT_HALF) {
                __half* C = (__half*)Cv;
                *(__half2*)(C + (size_t)m * N + n) =
                    __floats2half2_rn(acc[mt][nt][0] + bv.x, acc[mt][nt][1] + bv.y);
                *(__half2*)(C + (size_t)(m + 8) * N + n) =
                    __floats2half2_rn(acc[mt][nt][2] + bv.x, acc[mt][nt][3] + bv.y);
            } else {
                float* C = (float*)Cv;
                *(float2*)(C + (size_t)m * N + n) =
                    make_float2(acc[mt][nt][0] + bv.x, acc[mt][nt][1] + bv.y);
                *(float2*)(C + (size_t)(m + 8) * N + n) =
                    make_float2(acc[mt][nt][2] + bv.x, acc[mt][nt][3] + bv.y);
            }
        }
    }
}

// ---------------------------------------------------------------------------
// Pre-passes
// ---------------------------------------------------------------------------
__global__ void convert_half_kernel(const float* __restrict__ in,
                                    __half* __restrict__ out, int n)
{
    int i = blockIdx.x * blockDim.x + threadIdx.x;
    if (i < n) out[i] = __float2half_rn(in[i]);
}

__global__ void transpose_f2h_kernel(const float* __restrict__ in,
                                     __half* __restrict__ out,
                                     int K, int N)
{
    __shared__ float tsm[32][33];
    int xi = blockIdx.x * 32 + threadIdx.x;
    int yi = blockIdx.y * 32 + threadIdx.y;
    #pragma unroll
    for (int j = 0; j < 4; j++)
        tsm[threadIdx.y + j * 8][threadIdx.x] = in[(size_t)(yi + j * 8) * N + xi];
    __syncthreads();
    int xo = blockIdx.y * 32 + threadIdx.x;
    int yo = blockIdx.x * 32 + threadIdx.y;
    #pragma unroll
    for (int j = 0; j < 4; j++)
        out[(size_t)(yo + j * 8) * K + xo] =
            __float2half_rn(tsm[threadIdx.x][threadIdx.y + j * 8]);
}

// ---------------------------------------------------------------------------
// RoPE in half; Q rows pre-scaled by rsqrt(HDIM)*log2(e).
// ---------------------------------------------------------------------------
__global__ void rope_h_kernel(__half* __restrict__ qkv,
                              const float* __restrict__ cosp,
                              const float* __restrict__ sinp)
{
    int idx = blockIdx.x * blockDim.x + threadIdx.x;
    const int total = BATCH * SEQ * 2 * HEADS * (HALF / 2);
    if (idx >= total) return;

    int d2 = idx % (HALF / 2);  idx /= (HALF / 2);
    int h  = idx % HEADS;       idx /= HEADS;
    int qk = idx % 2;           idx /= 2;
    int n  = idx % SEQ;
    int b  = idx / SEQ;
    int d  = 2 * d2;

    const float SCLF = rsqrtf((float)HDIM) * 1.44269504f;
    const float s = (qk == 0) ? SCLF : 1.f;

    __half* row = qkv + (size_t)(b * SEQ + n) * QKV_COLS + qk * HIDDEN + h * HDIM;
    float2 lo = __half22float2(*(__half2*)(row + d));
    float2 hi = __half22float2(*(__half2*)(row + d + HALF));
    const float* cb = cosp + n * HDIM;
    const float* sb = sinp + n * HDIM;
    float cl0 = cb[d], cl1 = cb[d + 1], ch0 = cb[d + HALF], ch1 = cb[d + HALF + 1];
    float sl0 = sb[d], sl1 = sb[d + 1], sh0 = sb[d + HALF], sh1 = sb[d + HALF + 1];
    *(__half2*)(row + d) =
        __floats2half2_rn(s * (lo.x * cl0 - hi.x * sl0), s * (lo.y * cl1 - hi.y * sl1));
    *(__half2*)(row + d + HALF) =
        __floats2half2_rn(s * (hi.x * ch0 + lo.x * sh0), s * (hi.y * ch1 + lo.y * sh1));
}

// ---------------------------------------------------------------------------
// fp16 flash attention with ldmatrix fragments (unchanged from R8).
// ---------------------------------------------------------------------------
#define BQ      128
#define BKT     64
#define NITER   (SEQ / BKT)
#define LDK_H   88
#define LDP_H   72
#define P_H     (8 * 16 * LDP_H)    /* 9216 */
#define KBUF_H  (BKT * LDK_H)       /* 5632 */
#define ATTN_SMEM_BYTES ((P_H + 3 * KBUF_H) * 2)   /* 52224 */

__global__ __launch_bounds__(256, 2)
void flash_attn_h_kernel(const __half* __restrict__ qkv,
                         __half* __restrict__ out)
{
    extern __shared__ __half hsm[];
    __half* Pbase = hsm;
    __half* Ks    = hsm + P_H;
    __half* Vs    = Ks + 2 * KBUF_H;
    __half* Qs    = Ks;   // alias

    const int tid  = threadIdx.x;
    const int w    = tid >> 5;
    const int lane = tid & 31;
    const int g    = lane >> 2;
    const int t    = lane & 3;
    const int frag_r = ((lane >> 3) & 1) * 8 + (lane & 7);
    const int frag_c = (lane >> 4) * 8;

    const uint32_t P_b = (uint32_t)__cvta_generic_to_shared(Pbase);
    const uint32_t K_b = (uint32_t)__cvta_generic_to_shared(Ks);
    const uint32_t V_b = (uint32_t)__cvta_generic_to_shared(Vs);
    const uint32_t Q_b = K_b;

    const int q0 = blockIdx.x * BQ;
    const int h  = blockIdx.y & (HEADS - 1);
    const int b  = blockIdx.y >> 4;

    const __half* base = qkv + (size_t)(b * SEQ) * QKV_COLS;
    const __half* kb0  = base + HIDDEN + h * HDIM;
    const __half* vb0  = base + 2 * HIDDEN + h * HDIM;

    {
        const __half* qb = base + h * HDIM;
        #pragma unroll
        for (int j = 0; j < 5; j++) {
            int idx = tid + j * 256;
            int r = idx / 10, c = idx - r * 10;
            cp_async16(Qs + r * LDK_H + c * 8,
                       qb + (size_t)(q0 + r) * QKV_COLS + c * 8);
        }
        cp_commit();
        asm volatile("cp.async.wait_group 0;\n" ::: "memory");
        __syncthreads();
    }

    uint32_t qf[5][4];
    {
        const int row = w * 16 + frag_r;
        #pragma unroll
        for (int ks = 0; ks < 5; ks++)
            ldmx4(qf[ks], Q_b + (row * LDK_H + ks * 16 + frag_c) * 2);
    }
    __syncthreads();

    __half* Pw = Pbase + w * 16 * LDP_H;
    const uint32_t Pw_b = P_b + w * 16 * LDP_H * 2;

    float of[10][4];
    #pragma unroll
    for (int i = 0; i < 10; i++)
        #pragma unroll
        for (int j = 0; j < 4; j++) of[i][j] = 0.f;
    float m1 = -INFINITY, m2 = -INFINITY, l1 = 0.f, l2 = 0.f;

    auto load_tile = [&](__half* dst, const __half* src) {
        #pragma unroll
        for (int j = 0; j < 3; j++) {
            int idx = tid + j * 256;
            if (idx < BKT * 10) {
                int r = idx / 10, c = idx - r * 10;
                cp_async16(dst + r * LDK_H + c * 8, src + (size_t)r * QKV_COLS + c * 8);
            }
        }
    };

    load_tile(Ks, kb0);
    cp_commit();

    for (int it = 0; it < NITER; it++) {
        load_tile(Vs, vb0 + (size_t)(it * BKT) * QKV_COLS);
        cp_commit();
        if (it + 1 < NITER)
            load_tile(Ks + ((it + 1) & 1) * KBUF_H,
                      kb0 + (size_t)((it + 1) * BKT) * QKV_COLS);
        cp_commit();

        asm volatile("cp.async.wait_group 1;\n" ::: "memory");
        __syncthreads();

        const uint32_t Kt = K_b + (it & 1) * KBUF_H * 2;

        float sacc[8][4];
        #pragma unroll
        for (int nt = 0; nt < 8; nt++)
            #pragma unroll
            for (int j = 0; j < 4; j++) sacc[nt][j] = 0.f;

        #pragma unroll
        for (int ks = 0; ks < 5; ks++) {
            const int col = ks * 16 + frag_c;
            #pragma unroll
            for (int np = 0; np < 4; np++) {
                uint32_t br[4];
                ldmx4(br, Kt + ((np * 16 + frag_r) * LDK_H + col) * 2);
                mma_f16(sacc[2 * np],     qf[ks], br[0], br[2], sacc[2 * np]);
                mma_f16(sacc[2 * np + 1], qf[ks], br[1], br[3], sacc[2 * np + 1]);
            }
        }

        float mx1 = -INFINITY, mx2 = -INFINITY;
        #pragma unroll
        for (int nt = 0; nt < 8; nt++) {
            mx1 = fmaxf(mx1, fmaxf(sacc[nt][0], sacc[nt][1]));
            mx2 = fmaxf(mx2, fmaxf(sacc[nt][2], sacc[nt][3]));
        }
        mx1 = fmaxf(mx1, __shfl_xor_sync(0xffffffff, mx1, 1));
        mx1 = fmaxf(mx1, __shfl_xor_sync(0xffffffff, mx1, 2));
        mx2 = fmaxf(mx2, __shfl_xor_sync(0xffffffff, mx2, 1));
        mx2 = fmaxf(mx2, __shfl_xor_sync(0xffffffff, mx2, 2));

        float mn1 = fmaxf(m1, mx1);
        float mn2 = fmaxf(m2, mx2);
        float a1 = exp2f(m1 - mn1);
        float a2 = exp2f(m2 - mn2);
        m1 = mn1; m2 = mn2;

        float s1 = 0.f, s2 = 0.f;
        #pragma unroll
        for (int nt = 0; nt < 8; nt++) {
            sacc[nt][0] = exp2f(sacc[nt][0] - mn1);
            sacc[nt][1] = exp2f(sacc[nt][1] - mn1);
            sacc[nt][2] = exp2f(sacc[nt][2] - mn2);
            sacc[nt][3] = exp2f(sacc[nt][3] - mn2);
            s1 += sacc[nt][0] + sacc[nt][1];
            s2 += sacc[nt][2] + sacc[nt][3];
        }
        s1 += __shfl_xor_sync(0xffffffff, s1, 1);
        s1 += __shfl_xor_sync(0xffffffff, s1, 2);
        s2 += __shfl_xor_sync(0xffffffff, s2, 1);
        s2 += __shfl_xor_sync(0xffffffff, s2, 2);
        l1 = l1 * a1 + s1;
        l2 = l2 * a2 + s2;

        #pragma unroll
        for (int nt = 0; nt < 10; nt++) {
            of[nt][0] *= a1; of[nt][1] *= a1;
            of[nt][2] *= a2; of[nt][3] *= a2;
        }

        __syncwarp();
        #pragma unroll
        for (int nt = 0; nt < 8; nt++) {
            *(__half2*)(Pw + g * LDP_H + nt * 8 + 2 * t) =
                __floats2half2_rn(sacc[nt][0], sacc[nt][1]);
            *(__half2*)(Pw + (g + 8) * LDP_H + nt * 8 + 2 * t) =
                __floats2half2_rn(sacc[nt][2], sacc[nt][3]);
        }
        __syncwarp();

        #pragma unroll
        for (int ks = 0; ks < 4; ks++) {
            uint32_t af[4];
            ldmx4(af, Pw_b + (frag_r * LDP_H + ks * 16 + frag_c) * 2);
            const int vrow = ks * 16 + frag_r;
            #pragma unroll
            for (int vp = 0; vp < 5; vp++) {
                uint32_t br[4];
                ldmx4_t(br, V_b + (vrow * LDK_H + vp * 16 + frag_c) * 2);
                mma_f16(of[2 * vp],     af, br[0], br[1], of[2 * vp]);
                mma_f16(of[2 * vp + 1], af, br[2], br[3], of[2 * vp + 1]);
            }
        }
        __syncthreads();
    }

    const float inv1 = 1.f / l1;
    const float inv2 = 1.f / l2;
    const int r1 = q0 + w * 16 + g;
    __half* ob = out + (size_t)(b * SEQ) * HIDDEN + h * HDIM;
    #pragma unroll
    for (int nt = 0; nt < 10; nt++) {
        int c = nt * 8 + 2 * t;
        *(__half2*)(ob + (size_t)r1 * HIDDEN + c) =
            __floats2half2_rn(of[nt][0] * inv1, of[nt][1] * inv1);
        *(__half2*)(ob + (size_t)(r1 + 8) * HIDDEN + c) =
            __floats2half2_rn(of[nt][2] * inv2, of[nt][3] * inv2);
    }
}

// ---------------------------------------------------------------------------
extern "C" void kernel_launch(void* const* d_in, const int* in_sizes, int n_in,
                              void* d_out, int out_size)
{
    const float* x      = (const float*)d_in[0];
    const float* cosp   = (const float*)d_in[1];
    const float* sinp   = (const float*)d_in[2];
    const float* qkv_w  = (const float*)d_in[3];
    const float* qkv_b  = (const float*)d_in[4];
    const float* proj_w = (const float*)d_in[5];
    const float* proj_b = (const float*)d_in[6];
    float* out = (float*)d_out;

    __half *x_h, *qkv_h, *attn_h, *wqkvT_h, *wprojT_h;
    cudaGetSymbolAddress((void**)&x_h,      g_x_h);
    cudaGetSymbolAddress((void**)&qkv_h,    g_qkv_h);
    cudaGetSymbolAddress((void**)&attn_h,   g_attn_h);
    cudaGetSymbolAddress((void**)&wqkvT_h,  g_wqkvT_h);
    cudaGetSymbolAddress((void**)&wprojT_h, g_wprojT_h);

    static int attr_set = 0;
    if (!attr_set) {
        cudaFuncSetAttribute(gemm_h_kernel<true>,
                             cudaFuncAttributeMaxDynamicSharedMemorySize, GEMM_SMEM_BYTES);
        cudaFuncSetAttribute(gemm_h_kernel<false>,
                             cudaFuncAttributeMaxDynamicSharedMemorySize, GEMM_SMEM_BYTES);
        cudaFuncSetAttribute(flash_attn_h_kernel,
                             cudaFuncAttributeMaxDynamicSharedMemorySize, ATTN_SMEM_BYTES);
        attr_set = 1;
    }

    // 0) pre-passes
    {
        int n = ROWS * HIDDEN;
        convert_half_kernel<<<(n + 255) / 256, 256>>>(x, x_h, n);
        dim3 blk(32, 8);
        transpose_f2h_kernel<<<dim3(QKV_COLS / 32, HIDDEN / 32), blk>>>(
            qkv_w, wqkvT_h, HIDDEN, QKV_COLS);
        transpose_f2h_kernel<<<dim3(HIDDEN / 32, HIDDEN / 32), blk>>>(
            proj_w, wprojT_h, HIDDEN, HIDDEN);
    }

    // 1) QKV GEMM (fp16 HMMA, BK=64, 3-stage)
    {
        dim3 grid(QKV_COLS / 128, ROWS / 128);
        gemm_h_kernel<true><<<grid, 256, GEMM_SMEM_BYTES>>>(
            x_h, wqkvT_h, qkv_b, qkv_h, ROWS, QKV_COLS, HIDDEN);
    }

    // 2) RoPE (half; Q pre-scaled)
    {
        int total = BATCH * SEQ * 2 * HEADS * (HALF / 2);
        rope_h_kernel<<<(total + 255) / 256, 256>>>(qkv_h, cosp, sinp);
    }

    // 3) fp16 flash attention
    {
        dim3 grid(SEQ / BQ, BATCH * HEADS);
        flash_attn_h_kernel<<<grid, 256, ATTN_SMEM_BYTES>>>(qkv_h, attn_h);
    }

    // 4) Proj GEMM (fp16 HMMA, BK=64, 3-stage) -> fp32 out
    {
        dim3 grid(HIDDEN / 128, ROWS / 128);
        gemm_h_kernel<false><<<grid, 256, GEMM_SMEM_BYTES>>>(
            attn_h, wprojT_h, proj_b, out, ROWS, HIDDEN, HIDDEN);
    }
}

// round 10
// speedup vs baseline: 64.7763x; 1.0354x over previous
#include <cuda_runtime.h>
#include <cuda_fp16.h>
#include <math.h>
#include <stdint.h>

#define HIDDEN   1280
#define HEADS    16
#define HDIM     80
#define HALF     40
#define BATCH    2
#define SEQ      2048
#define ROWS     (BATCH*SEQ)        /* 4096 */
#define QKV_COLS (3*HIDDEN)         /* 3840 */

// Scratch (device globals; no runtime allocation allowed)
__device__ __half g_x_h[(size_t)ROWS * HIDDEN];            // 10.5 MB
__device__ __half g_qkv_h[(size_t)ROWS * QKV_COLS];        // 31.5 MB
__device__ __half g_attn_h[(size_t)ROWS * HIDDEN];         // 10.5 MB
__device__ __half g_wqkvT_h[(size_t)QKV_COLS * HIDDEN];    //  9.8 MB
__device__ __half g_wprojT_h[(size_t)HIDDEN * HIDDEN];     //  3.3 MB

__device__ __forceinline__ void cp_async16(void* smem_dst, const void* gmem_src)
{
    uint32_t s = (uint32_t)__cvta_generic_to_shared(smem_dst);
    asm volatile("cp.async.cg.shared.global [%0], [%1], 16;\n"
                 :: "r"(s), "l"(gmem_src) : "memory");
}
__device__ __forceinline__ void cp_commit()
{
    asm volatile("cp.async.commit_group;\n" ::: "memory");
}

__device__ __forceinline__ void ldmx4(uint32_t* r, uint32_t addr)
{
    asm volatile("ldmatrix.sync.aligned.m8n8.x4.shared.b16 {%0,%1,%2,%3}, [%4];"
                 : "=r"(r[0]), "=r"(r[1]), "=r"(r[2]), "=r"(r[3]) : "r"(addr));
}
__device__ __forceinline__ void ldmx4_t(uint32_t* r, uint32_t addr)
{
    asm volatile("ldmatrix.sync.aligned.m8n8.x4.trans.shared.b16 {%0,%1,%2,%3}, [%4];"
                 : "=r"(r[0]), "=r"(r[1]), "=r"(r[2]), "=r"(r[3]) : "r"(addr));
}

// fp16 HMMA: D(16x8,f32) = A(16x16,f16) x B(16x8,f16) + C
__device__ __forceinline__ void mma_f16(float* d, const uint32_t* a,
                                        uint32_t b0, uint32_t b1,
                                        const float* c)
{
    asm volatile(
        "mma.sync.aligned.m16n8k16.row.col.f32.f16.f16.f32 "
        "{%0,%1,%2,%3}, {%4,%5,%6,%7}, {%8,%9}, {%10,%11,%12,%13};\n"
        : "=f"(d[0]), "=f"(d[1]), "=f"(d[2]), "=f"(d[3])
        : "r"(a[0]), "r"(a[1]), "r"(a[2]), "r"(a[3]),
          "r"(b0), "r"(b1),
          "f"(c[0]), "f"(c[1]), "f"(c[2]), "f"(c[3]));
}

// ---------------------------------------------------------------------------
// fp16 tensor-core GEMM + bias (unchanged from R9).
// ---------------------------------------------------------------------------
#define LDA_H   72
#define A_STG_H (128 * LDA_H)   /* 9216 halves */
#define GSTG3   3
#define GEMM_SMEM_BYTES (GSTG3 * 2 * A_STG_H * 2)   /* 110592 B */

template<bool OUT_HALF>
__global__ __launch_bounds__(256, 2)
void gemm_h_kernel(const __half* __restrict__ A,
                   const __half* __restrict__ BT,
                   const float* __restrict__ bias,
                   void* __restrict__ Cv,
                   int M, int N, int K)
{
    extern __shared__ __half hsm[];
    __half* Asm = hsm;
    __half* Bsm = hsm + GSTG3 * A_STG_H;

    const int tid  = threadIdx.x;
    const int w    = tid >> 5;
    const int lane = tid & 31;
    const int g    = lane >> 2;
    const int t    = lane & 3;
    const int wm   = w >> 1;
    const int wn   = w & 1;
    const int rowB = blockIdx.y * 128;
    const int colB = blockIdx.x * 128;

    const int frag_r = ((lane >> 3) & 1) * 8 + (lane & 7);
    const int frag_c = (lane >> 4) * 8;

    const uint32_t As_b = (uint32_t)__cvta_generic_to_shared(Asm);
    const uint32_t Bs_b = (uint32_t)__cvta_generic_to_shared(Bsm);

    const __half* Ag = A  + (size_t)rowB * K;
    const __half* Bg = BT + (size_t)colB * K;

    float acc[2][8][4];
    #pragma unroll
    for (int mt = 0; mt < 2; mt++)
        #pragma unroll
        for (int nt = 0; nt < 8; nt++)
            #pragma unroll
            for (int j = 0; j < 4; j++) acc[mt][nt][j] = 0.f;

    const int KT = K >> 6;

    auto load_stage = [&](int slot, int k0) {
        __half* Ad = Asm + slot * A_STG_H;
        __half* Bd = Bsm + slot * A_STG_H;
        #pragma unroll
        for (int j = 0; j < 4; j++) {
            int idx = tid + j * 256;
            int r = idx >> 3, c = idx & 7;
            cp_async16(Ad + r * LDA_H + c * 8, Ag + (size_t)r * K + k0 + c * 8);
            cp_async16(Bd + r * LDA_H + c * 8, Bg + (size_t)r * K + k0 + c * 8);
        }
    };

    load_stage(0, 0);  cp_commit();
    load_stage(1, 64); cp_commit();

    int slot = 0;
    for (int it = 0; it < KT; it++) {
        asm volatile("cp.async.wait_group 1;\n" ::: "memory");
        __syncthreads();

        {
            int ps = slot + 2; if (ps >= 3) ps -= 3;
            if (it + 2 < KT) load_stage(ps, (it + 2) << 6);
            cp_commit();
        }

        const uint32_t At = As_b + slot * A_STG_H * 2;
        const uint32_t Bt = Bs_b + slot * A_STG_H * 2;

        #pragma unroll
        for (int ks = 0; ks < 4; ks++) {
            const int col = ks * 16 + frag_c;
            uint32_t a[2][4];
            #pragma unroll
            for (int mt = 0; mt < 2; mt++) {
                int row = wm * 32 + mt * 16 + frag_r;
                ldmx4(a[mt], At + (row * LDA_H + col) * 2);
            }
            #pragma unroll
            for (int np = 0; np < 4; np++) {
                int row = wn * 64 + np * 16 + frag_r;
                uint32_t br[4];
                ldmx4(br, Bt + (row * LDA_H + col) * 2);
                mma_f16(acc[0][2 * np],     a[0], br[0], br[2], acc[0][2 * np]);
                mma_f16(acc[0][2 * np + 1], a[0], br[1], br[3], acc[0][2 * np + 1]);
                mma_f16(acc[1][2 * np],     a[1], br[0], br[2], acc[1][2 * np]);
                mma_f16(acc[1][2 * np + 1], a[1], br[1], br[3], acc[1][2 * np + 1]);
            }
        }
        if (++slot == 3) slot = 0;
    }

    #pragma unroll
    for (int mt = 0; mt < 2; mt++) {
        int m = rowB + wm * 32 + mt * 16 + g;
        #pragma unroll
        for (int nt = 0; nt < 8; nt++) {
            int n = colB + wn * 64 + nt * 8 + 2 * t;
            float2 bv = *(const float2*)(bias + n);
            if (OUT_HALF) {
                __half* C = (__half*)Cv;
                *(__half2*)(C + (size_t)m * N + n) =
                    __floats2half2_rn(acc[mt][nt][0] + bv.x, acc[mt][nt][1] + bv.y);
                *(__half2*)(C + (size_t)(m + 8) * N + n) =
                    __floats2half2_rn(acc[mt][nt][2] + bv.x, acc[mt][nt][3] + bv.y);
            } else {
                float* C = (float*)Cv;
                *(float2*)(C + (size_t)m * N + n) =
                    make_float2(acc[mt][nt][0] + bv.x, acc[mt][nt][1] + bv.y);
                *(float2*)(C + (size_t)(m + 8) * N + n) =
                    make_float2(acc[mt][nt][2] + bv.x, acc[mt][nt][3] + bv.y);
            }
        }
    }
}

// ---------------------------------------------------------------------------
// Unified pre-pass: one launch, three independent jobs selected by block id.
//   [0, CONV_B)                : convert x fp32 -> half (8 elems/thread)
//   [CONV_B, CONV_B+TQ_B)      : transpose+convert qkv_w [1280][3840] -> [3840][1280]
//   [CONV_B+TQ_B, total)       : transpose+convert proj_w [1280][1280] -> [1280][1280]
// ---------------------------------------------------------------------------
#define CONV_B  ((ROWS * HIDDEN) / (256 * 8))        /* 2560 */
#define TQ_BX   (QKV_COLS / 32)                      /* 120 */
#define TQ_B    (TQ_BX * (HIDDEN / 32))              /* 4800 */
#define TP_BX   (HIDDEN / 32)                        /* 40 */
#define TP_B    (TP_BX * (HIDDEN / 32))              /* 1600 */
#define PRE_B   (CONV_B + TQ_B + TP_B)               /* 8960 */

__device__ __forceinline__ void transpose_tile_f2h(
    const float* __restrict__ in, __half* __restrict__ out,
    int K, int N, int bx, int by, int tx, int ty)
{
    __shared__ float tsm[32][33];
    int xi = bx * 32 + tx;
    int yi = by * 32 + ty;
    #pragma unroll
    for (int j = 0; j < 4; j++)
        tsm[ty + j * 8][tx] = in[(size_t)(yi + j * 8) * N + xi];
    __syncthreads();
    int xo = by * 32 + tx;
    int yo = bx * 32 + ty;
    #pragma unroll
    for (int j = 0; j < 4; j++)
        out[(size_t)(yo + j * 8) * K + xo] =
            __float2half_rn(tsm[tx][ty + j * 8]);
}

__global__ void prepass_kernel(const float* __restrict__ x,
                               const float* __restrict__ qkv_w,
                               const float* __restrict__ proj_w,
                               __half* __restrict__ x_h,
                               __half* __restrict__ wqkvT,
                               __half* __restrict__ wprojT)
{
    const int bid = blockIdx.x;
    const int tid = threadIdx.x;

    if (bid < CONV_B) {
        // convert x: 8 fp32 -> 8 half per thread, 16B-aligned both sides
        size_t i0 = ((size_t)bid * 256 + tid) * 8;
        float4 v0 = *(const float4*)(x + i0);
        float4 v1 = *(const float4*)(x + i0 + 4);
        __half2 h[4];
        h[0] = __floats2half2_rn(v0.x, v0.y);
        h[1] = __floats2half2_rn(v0.z, v0.w);
        h[2] = __floats2half2_rn(v1.x, v1.y);
        h[3] = __floats2half2_rn(v1.z, v1.w);
        *(uint4*)(x_h + i0) = *(uint4*)h;
    } else if (bid < CONV_B + TQ_B) {
        int rb = bid - CONV_B;
        transpose_tile_f2h(qkv_w, wqkvT, HIDDEN, QKV_COLS,
                           rb % TQ_BX, rb / TQ_BX, tid & 31, tid >> 5);
    } else {
        int rb = bid - CONV_B - TQ_B;
        transpose_tile_f2h(proj_w, wprojT, HIDDEN, HIDDEN,
                           rb % TP_BX, rb / TP_BX, tid & 31, tid >> 5);
    }
}

// ---------------------------------------------------------------------------
// RoPE in half, vectorized: one thread per (b,n,qk,h, 4-pair chunk).
// Q rows pre-scaled by rsqrt(HDIM)*log2(e).
// ---------------------------------------------------------------------------
__global__ void rope_h_kernel(__half* __restrict__ qkv,
                              const float* __restrict__ cosp,
                              const float* __restrict__ sinp)
{
    int idx = blockIdx.x * blockDim.x + threadIdx.x;
    const int total = BATCH * SEQ * 2 * HEADS * (HALF / 4);
    if (idx >= total) return;

    int c4 = idx % (HALF / 4);  idx /= (HALF / 4);
    int h  = idx % HEADS;       idx /= HEADS;
    int qk = idx % 2;           idx /= 2;
    int n  = idx % SEQ;
    int b  = idx / SEQ;
    int d  = 4 * c4;

    const float SCLF = rsqrtf((float)HDIM) * 1.44269504f;
    const float s = (qk == 0) ? SCLF : 1.f;

    __half* row = qkv + (size_t)(b * SEQ + n) * QKV_COLS + qk * HIDDEN + h * HDIM;
    __half2 lo2[2], hi2[2];
    *(uint2*)lo2 = *(const uint2*)(row + d);
    *(uint2*)hi2 = *(const uint2*)(row + d + HALF);
    float4 cl = *(const float4*)(cosp + n * HDIM + d);
    float4 ch = *(const float4*)(cosp + n * HDIM + d + HALF);
    float4 sl = *(const float4*)(sinp + n * HDIM + d);
    float4 sh = *(const float4*)(sinp + n * HDIM + d + HALF);

    float lo[4] = { __low2float(lo2[0]), __high2float(lo2[0]),
                    __low2float(lo2[1]), __high2float(lo2[1]) };
    float hi[4] = { __low2float(hi2[0]), __high2float(hi2[0]),
                    __low2float(hi2[1]), __high2float(hi2[1]) };

    __half2 olo[2], ohi[2];
    olo[0] = __floats2half2_rn(s * (lo[0] * cl.x - hi[0] * sl.x),
                               s * (lo[1] * cl.y - hi[1] * sl.y));
    olo[1] = __floats2half2_rn(s * (lo[2] * cl.z - hi[2] * sl.z),
                               s * (lo[3] * cl.w - hi[3] * sl.w));
    ohi[0] = __floats2half2_rn(s * (hi[0] * ch.x + lo[0] * sh.x),
                               s * (hi[1] * ch.y + lo[1] * sh.y));
    ohi[1] = __floats2half2_rn(s * (hi[2] * ch.z + lo[2] * sh.z),
                               s * (hi[3] * ch.w + lo[3] * sh.w));
    *(uint2*)(row + d)        = *(uint2*)olo;
    *(uint2*)(row + d + HALF) = *(uint2*)ohi;
}

// ---------------------------------------------------------------------------
// fp16 flash attention with ldmatrix fragments (unchanged from R9).
// ---------------------------------------------------------------------------
#define BQ      128
#define BKT     64
#define NITER   (SEQ / BKT)
#define LDK_H   88
#define LDP_H   72
#define P_H     (8 * 16 * LDP_H)
#define KBUF_H  (BKT * LDK_H)
#define ATTN_SMEM_BYTES ((P_H + 3 * KBUF_H) * 2)

__global__ __launch_bounds__(256, 2)
void flash_attn_h_kernel(const __half* __restrict__ qkv,
                         __half* __restrict__ out)
{
    extern __shared__ __half hsm[];
    __half* Pbase = hsm;
    __half* Ks    = hsm + P_H;
    __half* Vs    = Ks + 2 * KBUF_H;
    __half* Qs    = Ks;

    const int tid  = threadIdx.x;
    const int w    = tid >> 5;
    const int lane = tid & 31;
    const int g    = lane >> 2;
    const int t    = lane & 3;
    const int frag_r = ((lane >> 3) & 1) * 8 + (lane & 7);
    const int frag_c = (lane >> 4) * 8;

    const uint32_t P_b = (uint32_t)__cvta_generic_to_shared(Pbase);
    const uint32_t K_b = (uint32_t)__cvta_generic_to_shared(Ks);
    const uint32_t V_b = (uint32_t)__cvta_generic_to_shared(Vs);
    const uint32_t Q_b = K_b;

    const int q0 = blockIdx.x * BQ;
    const int h  = blockIdx.y & (HEADS - 1);
    const int b  = blockIdx.y >> 4;

    const __half* base = qkv + (size_t)(b * SEQ) * QKV_COLS;
    const __half* kb0  = base + HIDDEN + h * HDIM;
    const __half* vb0  = base + 2 * HIDDEN + h * HDIM;

    {
        const __half* qb = base + h * HDIM;
        #pragma unroll
        for (int j = 0; j < 5; j++) {
            int idx = tid + j * 256;
            int r = idx / 10, c = idx - r * 10;
            cp_async16(Qs + r * LDK_H + c * 8,
                       qb + (size_t)(q0 + r) * QKV_COLS + c * 8);
        }
        cp_commit();
        asm volatile("cp.async.wait_group 0;\n" ::: "memory");
        __syncthreads();
    }

    uint32_t qf[5][4];
    {
        const int row = w * 16 + frag_r;
        #pragma unroll
        for (int ks = 0; ks < 5; ks++)
            ldmx4(qf[ks], Q_b + (row * LDK_H + ks * 16 + frag_c) * 2);
    }
    __syncthreads();

    __half* Pw = Pbase + w * 16 * LDP_H;
    const uint32_t Pw_b = P_b + w * 16 * LDP_H * 2;

    float of[10][4];
    #pragma unroll
    for (int i = 0; i < 10; i++)
        #pragma unroll
        for (int j = 0; j < 4; j++) of[i][j] = 0.f;
    float m1 = -INFINITY, m2 = -INFINITY, l1 = 0.f, l2 = 0.f;

    auto load_tile = [&](__half* dst, const __half* src) {
        #pragma unroll
        for (int j = 0; j < 3; j++) {
            int idx = tid + j * 256;
            if (idx < BKT * 10) {
                int r = idx / 10, c = idx - r * 10;
                cp_async16(dst + r * LDK_H + c * 8, src + (size_t)r * QKV_COLS + c * 8);
            }
        }
    };

    load_tile(Ks, kb0);
    cp_commit();

    for (int it = 0; it < NITER; it++) {
        load_tile(Vs, vb0 + (size_t)(it * BKT) * QKV_COLS);
        cp_commit();
        if (it + 1 < NITER)
            load_tile(Ks + ((it + 1) & 1) * KBUF_H,
                      kb0 + (size_t)((it + 1) * BKT) * QKV_COLS);
        cp_commit();

        asm volatile("cp.async.wait_group 1;\n" ::: "memory");
        __syncthreads();

        const uint32_t Kt = K_b + (it & 1) * KBUF_H * 2;

        float sacc[8][4];
        #pragma unroll
        for (int nt = 0; nt < 8; nt++)
            #pragma unroll
            for (int j = 0; j < 4; j++) sacc[nt][j] = 0.f;

        #pragma unroll
        for (int ks = 0; ks < 5; ks++) {
            const int col = ks * 16 + frag_c;
            #pragma unroll
            for (int np = 0; np < 4; np++) {
                uint32_t br[4];
                ldmx4(br, Kt + ((np * 16 + frag_r) * LDK_H + col) * 2);
                mma_f16(sacc[2 * np],     qf[ks], br[0], br[2], sacc[2 * np]);
                mma_f16(sacc[2 * np + 1], qf[ks], br[1], br[3], sacc[2 * np + 1]);
            }
        }

        float mx1 = -INFINITY, mx2 = -INFINITY;
        #pragma unroll
        for (int nt = 0; nt < 8; nt++) {
            mx1 = fmaxf(mx1, fmaxf(sacc[nt][0], sacc[nt][1]));
            mx2 = fmaxf(mx2, fmaxf(sacc[nt][2], sacc[nt][3]));
        }
        mx1 = fmaxf(mx1, __shfl_xor_sync(0xffffffff, mx1, 1));
        mx1 = fmaxf(mx1, __shfl_xor_sync(0xffffffff, mx1, 2));
        mx2 = fmaxf(mx2, __shfl_xor_sync(0xffffffff, mx2, 1));
        mx2 = fmaxf(mx2, __shfl_xor_sync(0xffffffff, mx2, 2));

        float mn1 = fmaxf(m1, mx1);
        float mn2 = fmaxf(m2, mx2);
        float a1 = exp2f(m1 - mn1);
        float a2 = exp2f(m2 - mn2);
        m1 = mn1; m2 = mn2;

        float s1 = 0.f, s2 = 0.f;
        #pragma unroll
        for (int nt = 0; nt < 8; nt++) {
            sacc[nt][0] = exp2f(sacc[nt][0] - mn1);
            sacc[nt][1] = exp2f(sacc[nt][1] - mn1);
            sacc[nt][2] = exp2f(sacc[nt][2] - mn2);
            sacc[nt][3] = exp2f(sacc[nt][3] - mn2);
            s1 += sacc[nt][0] + sacc[nt][1];
            s2 += sacc[nt][2] + sacc[nt][3];
        }
        s1 += __shfl_xor_sync(0xffffffff, s1, 1);
        s1 += __shfl_xor_sync(0xffffffff, s1, 2);
        s2 += __shfl_xor_sync(0xffffffff, s2, 1);
        s2 += __shfl_xor_sync(0xffffffff, s2, 2);
        l1 = l1 * a1 + s1;
        l2 = l2 * a2 + s2;

        #pragma unroll
        for (int nt = 0; nt < 10; nt++) {
            of[nt][0] *= a1; of[nt][1] *= a1;
            of[nt][2] *= a2; of[nt][3] *= a2;
        }

        __syncwarp();
        #pragma unroll
        for (int nt = 0; nt < 8; nt++) {
            *(__half2*)(Pw + g * LDP_H + nt * 8 + 2 * t) =
                __floats2half2_rn(sacc[nt][0], sacc[nt][1]);
            *(__half2*)(Pw + (g + 8) * LDP_H + nt * 8 + 2 * t) =
                __floats2half2_rn(sacc[nt][2], sacc[nt][3]);
        }
        __syncwarp();

        #pragma unroll
        for (int ks = 0; ks < 4; ks++) {
            uint32_t af[4];
            ldmx4(af, Pw_b + (frag_r * LDP_H + ks * 16 + frag_c) * 2);
            const int vrow = ks * 16 + frag_r;
            #pragma unroll
            for (int vp = 0; vp < 5; vp++) {
                uint32_t br[4];
                ldmx4_t(br, V_b + (vrow * LDK_H + vp * 16 + frag_c) * 2);
                mma_f16(of[2 * vp],     af, br[0], br[1], of[2 * vp]);
                mma_f16(of[2 * vp + 1], af, br[2], br[3], of[2 * vp + 1]);
            }
        }
        __syncthreads();
    }

    const float inv1 = 1.f / l1;
    const float inv2 = 1.f / l2;
    const int r1 = q0 + w * 16 + g;
    __half* ob = out + (size_t)(b * SEQ) * HIDDEN + h * HDIM;
    #pragma unroll
    for (int nt = 0; nt < 10; nt++) {
        int c = nt * 8 + 2 * t;
        *(__half2*)(ob + (size_t)r1 * HIDDEN + c) =
            __floats2half2_rn(of[nt][0] * inv1, of[nt][1] * inv1);
        *(__half2*)(ob + (size_t)(r1 + 8) * HIDDEN + c) =
            __floats2half2_rn(of[nt][2] * inv2, of[nt][3] * inv2);
    }
}

// ---------------------------------------------------------------------------
extern "C" void kernel_launch(void* const* d_in, const int* in_sizes, int n_in,
                              void* d_out, int out_size)
{
    const float* x      = (const float*)d_in[0];
    const float* cosp   = (const float*)d_in[1];
    const float* sinp   = (const float*)d_in[2];
    const float* qkv_w  = (const float*)d_in[3];
    const float* qkv_b  = (const float*)d_in[4];
    const float* proj_w = (const float*)d_in[5];
    const float* proj_b = (const float*)d_in[6];
    float* out = (float*)d_out;

    __half *x_h, *qkv_h, *attn_h, *wqkvT_h, *wprojT_h;
    cudaGetSymbolAddress((void**)&x_h,      g_x_h);
    cudaGetSymbolAddress((void**)&qkv_h,    g_qkv_h);
    cudaGetSymbolAddress((void**)&attn_h,   g_attn_h);
    cudaGetSymbolAddress((void**)&wqkvT_h,  g_wqkvT_h);
    cudaGetSymbolAddress((void**)&wprojT_h, g_wprojT_h);

    static int attr_set = 0;
    if (!attr_set) {
        cudaFuncSetAttribute(gemm_h_kernel<true>,
                             cudaFuncAttributeMaxDynamicSharedMemorySize, GEMM_SMEM_BYTES);
        cudaFuncSetAttribute(gemm_h_kernel<false>,
                             cudaFuncAttributeMaxDynamicSharedMemorySize, GEMM_SMEM_BYTES);
        cudaFuncSetAttribute(flash_attn_h_kernel,
                             cudaFuncAttributeMaxDynamicSharedMemorySize, ATTN_SMEM_BYTES);
        attr_set = 1;
    }

    // 0) single fused pre-pass (convert x || transpose qkv_w || transpose proj_w)
    prepass_kernel<<<PRE_B, 256>>>(x, qkv_w, proj_w, x_h, wqkvT_h, wprojT_h);

    // 1) QKV GEMM (fp16 HMMA, BK=64, 3-stage)
    {
        dim3 grid(QKV_COLS / 128, ROWS / 128);
        gemm_h_kernel<true><<<grid, 256, GEMM_SMEM_BYTES>>>(
            x_h, wqkvT_h, qkv_b, qkv_h, ROWS, QKV_COLS, HIDDEN);
    }

    // 2) RoPE (half; vectorized; Q pre-scaled)
    {
        int total = BATCH * SEQ * 2 * HEADS * (HALF / 4);
        rope_h_kernel<<<(total + 255) / 256, 256>>>(qkv_h, cosp, sinp);
    }

    // 3) fp16 flash attention
    {
        dim3 grid(SEQ / BQ, BATCH * HEADS);
        flash_attn_h_kernel<<<grid, 256, ATTN_SMEM_BYTES>>>(qkv_h, attn_h);
    }

    // 4) Proj GEMM (fp16 HMMA, BK=64, 3-stage) -> fp32 out
    {
        dim3 grid(HIDDEN / 128, ROWS / 128);
        gemm_h_kernel<false><<<grid, 256, GEMM_SMEM_BYTES>>>(
            attn_h, wprojT_h, proj_b, out, ROWS, HIDDEN, HIDDEN);
    }
}

// round 11
// speedup vs baseline: 66.9746x; 1.0339x over previous
#include <cuda_runtime.h>
#include <cuda_fp16.h>
#include <math.h>
#include <stdint.h>

#define HIDDEN   1280
#define HEADS    16
#define HDIM     80
#define HALF     40
#define BATCH    2
#define SEQ      2048
#define ROWS     (BATCH*SEQ)        /* 4096 */
#define QKV_COLS (3*HIDDEN)         /* 3840 */

// Scratch (device globals; no runtime allocation allowed)
__device__ __half g_x_h[(size_t)ROWS * HIDDEN];            // 10.5 MB
__device__ __half g_qkv_h[(size_t)ROWS * QKV_COLS];        // 31.5 MB
__device__ __half g_attn_h[(size_t)ROWS * HIDDEN];         // 10.5 MB
__device__ __half g_wqkvT_h[(size_t)QKV_COLS * HIDDEN];    //  9.8 MB
__device__ __half g_wprojT_h[(size_t)HIDDEN * HIDDEN];     //  3.3 MB

__device__ __forceinline__ void cp_async16(void* smem_dst, const void* gmem_src)
{
    uint32_t s = (uint32_t)__cvta_generic_to_shared(smem_dst);
    asm volatile("cp.async.cg.shared.global [%0], [%1], 16;\n"
                 :: "r"(s), "l"(gmem_src) : "memory");
}
__device__ __forceinline__ void cp_commit()
{
    asm volatile("cp.async.commit_group;\n" ::: "memory");
}

__device__ __forceinline__ void ldmx4(uint32_t* r, uint32_t addr)
{
    asm volatile("ldmatrix.sync.aligned.m8n8.x4.shared.b16 {%0,%1,%2,%3}, [%4];"
                 : "=r"(r[0]), "=r"(r[1]), "=r"(r[2]), "=r"(r[3]) : "r"(addr));
}
__device__ __forceinline__ void ldmx4_t(uint32_t* r, uint32_t addr)
{
    asm volatile("ldmatrix.sync.aligned.m8n8.x4.trans.shared.b16 {%0,%1,%2,%3}, [%4];"
                 : "=r"(r[0]), "=r"(r[1]), "=r"(r[2]), "=r"(r[3]) : "r"(addr));
}

// fp16 HMMA: D(16x8,f32) = A(16x16,f16) x B(16x8,f16) + C
__device__ __forceinline__ void mma_f16(float* d, const uint32_t* a,
                                        uint32_t b0, uint32_t b1,
                                        const float* c)
{
    asm volatile(
        "mma.sync.aligned.m16n8k16.row.col.f32.f16.f16.f32 "
        "{%0,%1,%2,%3}, {%4,%5,%6,%7}, {%8,%9}, {%10,%11,%12,%13};\n"
        : "=f"(d[0]), "=f"(d[1]), "=f"(d[2]), "=f"(d[3])
        : "r"(a[0]), "r"(a[1]), "r"(a[2]), "r"(a[3]),
          "r"(b0), "r"(b1),
          "f"(c[0]), "f"(c[1]), "f"(c[2]), "f"(c[3]));
}

// ---------------------------------------------------------------------------
// fp16 tensor-core GEMM + bias (unchanged from R9/R10).
// ---------------------------------------------------------------------------
#define LDA_H   72
#define A_STG_H (128 * LDA_H)   /* 9216 halves */
#define GSTG3   3
#define GEMM_SMEM_BYTES (GSTG3 * 2 * A_STG_H * 2)   /* 110592 B */

template<bool OUT_HALF>
__global__ __launch_bounds__(256, 2)
void gemm_h_kernel(const __half* __restrict__ A,
                   const __half* __restrict__ BT,
                   const float* __restrict__ bias,
                   void* __restrict__ Cv,
                   int M, int N, int K)
{
    extern __shared__ __half hsm[];
    __half* Asm = hsm;
    __half* Bsm = hsm + GSTG3 * A_STG_H;

    const int tid  = threadIdx.x;
    const int w    = tid >> 5;
    const int lane = tid & 31;
    const int g    = lane >> 2;
    const int t    = lane & 3;
    const int wm   = w >> 1;
    const int wn   = w & 1;
    const int rowB = blockIdx.y * 128;
    const int colB = blockIdx.x * 128;

    const int frag_r = ((lane >> 3) & 1) * 8 + (lane & 7);
    const int frag_c = (lane >> 4) * 8;

    const uint32_t As_b = (uint32_t)__cvta_generic_to_shared(Asm);
    const uint32_t Bs_b = (uint32_t)__cvta_generic_to_shared(Bsm);

    const __half* Ag = A  + (size_t)rowB * K;
    const __half* Bg = BT + (size_t)colB * K;

    float acc[2][8][4];
    #pragma unroll
    for (int mt = 0; mt < 2; mt++)
        #pragma unroll
        for (int nt = 0; nt < 8; nt++)
            #pragma unroll
            for (int j = 0; j < 4; j++) acc[mt][nt][j] = 0.f;

    const int KT = K >> 6;

    auto load_stage = [&](int slot, int k0) {
        __half* Ad = Asm + slot * A_STG_H;
        __half* Bd = Bsm + slot * A_STG_H;
        #pragma unroll
        for (int j = 0; j < 4; j++) {
            int idx = tid + j * 256;
            int r = idx >> 3, c = idx & 7;
            cp_async16(Ad + r * LDA_H + c * 8, Ag + (size_t)r * K + k0 + c * 8);
            cp_async16(Bd + r * LDA_H + c * 8, Bg + (size_t)r * K + k0 + c * 8);
        }
    };

    load_stage(0, 0);  cp_commit();
    load_stage(1, 64); cp_commit();

    int slot = 0;
    for (int it = 0; it < KT; it++) {
        asm volatile("cp.async.wait_group 1;\n" ::: "memory");
        __syncthreads();

        {
            int ps = slot + 2; if (ps >= 3) ps -= 3;
            if (it + 2 < KT) load_stage(ps, (it + 2) << 6);
            cp_commit();
        }

        const uint32_t At = As_b + slot * A_STG_H * 2;
        const uint32_t Bt = Bs_b + slot * A_STG_H * 2;

        #pragma unroll
        for (int ks = 0; ks < 4; ks++) {
            const int col = ks * 16 + frag_c;
            uint32_t a[2][4];
            #pragma unroll
            for (int mt = 0; mt < 2; mt++) {
                int row = wm * 32 + mt * 16 + frag_r;
                ldmx4(a[mt], At + (row * LDA_H + col) * 2);
            }
            #pragma unroll
            for (int np = 0; np < 4; np++) {
                int row = wn * 64 + np * 16 + frag_r;
                uint32_t br[4];
                ldmx4(br, Bt + (row * LDA_H + col) * 2);
                mma_f16(acc[0][2 * np],     a[0], br[0], br[2], acc[0][2 * np]);
                mma_f16(acc[0][2 * np + 1], a[0], br[1], br[3], acc[0][2 * np + 1]);
                mma_f16(acc[1][2 * np],     a[1], br[0], br[2], acc[1][2 * np]);
                mma_f16(acc[1][2 * np + 1], a[1], br[1], br[3], acc[1][2 * np + 1]);
            }
        }
        if (++slot == 3) slot = 0;
    }

    #pragma unroll
    for (int mt = 0; mt < 2; mt++) {
        int m = rowB + wm * 32 + mt * 16 + g;
        #pragma unroll
        for (int nt = 0; nt < 8; nt++) {
            int n = colB + wn * 64 + nt * 8 + 2 * t;
            float2 bv = *(const float2*)(bias + n);
            if (OUT_HALF) {
                __half* C = (__half*)Cv;
                *(__half2*)(C + (size_t)m * N + n) =
                    __floats2half2_rn(acc[mt][nt][0] + bv.x, acc[mt][nt][1] + bv.y);
                *(__half2*)(C + (size_t)(m + 8) * N + n) =
                    __floats2half2_rn(acc[mt][nt][2] + bv.x, acc[mt][nt][3] + bv.y);
            } else {
                float* C = (float*)Cv;
                *(float2*)(C + (size_t)m * N + n) =
                    make_float2(acc[mt][nt][0] + bv.x, acc[mt][nt][1] + bv.y);
                *(float2*)(C + (size_t)(m + 8) * N + n) =
                    make_float2(acc[mt][nt][2] + bv.x, acc[mt][nt][3] + bv.y);
            }
        }
    }
}

// ---------------------------------------------------------------------------
// Unified pre-pass (unchanged from R10).
// ---------------------------------------------------------------------------
#define CONV_B  ((ROWS * HIDDEN) / (256 * 8))        /* 2560 */
#define TQ_BX   (QKV_COLS / 32)                      /* 120 */
#define TQ_B    (TQ_BX * (HIDDEN / 32))              /* 4800 */
#define TP_BX   (HIDDEN / 32)                        /* 40 */
#define TP_B    (TP_BX * (HIDDEN / 32))              /* 1600 */
#define PRE_B   (CONV_B + TQ_B + TP_B)               /* 8960 */

__device__ __forceinline__ void transpose_tile_f2h(
    const float* __restrict__ in, __half* __restrict__ out,
    int K, int N, int bx, int by, int tx, int ty)
{
    __shared__ float tsm[32][33];
    int xi = bx * 32 + tx;
    int yi = by * 32 + ty;
    #pragma unroll
    for (int j = 0; j < 4; j++)
        tsm[ty + j * 8][tx] = in[(size_t)(yi + j * 8) * N + xi];
    __syncthreads();
    int xo = by * 32 + tx;
    int yo = bx * 32 + ty;
    #pragma unroll
    for (int j = 0; j < 4; j++)
        out[(size_t)(yo + j * 8) * K + xo] =
            __float2half_rn(tsm[tx][ty + j * 8]);
}

__global__ void prepass_kernel(const float* __restrict__ x,
                               const float* __restrict__ qkv_w,
                               const float* __restrict__ proj_w,
                               __half* __restrict__ x_h,
                               __half* __restrict__ wqkvT,
                               __half* __restrict__ wprojT)
{
    const int bid = blockIdx.x;
    const int tid = threadIdx.x;

    if (bid < CONV_B) {
        size_t i0 = ((size_t)bid * 256 + tid) * 8;
        float4 v0 = *(const float4*)(x + i0);
        float4 v1 = *(const float4*)(x + i0 + 4);
        __half2 h[4];
        h[0] = __floats2half2_rn(v0.x, v0.y);
        h[1] = __floats2half2_rn(v0.z, v0.w);
        h[2] = __floats2half2_rn(v1.x, v1.y);
        h[3] = __floats2half2_rn(v1.z, v1.w);
        *(uint4*)(x_h + i0) = *(uint4*)h;
    } else if (bid < CONV_B + TQ_B) {
        int rb = bid - CONV_B;
        transpose_tile_f2h(qkv_w, wqkvT, HIDDEN, QKV_COLS,
                           rb % TQ_BX, rb / TQ_BX, tid & 31, tid >> 5);
    } else {
        int rb = bid - CONV_B - TQ_B;
        transpose_tile_f2h(proj_w, wprojT, HIDDEN, HIDDEN,
                           rb % TP_BX, rb / TP_BX, tid & 31, tid >> 5);
    }
}

// ---------------------------------------------------------------------------
// RoPE in half, vectorized (unchanged from R10).
// ---------------------------------------------------------------------------
__global__ void rope_h_kernel(__half* __restrict__ qkv,
                              const float* __restrict__ cosp,
                              const float* __restrict__ sinp)
{
    int idx = blockIdx.x * blockDim.x + threadIdx.x;
    const int total = BATCH * SEQ * 2 * HEADS * (HALF / 4);
    if (idx >= total) return;

    int c4 = idx % (HALF / 4);  idx /= (HALF / 4);
    int h  = idx % HEADS;       idx /= HEADS;
    int qk = idx % 2;           idx /= 2;
    int n  = idx % SEQ;
    int b  = idx / SEQ;
    int d  = 4 * c4;

    const float SCLF = rsqrtf((float)HDIM) * 1.44269504f;
    const float s = (qk == 0) ? SCLF : 1.f;

    __half* row = qkv + (size_t)(b * SEQ + n) * QKV_COLS + qk * HIDDEN + h * HDIM;
    __half2 lo2[2], hi2[2];
    *(uint2*)lo2 = *(const uint2*)(row + d);
    *(uint2*)hi2 = *(const uint2*)(row + d + HALF);
    float4 cl = *(const float4*)(cosp + n * HDIM + d);
    float4 ch = *(const float4*)(cosp + n * HDIM + d + HALF);
    float4 sl = *(const float4*)(sinp + n * HDIM + d);
    float4 sh = *(const float4*)(sinp + n * HDIM + d + HALF);

    float lo[4] = { __low2float(lo2[0]), __high2float(lo2[0]),
                    __low2float(lo2[1]), __high2float(lo2[1]) };
    float hi[4] = { __low2float(hi2[0]), __high2float(hi2[0]),
                    __low2float(hi2[1]), __high2float(hi2[1]) };

    __half2 olo[2], ohi[2];
    olo[0] = __floats2half2_rn(s * (lo[0] * cl.x - hi[0] * sl.x),
                               s * (lo[1] * cl.y - hi[1] * sl.y));
    olo[1] = __floats2half2_rn(s * (lo[2] * cl.z - hi[2] * sl.z),
                               s * (lo[3] * cl.w - hi[3] * sl.w));
    ohi[0] = __floats2half2_rn(s * (hi[0] * ch.x + lo[0] * sh.x),
                               s * (hi[1] * ch.y + lo[1] * sh.y));
    ohi[1] = __floats2half2_rn(s * (hi[2] * ch.z + lo[2] * sh.z),
                               s * (hi[3] * ch.w + lo[3] * sh.w));
    *(uint2*)(row + d)        = *(uint2*)olo;
    *(uint2*)(row + d + HALF) = *(uint2*)ohi;
}

// ---------------------------------------------------------------------------
// fp16 flash attention: 4-warp blocks, BQ=64, occ=4.
// Per-warp schedule identical to R10 (16 query rows, same ldmatrix/mma mix);
// only the block decomposition changed: 42 KB smem -> 4 blocks/SM, each
// __syncthreads couples 4 warps, and 4 blocks' phases interleave per SM.
// ---------------------------------------------------------------------------
#define BQ      64
#define NWRP    4
#define NTHR    (NWRP * 32)          /* 128 */
#define BKT     64
#define NITER   (SEQ / BKT)
#define LDK_H   88
#define LDP_H   72
#define P_H     (NWRP * 16 * LDP_H)  /* 4608 */
#define KBUF_H  (BKT * LDK_H)        /* 5632 */
#define ATTN_SMEM_BYTES ((P_H + 3 * KBUF_H) * 2)   /* 43008 B */

__global__ __launch_bounds__(NTHR, 4)
void flash_attn_h_kernel(const __half* __restrict__ qkv,
                         __half* __restrict__ out)
{
    extern __shared__ __half hsm[];
    __half* Pbase = hsm;
    __half* Ks    = hsm + P_H;          // 2 x [BKT][LDK_H]
    __half* Vs    = Ks + 2 * KBUF_H;    // 1 x [BKT][LDK_H]
    __half* Qs    = Ks;                 // alias (64*88 = KBUF_H <= 2*KBUF_H)

    const int tid  = threadIdx.x;
    const int w    = tid >> 5;
    const int lane = tid & 31;
    const int g    = lane >> 2;
    const int t    = lane & 3;
    const int frag_r = ((lane >> 3) & 1) * 8 + (lane & 7);
    const int frag_c = (lane >> 4) * 8;

    const uint32_t P_b = (uint32_t)__cvta_generic_to_shared(Pbase);
    const uint32_t K_b = (uint32_t)__cvta_generic_to_shared(Ks);
    const uint32_t V_b = (uint32_t)__cvta_generic_to_shared(Vs);
    const uint32_t Q_b = K_b;

    const int q0 = blockIdx.x * BQ;
    const int h  = blockIdx.y & (HEADS - 1);
    const int b  = blockIdx.y >> 4;

    const __half* base = qkv + (size_t)(b * SEQ) * QKV_COLS;
    const __half* kb0  = base + HIDDEN + h * HDIM;
    const __half* vb0  = base + 2 * HIDDEN + h * HDIM;

    // ---- stage Q tile (64 rows), hoist fragments ----
    {
        const __half* qb = base + h * HDIM;
        #pragma unroll
        for (int j = 0; j < 5; j++) {
            int idx = tid + j * NTHR;         // 0..639
            int r = idx / 10, c = idx - r * 10;
            cp_async16(Qs + r * LDK_H + c * 8,
                       qb + (size_t)(q0 + r) * QKV_COLS + c * 8);
        }
        cp_commit();
        asm volatile("cp.async.wait_group 0;\n" ::: "memory");
        __syncthreads();
    }

    uint32_t qf[5][4];
    {
        const int row = w * 16 + frag_r;
        #pragma unroll
        for (int ks = 0; ks < 5; ks++)
            ldmx4(qf[ks], Q_b + (row * LDK_H + ks * 16 + frag_c) * 2);
    }
    __syncthreads();   // Qs dead -> K buffers free

    __half* Pw = Pbase + w * 16 * LDP_H;
    const uint32_t Pw_b = P_b + w * 16 * LDP_H * 2;

    float of[10][4];
    #pragma unroll
    for (int i = 0; i < 10; i++)
        #pragma unroll
        for (int j = 0; j < 4; j++) of[i][j] = 0.f;
    float m1 = -INFINITY, m2 = -INFINITY, l1 = 0.f, l2 = 0.f;

    auto load_tile = [&](__half* dst, const __half* src) {
        #pragma unroll
        for (int j = 0; j < 5; j++) {
            int idx = tid + j * NTHR;         // 0..639 exact
            int r = idx / 10, c = idx - r * 10;
            cp_async16(dst + r * LDK_H + c * 8, src + (size_t)r * QKV_COLS + c * 8);
        }
    };

    load_tile(Ks, kb0);
    cp_commit();

    for (int it = 0; it < NITER; it++) {
        load_tile(Vs, vb0 + (size_t)(it * BKT) * QKV_COLS);
        cp_commit();
        if (it + 1 < NITER)
            load_tile(Ks + ((it + 1) & 1) * KBUF_H,
                      kb0 + (size_t)((it + 1) * BKT) * QKV_COLS);
        cp_commit();

        asm volatile("cp.async.wait_group 1;\n" ::: "memory");
        __syncthreads();

        const uint32_t Kt = K_b + (it & 1) * KBUF_H * 2;

        // ---- S = Q x K^T ----
        float sacc[8][4];
        #pragma unroll
        for (int nt = 0; nt < 8; nt++)
            #pragma unroll
            for (int j = 0; j < 4; j++) sacc[nt][j] = 0.f;

        #pragma unroll
        for (int ks = 0; ks < 5; ks++) {
            const int col = ks * 16 + frag_c;
            #pragma unroll
            for (int np = 0; np < 4; np++) {
                uint32_t br[4];
                ldmx4(br, Kt + ((np * 16 + frag_r) * LDK_H + col) * 2);
                mma_f16(sacc[2 * np],     qf[ks], br[0], br[2], sacc[2 * np]);
                mma_f16(sacc[2 * np + 1], qf[ks], br[1], br[3], sacc[2 * np + 1]);
            }
        }

        // ---- online softmax (warp-private; scores in log2 units) ----
        float mx1 = -INFINITY, mx2 = -INFINITY;
        #pragma unroll
        for (int nt = 0; nt < 8; nt++) {
            mx1 = fmaxf(mx1, fmaxf(sacc[nt][0], sacc[nt][1]));
            mx2 = fmaxf(mx2, fmaxf(sacc[nt][2], sacc[nt][3]));
        }
        mx1 = fmaxf(mx1, __shfl_xor_sync(0xffffffff, mx1, 1));
        mx1 = fmaxf(mx1, __shfl_xor_sync(0xffffffff, mx1, 2));
        mx2 = fmaxf(mx2, __shfl_xor_sync(0xffffffff, mx2, 1));
        mx2 = fmaxf(mx2, __shfl_xor_sync(0xffffffff, mx2, 2));

        float mn1 = fmaxf(m1, mx1);
        float mn2 = fmaxf(m2, mx2);
        float a1 = exp2f(m1 - mn1);
        float a2 = exp2f(m2 - mn2);
        m1 = mn1; m2 = mn2;

        float s1 = 0.f, s2 = 0.f;
        #pragma unroll
        for (int nt = 0; nt < 8; nt++) {
            sacc[nt][0] = exp2f(sacc[nt][0] - mn1);
            sacc[nt][1] = exp2f(sacc[nt][1] - mn1);
            sacc[nt][2] = exp2f(sacc[nt][2] - mn2);
            sacc[nt][3] = exp2f(sacc[nt][3] - mn2);
            s1 += sacc[nt][0] + sacc[nt][1];
            s2 += sacc[nt][2] + sacc[nt][3];
        }
        s1 += __shfl_xor_sync(0xffffffff, s1, 1);
        s1 += __shfl_xor_sync(0xffffffff, s1, 2);
        s2 += __shfl_xor_sync(0xffffffff, s2, 1);
        s2 += __shfl_xor_sync(0xffffffff, s2, 2);
        l1 = l1 * a1 + s1;
        l2 = l2 * a2 + s2;

        #pragma unroll
        for (int nt = 0; nt < 10; nt++) {
            of[nt][0] *= a1; of[nt][1] *= a1;
            of[nt][2] *= a2; of[nt][3] *= a2;
        }

        // ---- P -> warp-private strip ----
        __syncwarp();
        #pragma unroll
        for (int nt = 0; nt < 8; nt++) {
            *(__half2*)(Pw + g * LDP_H + nt * 8 + 2 * t) =
                __floats2half2_rn(sacc[nt][0], sacc[nt][1]);
            *(__half2*)(Pw + (g + 8) * LDP_H + nt * 8 + 2 * t) =
                __floats2half2_rn(sacc[nt][2], sacc[nt][3]);
        }
        __syncwarp();

        // ---- O += P x V (V fragments via ldmatrix.trans) ----
        #pragma unroll
        for (int ks = 0; ks < 4; ks++) {
            uint32_t af[4];
            ldmx4(af, Pw_b + (frag_r * LDP_H + ks * 16 + frag_c) * 2);
            const int vrow = ks * 16 + frag_r;
            #pragma unroll
            for (int vp = 0; vp < 5; vp++) {
                uint32_t br[4];
                ldmx4_t(br, V_b + (vrow * LDK_H + vp * 16 + frag_c) * 2);
                mma_f16(of[2 * vp],     af, br[0], br[1], of[2 * vp]);
                mma_f16(of[2 * vp + 1], af, br[2], br[3], of[2 * vp + 1]);
            }
        }
        __syncthreads();
    }

    // ---- epilogue ----
    const float inv1 = 1.f / l1;
    const float inv2 = 1.f / l2;
    const int r1 = q0 + w * 16 + g;
    __half* ob = out + (size_t)(b * SEQ) * HIDDEN + h * HDIM;
    #pragma unroll
    for (int nt = 0; nt < 10; nt++) {
        int c = nt * 8 + 2 * t;
        *(__half2*)(ob + (size_t)r1 * HIDDEN + c) =
            __floats2half2_rn(of[nt][0] * inv1, of[nt][1] * inv1);
        *(__half2*)(ob + (size_t)(r1 + 8) * HIDDEN + c) =
            __floats2half2_rn(of[nt][2] * inv2, of[nt][3] * inv2);
    }
}

// ---------------------------------------------------------------------------
extern "C" void kernel_launch(void* const* d_in, const int* in_sizes, int n_in,
                              void* d_out, int out_size)
{
    const float* x      = (const float*)d_in[0];
    const float* cosp   = (const float*)d_in[1];
    const float* sinp   = (const float*)d_in[2];
    const float* qkv_w  = (const float*)d_in[3];
    const float* qkv_b  = (const float*)d_in[4];
    const float* proj_w = (const float*)d_in[5];
    const float* proj_b = (const float*)d_in[6];
    float* out = (float*)d_out;

    __half *x_h, *qkv_h, *attn_h, *wqkvT_h, *wprojT_h;
    cudaGetSymbolAddress((void**)&x_h,      g_x_h);
    cudaGetSymbolAddress((void**)&qkv_h,    g_qkv_h);
    cudaGetSymbolAddress((void**)&attn_h,   g_attn_h);
    cudaGetSymbolAddress((void**)&wqkvT_h,  g_wqkvT_h);
    cudaGetSymbolAddress((void**)&wprojT_h, g_wprojT_h);

    static int attr_set = 0;
    if (!attr_set) {
        cudaFuncSetAttribute(gemm_h_kernel<true>,
                             cudaFuncAttributeMaxDynamicSharedMemorySize, GEMM_SMEM_BYTES);
        cudaFuncSetAttribute(gemm_h_kernel<false>,
                             cudaFuncAttributeMaxDynamicSharedMemorySize, GEMM_SMEM_BYTES);
        cudaFuncSetAttribute(flash_attn_h_kernel,
                             cudaFuncAttributeMaxDynamicSharedMemorySize, ATTN_SMEM_BYTES);
        attr_set = 1;
    }

    // 0) single fused pre-pass
    prepass_kernel<<<PRE_B, 256>>>(x, qkv_w, proj_w, x_h, wqkvT_h, wprojT_h);

    // 1) QKV GEMM
    {
        dim3 grid(QKV_COLS / 128, ROWS / 128);
        gemm_h_kernel<true><<<grid, 256, GEMM_SMEM_BYTES>>>(
            x_h, wqkvT_h, qkv_b, qkv_h, ROWS, QKV_COLS, HIDDEN);
    }

    // 2) RoPE
    {
        int total = BATCH * SEQ * 2 * HEADS * (HALF / 4);
        rope_h_kernel<<<(total + 255) / 256, 256>>>(qkv_h, cosp, sinp);
    }

    // 3) fp16 flash attention (4-warp blocks, occ 4)
    {
        dim3 grid(SEQ / BQ, BATCH * HEADS);   // (32, 32)
        flash_attn_h_kernel<<<grid, NTHR, ATTN_SMEM_BYTES>>>(qkv_h, attn_h);
    }

    // 4) Proj GEMM -> fp32 out
    {
        dim3 grid(HIDDEN / 128, ROWS / 128);
        gemm_h_kernel<false><<<grid, 256, GEMM_SMEM_BYTES>>>(
            attn_h, wprojT_h, proj_b, out, ROWS, HIDDEN, HIDDEN);
    }
}

// round 12
// speedup vs baseline: 68.5689x; 1.0238x over previous
#include <cuda_runtime.h>
#include <cuda_fp16.h>
#include <math.h>
#include <stdint.h>

#define HIDDEN   1280
#define HEADS    16
#define HDIM     80
#define HALF     40
#define BATCH    2
#define SEQ      2048
#define ROWS     (BATCH*SEQ)        /* 4096 */
#define QKV_COLS (3*HIDDEN)         /* 3840 */

// Scratch (device globals; no runtime allocation allowed)
__device__ __half g_x_h[(size_t)ROWS * HIDDEN];            // 10.5 MB
__device__ __half g_qkv_h[(size_t)ROWS * QKV_COLS];        // 31.5 MB
__device__ __half g_attn_h[(size_t)ROWS * HIDDEN];         // 10.5 MB
__device__ __half g_wqkvT_h[(size_t)QKV_COLS * HIDDEN];    //  9.8 MB
__device__ __half g_wprojT_h[(size_t)HIDDEN * HIDDEN];     //  3.3 MB

__device__ __forceinline__ void cp_async16(void* smem_dst, const void* gmem_src)
{
    uint32_t s = (uint32_t)__cvta_generic_to_shared(smem_dst);
    asm volatile("cp.async.cg.shared.global [%0], [%1], 16;\n"
                 :: "r"(s), "l"(gmem_src) : "memory");
}
__device__ __forceinline__ void cp_commit()
{
    asm volatile("cp.async.commit_group;\n" ::: "memory");
}

__device__ __forceinline__ void ldmx4(uint32_t* r, uint32_t addr)
{
    asm volatile("ldmatrix.sync.aligned.m8n8.x4.shared.b16 {%0,%1,%2,%3}, [%4];"
                 : "=r"(r[0]), "=r"(r[1]), "=r"(r[2]), "=r"(r[3]) : "r"(addr));
}
__device__ __forceinline__ void ldmx4_t(uint32_t* r, uint32_t addr)
{
    asm volatile("ldmatrix.sync.aligned.m8n8.x4.trans.shared.b16 {%0,%1,%2,%3}, [%4];"
                 : "=r"(r[0]), "=r"(r[1]), "=r"(r[2]), "=r"(r[3]) : "r"(addr));
}

// fp16x2 exp2 approx (MUFU, one op for two values)
__device__ __forceinline__ uint32_t h2exp2(uint32_t x)
{
    uint32_t r;
    asm("ex2.approx.f16x2 %0, %1;" : "=r"(r) : "r"(x));
    return r;
}

// fp16 HMMA: D(16x8,f32) = A(16x16,f16) x B(16x8,f16) + C
__device__ __forceinline__ void mma_f16(float* d, const uint32_t* a,
                                        uint32_t b0, uint32_t b1,
                                        const float* c)
{
    asm volatile(
        "mma.sync.aligned.m16n8k16.row.col.f32.f16.f16.f32 "
        "{%0,%1,%2,%3}, {%4,%5,%6,%7}, {%8,%9}, {%10,%11,%12,%13};\n"
        : "=f"(d[0]), "=f"(d[1]), "=f"(d[2]), "=f"(d[3])
        : "r"(a[0]), "r"(a[1]), "r"(a[2]), "r"(a[3]),
          "r"(b0), "r"(b1),
          "f"(c[0]), "f"(c[1]), "f"(c[2]), "f"(c[3]));
}

// ---------------------------------------------------------------------------
// fp16 tensor-core GEMM + bias (unchanged from R9-R11).
// ---------------------------------------------------------------------------
#define LDA_H   72
#define A_STG_H (128 * LDA_H)   /* 9216 halves */
#define GSTG3   3
#define GEMM_SMEM_BYTES (GSTG3 * 2 * A_STG_H * 2)   /* 110592 B */

template<bool OUT_HALF>
__global__ __launch_bounds__(256, 2)
void gemm_h_kernel(const __half* __restrict__ A,
                   const __half* __restrict__ BT,
                   const float* __restrict__ bias,
                   void* __restrict__ Cv,
                   int M, int N, int K)
{
    extern __shared__ __half hsm[];
    __half* Asm = hsm;
    __half* Bsm = hsm + GSTG3 * A_STG_H;

    const int tid  = threadIdx.x;
    const int w    = tid >> 5;
    const int lane = tid & 31;
    const int g    = lane >> 2;
    const int t    = lane & 3;
    const int wm   = w >> 1;
    const int wn   = w & 1;
    const int rowB = blockIdx.y * 128;
    const int colB = blockIdx.x * 128;

    const int frag_r = ((lane >> 3) & 1) * 8 + (lane & 7);
    const int frag_c = (lane >> 4) * 8;

    const uint32_t As_b = (uint32_t)__cvta_generic_to_shared(Asm);
    const uint32_t Bs_b = (uint32_t)__cvta_generic_to_shared(Bsm);

    const __half* Ag = A  + (size_t)rowB * K;
    const __half* Bg = BT + (size_t)colB * K;

    float acc[2][8][4];
    #pragma unroll
    for (int mt = 0; mt < 2; mt++)
        #pragma unroll
        for (int nt = 0; nt < 8; nt++)
            #pragma unroll
            for (int j = 0; j < 4; j++) acc[mt][nt][j] = 0.f;

    const int KT = K >> 6;

    auto load_stage = [&](int slot, int k0) {
        __half* Ad = Asm + slot * A_STG_H;
        __half* Bd = Bsm + slot * A_STG_H;
        #pragma unroll
        for (int j = 0; j < 4; j++) {
            int idx = tid + j * 256;
            int r = idx >> 3, c = idx & 7;
            cp_async16(Ad + r * LDA_H + c * 8, Ag + (size_t)r * K + k0 + c * 8);
            cp_async16(Bd + r * LDA_H + c * 8, Bg + (size_t)r * K + k0 + c * 8);
        }
    };

    load_stage(0, 0);  cp_commit();
    load_stage(1, 64); cp_commit();

    int slot = 0;
    for (int it = 0; it < KT; it++) {
        asm volatile("cp.async.wait_group 1;\n" ::: "memory");
        __syncthreads();

        {
            int ps = slot + 2; if (ps >= 3) ps -= 3;
            if (it + 2 < KT) load_stage(ps, (it + 2) << 6);
            cp_commit();
        }

        const uint32_t At = As_b + slot * A_STG_H * 2;
        const uint32_t Bt = Bs_b + slot * A_STG_H * 2;

        #pragma unroll
        for (int ks = 0; ks < 4; ks++) {
            const int col = ks * 16 + frag_c;
            uint32_t a[2][4];
            #pragma unroll
            for (int mt = 0; mt < 2; mt++) {
                int row = wm * 32 + mt * 16 + frag_r;
                ldmx4(a[mt], At + (row * LDA_H + col) * 2);
            }
            #pragma unroll
            for (int np = 0; np < 4; np++) {
                int row = wn * 64 + np * 16 + frag_r;
                uint32_t br[4];
                ldmx4(br, Bt + (row * LDA_H + col) * 2);
                mma_f16(acc[0][2 * np],     a[0], br[0], br[2], acc[0][2 * np]);
                mma_f16(acc[0][2 * np + 1], a[0], br[1], br[3], acc[0][2 * np + 1]);
                mma_f16(acc[1][2 * np],     a[1], br[0], br[2], acc[1][2 * np]);
                mma_f16(acc[1][2 * np + 1], a[1], br[1], br[3], acc[1][2 * np + 1]);
            }
        }
        if (++slot == 3) slot = 0;
    }

    #pragma unroll
    for (int mt = 0; mt < 2; mt++) {
        int m = rowB + wm * 32 + mt * 16 + g;
        #pragma unroll
        for (int nt = 0; nt < 8; nt++) {
            int n = colB + wn * 64 + nt * 8 + 2 * t;
            float2 bv = *(const float2*)(bias + n);
            if (OUT_HALF) {
                __half* C = (__half*)Cv;
                *(__half2*)(C + (size_t)m * N + n) =
                    __floats2half2_rn(acc[mt][nt][0] + bv.x, acc[mt][nt][1] + bv.y);
                *(__half2*)(C + (size_t)(m + 8) * N + n) =
                    __floats2half2_rn(acc[mt][nt][2] + bv.x, acc[mt][nt][3] + bv.y);
            } else {
                float* C = (float*)Cv;
                *(float2*)(C + (size_t)m * N + n) =
                    make_float2(acc[mt][nt][0] + bv.x, acc[mt][nt][1] + bv.y);
                *(float2*)(C + (size_t)(m + 8) * N + n) =
                    make_float2(acc[mt][nt][2] + bv.x, acc[mt][nt][3] + bv.y);
            }
        }
    }
}

// ---------------------------------------------------------------------------
// Unified pre-pass (unchanged from R10).
// ---------------------------------------------------------------------------
#define CONV_B  ((ROWS * HIDDEN) / (256 * 8))        /* 2560 */
#define TQ_BX   (QKV_COLS / 32)                      /* 120 */
#define TQ_B    (TQ_BX * (HIDDEN / 32))              /* 4800 */
#define TP_BX   (HIDDEN / 32)                        /* 40 */
#define TP_B    (TP_BX * (HIDDEN / 32))              /* 1600 */
#define PRE_B   (CONV_B + TQ_B + TP_B)               /* 8960 */

__device__ __forceinline__ void transpose_tile_f2h(
    const float* __restrict__ in, __half* __restrict__ out,
    int K, int N, int bx, int by, int tx, int ty)
{
    __shared__ float tsm[32][33];
    int xi = bx * 32 + tx;
    int yi = by * 32 + ty;
    #pragma unroll
    for (int j = 0; j < 4; j++)
        tsm[ty + j * 8][tx] = in[(size_t)(yi + j * 8) * N + xi];
    __syncthreads();
    int xo = by * 32 + tx;
    int yo = bx * 32 + ty;
    #pragma unroll
    for (int j = 0; j < 4; j++)
        out[(size_t)(yo + j * 8) * K + xo] =
            __float2half_rn(tsm[tx][ty + j * 8]);
}

__global__ void prepass_kernel(const float* __restrict__ x,
                               const float* __restrict__ qkv_w,
                               const float* __restrict__ proj_w,
                               __half* __restrict__ x_h,
                               __half* __restrict__ wqkvT,
                               __half* __restrict__ wprojT)
{
    const int bid = blockIdx.x;
    const int tid = threadIdx.x;

    if (bid < CONV_B) {
        size_t i0 = ((size_t)bid * 256 + tid) * 8;
        float4 v0 = *(const float4*)(x + i0);
        float4 v1 = *(const float4*)(x + i0 + 4);
        __half2 h[4];
        h[0] = __floats2half2_rn(v0.x, v0.y);
        h[1] = __floats2half2_rn(v0.z, v0.w);
        h[2] = __floats2half2_rn(v1.x, v1.y);
        h[3] = __floats2half2_rn(v1.z, v1.w);
        *(uint4*)(x_h + i0) = *(uint4*)h;
    } else if (bid < CONV_B + TQ_B) {
        int rb = bid - CONV_B;
        transpose_tile_f2h(qkv_w, wqkvT, HIDDEN, QKV_COLS,
                           rb % TQ_BX, rb / TQ_BX, tid & 31, tid >> 5);
    } else {
        int rb = bid - CONV_B - TQ_B;
        transpose_tile_f2h(proj_w, wprojT, HIDDEN, HIDDEN,
                           rb % TP_BX, rb / TP_BX, tid & 31, tid >> 5);
    }
}

// ---------------------------------------------------------------------------
// RoPE in half, vectorized (unchanged from R10).
// ---------------------------------------------------------------------------
__global__ void rope_h_kernel(__half* __restrict__ qkv,
                              const float* __restrict__ cosp,
                              const float* __restrict__ sinp)
{
    int idx = blockIdx.x * blockDim.x + threadIdx.x;
    const int total = BATCH * SEQ * 2 * HEADS * (HALF / 4);
    if (idx >= total) return;

    int c4 = idx % (HALF / 4);  idx /= (HALF / 4);
    int h  = idx % HEADS;       idx /= HEADS;
    int qk = idx % 2;           idx /= 2;
    int n  = idx % SEQ;
    int b  = idx / SEQ;
    int d  = 4 * c4;

    const float SCLF = rsqrtf((float)HDIM) * 1.44269504f;
    const float s = (qk == 0) ? SCLF : 1.f;

    __half* row = qkv + (size_t)(b * SEQ + n) * QKV_COLS + qk * HIDDEN + h * HDIM;
    __half2 lo2[2], hi2[2];
    *(uint2*)lo2 = *(const uint2*)(row + d);
    *(uint2*)hi2 = *(const uint2*)(row + d + HALF);
    float4 cl = *(const float4*)(cosp + n * HDIM + d);
    float4 ch = *(const float4*)(cosp + n * HDIM + d + HALF);
    float4 sl = *(const float4*)(sinp + n * HDIM + d);
    float4 sh = *(const float4*)(sinp + n * HDIM + d + HALF);

    float lo[4] = { __low2float(lo2[0]), __high2float(lo2[0]),
                    __low2float(lo2[1]), __high2float(lo2[1]) };
    float hi[4] = { __low2float(hi2[0]), __high2float(hi2[0]),
                    __low2float(hi2[1]), __high2float(hi2[1]) };

    __half2 olo[2], ohi[2];
    olo[0] = __floats2half2_rn(s * (lo[0] * cl.x - hi[0] * sl.x),
                               s * (lo[1] * cl.y - hi[1] * sl.y));
    olo[1] = __floats2half2_rn(s * (lo[2] * cl.z - hi[2] * sl.z),
                               s * (lo[3] * cl.w - hi[3] * sl.w));
    ohi[0] = __floats2half2_rn(s * (hi[0] * ch.x + lo[0] * sh.x),
                               s * (hi[1] * ch.y + lo[1] * sh.y));
    ohi[1] = __floats2half2_rn(s * (hi[2] * ch.z + lo[2] * sh.z),
                               s * (hi[3] * ch.w + lo[3] * sh.w));
    *(uint2*)(row + d)        = *(uint2*)olo;
    *(uint2*)(row + d + HALF) = *(uint2*)ohi;
}

// ---------------------------------------------------------------------------
// fp16 flash attention, 4-warp blocks, BQ=64 (R11 structure) with:
//  - softmax exp via ex2.approx.f16x2 (fused pack+exp, half the MUFU)
//  - row sums l via ones-column mma (constant B fragment; no fp32 sum/shfl)
// ---------------------------------------------------------------------------
#define BQ      64
#define NWRP    4
#define NTHR    (NWRP * 32)          /* 128 */
#define BKT     64
#define NITER   (SEQ / BKT)
#define LDK_H   88
#define LDP_H   72
#define P_H     (NWRP * 16 * LDP_H)  /* 4608 */
#define KBUF_H  (BKT * LDK_H)        /* 5632 */
#define ATTN_SMEM_BYTES ((P_H + 3 * KBUF_H) * 2)   /* 43008 B */

__global__ __launch_bounds__(NTHR, 4)
void flash_attn_h_kernel(const __half* __restrict__ qkv,
                         __half* __restrict__ out)
{
    extern __shared__ __half hsm[];
    __half* Pbase = hsm;
    __half* Ks    = hsm + P_H;
    __half* Vs    = Ks + 2 * KBUF_H;
    __half* Qs    = Ks;   // alias

    const int tid  = threadIdx.x;
    const int w    = tid >> 5;
    const int lane = tid & 31;
    const int g    = lane >> 2;
    const int t    = lane & 3;
    const int frag_r = ((lane >> 3) & 1) * 8 + (lane & 7);
    const int frag_c = (lane >> 4) * 8;

    const uint32_t P_b = (uint32_t)__cvta_generic_to_shared(Pbase);
    const uint32_t K_b = (uint32_t)__cvta_generic_to_shared(Ks);
    const uint32_t V_b = (uint32_t)__cvta_generic_to_shared(Vs);
    const uint32_t Q_b = K_b;

    const int q0 = blockIdx.x * BQ;
    const int h  = blockIdx.y & (HEADS - 1);
    const int b  = blockIdx.y >> 4;

    const __half* base = qkv + (size_t)(b * SEQ) * QKV_COLS;
    const __half* kb0  = base + HIDDEN + h * HDIM;
    const __half* vb0  = base + 2 * HIDDEN + h * HDIM;

    // ones-column B fragment: col 0 of an 8-col tile is held by lanes g==0
    const uint32_t ones_b = (g == 0) ? 0x3C003C00u : 0u;

    // ---- stage Q tile (64 rows), hoist fragments ----
    {
        const __half* qb = base + h * HDIM;
        #pragma unroll
        for (int j = 0; j < 5; j++) {
            int idx = tid + j * NTHR;
            int r = idx / 10, c = idx - r * 10;
            cp_async16(Qs + r * LDK_H + c * 8,
                       qb + (size_t)(q0 + r) * QKV_COLS + c * 8);
        }
        cp_commit();
        asm volatile("cp.async.wait_group 0;\n" ::: "memory");
        __syncthreads();
    }

    uint32_t qf[5][4];
    {
        const int row = w * 16 + frag_r;
        #pragma unroll
        for (int ks = 0; ks < 5; ks++)
            ldmx4(qf[ks], Q_b + (row * LDK_H + ks * 16 + frag_c) * 2);
    }
    __syncthreads();

    __half* Pw = Pbase + w * 16 * LDP_H;
    const uint32_t Pw_b = P_b + w * 16 * LDP_H * 2;

    float of[10][4];
    #pragma unroll
    for (int i = 0; i < 10; i++)
        #pragma unroll
        for (int j = 0; j < 4; j++) of[i][j] = 0.f;
    float lacc[4] = {0.f, 0.f, 0.f, 0.f};
    float m1 = -INFINITY, m2 = -INFINITY;

    auto load_tile = [&](__half* dst, const __half* src) {
        #pragma unroll
        for (int j = 0; j < 5; j++) {
            int idx = tid + j * NTHR;
            int r = idx / 10, c = idx - r * 10;
            cp_async16(dst + r * LDK_H + c * 8, src + (size_t)r * QKV_COLS + c * 8);
        }
    };

    load_tile(Ks, kb0);
    cp_commit();

    for (int it = 0; it < NITER; it++) {
        load_tile(Vs, vb0 + (size_t)(it * BKT) * QKV_COLS);
        cp_commit();
        if (it + 1 < NITER)
            load_tile(Ks + ((it + 1) & 1) * KBUF_H,
                      kb0 + (size_t)((it + 1) * BKT) * QKV_COLS);
        cp_commit();

        asm volatile("cp.async.wait_group 1;\n" ::: "memory");
        __syncthreads();

        const uint32_t Kt = K_b + (it & 1) * KBUF_H * 2;

        // ---- S = Q x K^T ----
        float sacc[8][4];
        #pragma unroll
        for (int nt = 0; nt < 8; nt++)
            #pragma unroll
            for (int j = 0; j < 4; j++) sacc[nt][j] = 0.f;

        #pragma unroll
        for (int ks = 0; ks < 5; ks++) {
            const int col = ks * 16 + frag_c;
            #pragma unroll
            for (int np = 0; np < 4; np++) {
                uint32_t br[4];
                ldmx4(br, Kt + ((np * 16 + frag_r) * LDK_H + col) * 2);
                mma_f16(sacc[2 * np],     qf[ks], br[0], br[2], sacc[2 * np]);
                mma_f16(sacc[2 * np + 1], qf[ks], br[1], br[3], sacc[2 * np + 1]);
            }
        }

        // ---- online softmax (max in fp32; exp via fp16x2 MUFU) ----
        float mx1 = -INFINITY, mx2 = -INFINITY;
        #pragma unroll
        for (int nt = 0; nt < 8; nt++) {
            mx1 = fmaxf(mx1, fmaxf(sacc[nt][0], sacc[nt][1]));
            mx2 = fmaxf(mx2, fmaxf(sacc[nt][2], sacc[nt][3]));
        }
        mx1 = fmaxf(mx1, __shfl_xor_sync(0xffffffff, mx1, 1));
        mx1 = fmaxf(mx1, __shfl_xor_sync(0xffffffff, mx1, 2));
        mx2 = fmaxf(mx2, __shfl_xor_sync(0xffffffff, mx2, 1));
        mx2 = fmaxf(mx2, __shfl_xor_sync(0xffffffff, mx2, 2));

        float mn1 = fmaxf(m1, mx1);
        float mn2 = fmaxf(m2, mx2);
        float a1 = exp2f(m1 - mn1);
        float a2 = exp2f(m2 - mn2);
        m1 = mn1; m2 = mn2;

        // rescale O and l accumulators
        #pragma unroll
        for (int nt = 0; nt < 10; nt++) {
            of[nt][0] *= a1; of[nt][1] *= a1;
            of[nt][2] *= a2; of[nt][3] *= a2;
        }
        lacc[0] *= a1; lacc[1] *= a1;
        lacc[2] *= a2; lacc[3] *= a2;

        // ---- P = exp2(S - m) as half2, straight into the strip ----
        __syncwarp();
        #pragma unroll
        for (int nt = 0; nt < 8; nt++) {
            __half2 d01 = __floats2half2_rn(sacc[nt][0] - mn1, sacc[nt][1] - mn1);
            __half2 d23 = __floats2half2_rn(sacc[nt][2] - mn2, sacc[nt][3] - mn2);
            *(uint32_t*)(Pw + g * LDP_H + nt * 8 + 2 * t) =
                h2exp2(*(uint32_t*)&d01);
            *(uint32_t*)(Pw + (g + 8) * LDP_H + nt * 8 + 2 * t) =
                h2exp2(*(uint32_t*)&d23);
        }
        __syncwarp();

        // ---- O += P x V; l += P x 1 (constant ones fragment) ----
        #pragma unroll
        for (int ks = 0; ks < 4; ks++) {
            uint32_t af[4];
            ldmx4(af, Pw_b + (frag_r * LDP_H + ks * 16 + frag_c) * 2);
            const int vrow = ks * 16 + frag_r;
            #pragma unroll
            for (int vp = 0; vp < 5; vp++) {
                uint32_t br[4];
                ldmx4_t(br, V_b + (vrow * LDK_H + vp * 16 + frag_c) * 2);
                mma_f16(of[2 * vp],     af, br[0], br[1], of[2 * vp]);
                mma_f16(of[2 * vp + 1], af, br[2], br[3], of[2 * vp + 1]);
            }
            mma_f16(lacc, af, ones_b, ones_b, lacc);
        }
        __syncthreads();
    }

    // ---- epilogue: row sums live in lane (g*4).lacc[0]/lacc[2] (col 0) ----
    float l1 = __shfl_sync(0xffffffff, lacc[0], lane & 28);
    float l2 = __shfl_sync(0xffffffff, lacc[2], lane & 28);
    const float inv1 = 1.f / l1;
    const float inv2 = 1.f / l2;
    const int r1 = q0 + w * 16 + g;
    __half* ob = out + (size_t)(b * SEQ) * HIDDEN + h * HDIM;
    #pragma unroll
    for (int nt = 0; nt < 10; nt++) {
        int c = nt * 8 + 2 * t;
        *(__half2*)(ob + (size_t)r1 * HIDDEN + c) =
            __floats2half2_rn(of[nt][0] * inv1, of[nt][1] * inv1);
        *(__half2*)(ob + (size_t)(r1 + 8) * HIDDEN + c) =
            __floats2half2_rn(of[nt][2] * inv2, of[nt][3] * inv2);
    }
}

// ---------------------------------------------------------------------------
extern "C" void kernel_launch(void* const* d_in, const int* in_sizes, int n_in,
                              void* d_out, int out_size)
{
    const float* x      = (const float*)d_in[0];
    const float* cosp   = (const float*)d_in[1];
    const float* sinp   = (const float*)d_in[2];
    const float* qkv_w  = (const float*)d_in[3];
    const float* qkv_b  = (const float*)d_in[4];
    const float* proj_w = (const float*)d_in[5];
    const float* proj_b = (const float*)d_in[6];
    float* out = (float*)d_out;

    __half *x_h, *qkv_h, *attn_h, *wqkvT_h, *wprojT_h;
    cudaGetSymbolAddress((void**)&x_h,      g_x_h);
    cudaGetSymbolAddress((void**)&qkv_h,    g_qkv_h);
    cudaGetSymbolAddress((void**)&attn_h,   g_attn_h);
    cudaGetSymbolAddress((void**)&wqkvT_h,  g_wqkvT_h);
    cudaGetSymbolAddress((void**)&wprojT_h, g_wprojT_h);

    static int attr_set = 0;
    if (!attr_set) {
        cudaFuncSetAttribute(gemm_h_kernel<true>,
                             cudaFuncAttributeMaxDynamicSharedMemorySize, GEMM_SMEM_BYTES);
        cudaFuncSetAttribute(gemm_h_kernel<false>,
                             cudaFuncAttributeMaxDynamicSharedMemorySize, GEMM_SMEM_BYTES);
        cudaFuncSetAttribute(flash_attn_h_kernel,
                             cudaFuncAttributeMaxDynamicSharedMemorySize, ATTN_SMEM_BYTES);
        attr_set = 1;
    }

    // 0) single fused pre-pass
    prepass_kernel<<<PRE_B, 256>>>(x, qkv_w, proj_w, x_h, wqkvT_h, wprojT_h);

    // 1) QKV GEMM
    {
        dim3 grid(QKV_COLS / 128, ROWS / 128);
        gemm_h_kernel<true><<<grid, 256, GEMM_SMEM_BYTES>>>(
            x_h, wqkvT_h, qkv_b, qkv_h, ROWS, QKV_COLS, HIDDEN);
    }

    // 2) RoPE
    {
        int total = BATCH * SEQ * 2 * HEADS * (HALF / 4);
        rope_h_kernel<<<(total + 255) / 256, 256>>>(qkv_h, cosp, sinp);
    }

    // 3) fp16 flash attention
    {
        dim3 grid(SEQ / BQ, BATCH * HEADS);   // (32, 32)
        flash_attn_h_kernel<<<grid, NTHR, ATTN_SMEM_BYTES>>>(qkv_h, attn_h);
    }

    // 4) Proj GEMM -> fp32 out
    {
        dim3 grid(HIDDEN / 128, ROWS / 128);
        gemm_h_kernel<false><<<grid, 256, GEMM_SMEM_BYTES>>>(
            attn_h, wprojT_h, proj_b, out, ROWS, HIDDEN, HIDDEN);
    }
}

// round 13
// speedup vs baseline: 68.9547x; 1.0056x over previous
#include <cuda_runtime.h>
#include <cuda_fp16.h>
#include <math.h>
#include <stdint.h>

#define HIDDEN   1280
#define HEADS    16
#define HDIM     80
#define HALF     40
#define BATCH    2
#define SEQ      2048
#define ROWS     (BATCH*SEQ)        /* 4096 */
#define QKV_COLS (3*HIDDEN)         /* 3840 */

// Scratch (device globals; no runtime allocation allowed)
__device__ __half g_x_h[(size_t)ROWS * HIDDEN];            // 10.5 MB
__device__ __half g_qkv_h[(size_t)ROWS * QKV_COLS];        // 31.5 MB
__device__ __half g_attn_h[(size_t)ROWS * HIDDEN];         // 10.5 MB
__device__ __half g_wqkvT_h[(size_t)QKV_COLS * HIDDEN];    //  9.8 MB
__device__ __half g_wprojT_h[(size_t)HIDDEN * HIDDEN];     //  3.3 MB

__device__ __forceinline__ void cp_async16(void* smem_dst, const void* gmem_src)
{
    uint32_t s = (uint32_t)__cvta_generic_to_shared(smem_dst);
    asm volatile("cp.async.cg.shared.global [%0], [%1], 16;\n"
                 :: "r"(s), "l"(gmem_src) : "memory");
}
__device__ __forceinline__ void cp_commit()
{
    asm volatile("cp.async.commit_group;\n" ::: "memory");
}

__device__ __forceinline__ void ldmx4(uint32_t* r, uint32_t addr)
{
    asm volatile("ldmatrix.sync.aligned.m8n8.x4.shared.b16 {%0,%1,%2,%3}, [%4];"
                 : "=r"(r[0]), "=r"(r[1]), "=r"(r[2]), "=r"(r[3]) : "r"(addr));
}
__device__ __forceinline__ void ldmx4_t(uint32_t* r, uint32_t addr)
{
    asm volatile("ldmatrix.sync.aligned.m8n8.x4.trans.shared.b16 {%0,%1,%2,%3}, [%4];"
                 : "=r"(r[0]), "=r"(r[1]), "=r"(r[2]), "=r"(r[3]) : "r"(addr));
}

// fp16x2 exp2 approx (MUFU, one op for two values)
__device__ __forceinline__ uint32_t h2exp2(uint32_t x)
{
    uint32_t r;
    asm("ex2.approx.f16x2 %0, %1;" : "=r"(r) : "r"(x));
    return r;
}

// fp16 HMMA: D(16x8,f32) = A(16x16,f16) x B(16x8,f16) + C
__device__ __forceinline__ void mma_f16(float* d, const uint32_t* a,
                                        uint32_t b0, uint32_t b1,
                                        const float* c)
{
    asm volatile(
        "mma.sync.aligned.m16n8k16.row.col.f32.f16.f16.f32 "
        "{%0,%1,%2,%3}, {%4,%5,%6,%7}, {%8,%9}, {%10,%11,%12,%13};\n"
        : "=f"(d[0]), "=f"(d[1]), "=f"(d[2]), "=f"(d[3])
        : "r"(a[0]), "r"(a[1]), "r"(a[2]), "r"(a[3]),
          "r"(b0), "r"(b1),
          "f"(c[0]), "f"(c[1]), "f"(c[2]), "f"(c[3]));
}

// ---------------------------------------------------------------------------
// fp16 tensor-core GEMM + bias (unchanged from R9-R12).
// ---------------------------------------------------------------------------
#define LDA_H   72
#define A_STG_H (128 * LDA_H)   /* 9216 halves */
#define GSTG3   3
#define GEMM_SMEM_BYTES (GSTG3 * 2 * A_STG_H * 2)   /* 110592 B */

template<bool OUT_HALF>
__global__ __launch_bounds__(256, 2)
void gemm_h_kernel(const __half* __restrict__ A,
                   const __half* __restrict__ BT,
                   const float* __restrict__ bias,
                   void* __restrict__ Cv,
                   int M, int N, int K)
{
    extern __shared__ __half hsm[];
    __half* Asm = hsm;
    __half* Bsm = hsm + GSTG3 * A_STG_H;

    const int tid  = threadIdx.x;
    const int w    = tid >> 5;
    const int lane = tid & 31;
    const int g    = lane >> 2;
    const int t    = lane & 3;
    const int wm   = w >> 1;
    const int wn   = w & 1;
    const int rowB = blockIdx.y * 128;
    const int colB = blockIdx.x * 128;

    const int frag_r = ((lane >> 3) & 1) * 8 + (lane & 7);
    const int frag_c = (lane >> 4) * 8;

    const uint32_t As_b = (uint32_t)__cvta_generic_to_shared(Asm);
    const uint32_t Bs_b = (uint32_t)__cvta_generic_to_shared(Bsm);

    const __half* Ag = A  + (size_t)rowB * K;
    const __half* Bg = BT + (size_t)colB * K;

    float acc[2][8][4];
    #pragma unroll
    for (int mt = 0; mt < 2; mt++)
        #pragma unroll
        for (int nt = 0; nt < 8; nt++)
            #pragma unroll
            for (int j = 0; j < 4; j++) acc[mt][nt][j] = 0.f;

    const int KT = K >> 6;

    auto load_stage = [&](int slot, int k0) {
        __half* Ad = Asm + slot * A_STG_H;
        __half* Bd = Bsm + slot * A_STG_H;
        #pragma unroll
        for (int j = 0; j < 4; j++) {
            int idx = tid + j * 256;
            int r = idx >> 3, c = idx & 7;
            cp_async16(Ad + r * LDA_H + c * 8, Ag + (size_t)r * K + k0 + c * 8);
            cp_async16(Bd + r * LDA_H + c * 8, Bg + (size_t)r * K + k0 + c * 8);
        }
    };

    load_stage(0, 0);  cp_commit();
    load_stage(1, 64); cp_commit();

    int slot = 0;
    for (int it = 0; it < KT; it++) {
        asm volatile("cp.async.wait_group 1;\n" ::: "memory");
        __syncthreads();

        {
            int ps = slot + 2; if (ps >= 3) ps -= 3;
            if (it + 2 < KT) load_stage(ps, (it + 2) << 6);
            cp_commit();
        }

        const uint32_t At = As_b + slot * A_STG_H * 2;
        const uint32_t Bt = Bs_b + slot * A_STG_H * 2;

        #pragma unroll
        for (int ks = 0; ks < 4; ks++) {
            const int col = ks * 16 + frag_c;
            uint32_t a[2][4];
            #pragma unroll
            for (int mt = 0; mt < 2; mt++) {
                int row = wm * 32 + mt * 16 + frag_r;
                ldmx4(a[mt], At + (row * LDA_H + col) * 2);
            }
            #pragma unroll
            for (int np = 0; np < 4; np++) {
                int row = wn * 64 + np * 16 + frag_r;
                uint32_t br[4];
                ldmx4(br, Bt + (row * LDA_H + col) * 2);
                mma_f16(acc[0][2 * np],     a[0], br[0], br[2], acc[0][2 * np]);
                mma_f16(acc[0][2 * np + 1], a[0], br[1], br[3], acc[0][2 * np + 1]);
                mma_f16(acc[1][2 * np],     a[1], br[0], br[2], acc[1][2 * np]);
                mma_f16(acc[1][2 * np + 1], a[1], br[1], br[3], acc[1][2 * np + 1]);
            }
        }
        if (++slot == 3) slot = 0;
    }

    #pragma unroll
    for (int mt = 0; mt < 2; mt++) {
        int m = rowB + wm * 32 + mt * 16 + g;
        #pragma unroll
        for (int nt = 0; nt < 8; nt++) {
            int n = colB + wn * 64 + nt * 8 + 2 * t;
            float2 bv = *(const float2*)(bias + n);
            if (OUT_HALF) {
                __half* C = (__half*)Cv;
                *(__half2*)(C + (size_t)m * N + n) =
                    __floats2half2_rn(acc[mt][nt][0] + bv.x, acc[mt][nt][1] + bv.y);
                *(__half2*)(C + (size_t)(m + 8) * N + n) =
                    __floats2half2_rn(acc[mt][nt][2] + bv.x, acc[mt][nt][3] + bv.y);
            } else {
                float* C = (float*)Cv;
                *(float2*)(C + (size_t)m * N + n) =
                    make_float2(acc[mt][nt][0] + bv.x, acc[mt][nt][1] + bv.y);
                *(float2*)(C + (size_t)(m + 8) * N + n) =
                    make_float2(acc[mt][nt][2] + bv.x, acc[mt][nt][3] + bv.y);
            }
        }
    }
}

// ---------------------------------------------------------------------------
// Unified pre-pass (unchanged from R10).
// ---------------------------------------------------------------------------
#define CONV_B  ((ROWS * HIDDEN) / (256 * 8))        /* 2560 */
#define TQ_BX   (QKV_COLS / 32)                      /* 120 */
#define TQ_B    (TQ_BX * (HIDDEN / 32))              /* 4800 */
#define TP_BX   (HIDDEN / 32)                        /* 40 */
#define TP_B    (TP_BX * (HIDDEN / 32))              /* 1600 */
#define PRE_B   (CONV_B + TQ_B + TP_B)               /* 8960 */

__device__ __forceinline__ void transpose_tile_f2h(
    const float* __restrict__ in, __half* __restrict__ out,
    int K, int N, int bx, int by, int tx, int ty)
{
    __shared__ float tsm[32][33];
    int xi = bx * 32 + tx;
    int yi = by * 32 + ty;
    #pragma unroll
    for (int j = 0; j < 4; j++)
        tsm[ty + j * 8][tx] = in[(size_t)(yi + j * 8) * N + xi];
    __syncthreads();
    int xo = by * 32 + tx;
    int yo = bx * 32 + ty;
    #pragma unroll
    for (int j = 0; j < 4; j++)
        out[(size_t)(yo + j * 8) * K + xo] =
            __float2half_rn(tsm[tx][ty + j * 8]);
}

__global__ void prepass_kernel(const float* __restrict__ x,
                               const float* __restrict__ qkv_w,
                               const float* __restrict__ proj_w,
                               __half* __restrict__ x_h,
                               __half* __restrict__ wqkvT,
                               __half* __restrict__ wprojT)
{
    const int bid = blockIdx.x;
    const int tid = threadIdx.x;

    if (bid < CONV_B) {
        size_t i0 = ((size_t)bid * 256 + tid) * 8;
        float4 v0 = *(const float4*)(x + i0);
        float4 v1 = *(const float4*)(x + i0 + 4);
        __half2 h[4];
        h[0] = __floats2half2_rn(v0.x, v0.y);
        h[1] = __floats2half2_rn(v0.z, v0.w);
        h[2] = __floats2half2_rn(v1.x, v1.y);
        h[3] = __floats2half2_rn(v1.z, v1.w);
        *(uint4*)(x_h + i0) = *(uint4*)h;
    } else if (bid < CONV_B + TQ_B) {
        int rb = bid - CONV_B;
        transpose_tile_f2h(qkv_w, wqkvT, HIDDEN, QKV_COLS,
                           rb % TQ_BX, rb / TQ_BX, tid & 31, tid >> 5);
    } else {
        int rb = bid - CONV_B - TQ_B;
        transpose_tile_f2h(proj_w, wprojT, HIDDEN, HIDDEN,
                           rb % TP_BX, rb / TP_BX, tid & 31, tid >> 5);
    }
}

// ---------------------------------------------------------------------------
// RoPE in half, vectorized (unchanged from R10).
// ---------------------------------------------------------------------------
__global__ void rope_h_kernel(__half* __restrict__ qkv,
                              const float* __restrict__ cosp,
                              const float* __restrict__ sinp)
{
    int idx = blockIdx.x * blockDim.x + threadIdx.x;
    const int total = BATCH * SEQ * 2 * HEADS * (HALF / 4);
    if (idx >= total) return;

    int c4 = idx % (HALF / 4);  idx /= (HALF / 4);
    int h  = idx % HEADS;       idx /= HEADS;
    int qk = idx % 2;           idx /= 2;
    int n  = idx % SEQ;
    int b  = idx / SEQ;
    int d  = 4 * c4;

    const float SCLF = rsqrtf((float)HDIM) * 1.44269504f;
    const float s = (qk == 0) ? SCLF : 1.f;

    __half* row = qkv + (size_t)(b * SEQ + n) * QKV_COLS + qk * HIDDEN + h * HDIM;
    __half2 lo2[2], hi2[2];
    *(uint2*)lo2 = *(const uint2*)(row + d);
    *(uint2*)hi2 = *(const uint2*)(row + d + HALF);
    float4 cl = *(const float4*)(cosp + n * HDIM + d);
    float4 ch = *(const float4*)(cosp + n * HDIM + d + HALF);
    float4 sl = *(const float4*)(sinp + n * HDIM + d);
    float4 sh = *(const float4*)(sinp + n * HDIM + d + HALF);

    float lo[4] = { __low2float(lo2[0]), __high2float(lo2[0]),
                    __low2float(lo2[1]), __high2float(lo2[1]) };
    float hi[4] = { __low2float(hi2[0]), __high2float(hi2[0]),
                    __low2float(hi2[1]), __high2float(hi2[1]) };

    __half2 olo[2], ohi[2];
    olo[0] = __floats2half2_rn(s * (lo[0] * cl.x - hi[0] * sl.x),
                               s * (lo[1] * cl.y - hi[1] * sl.y));
    olo[1] = __floats2half2_rn(s * (lo[2] * cl.z - hi[2] * sl.z),
                               s * (lo[3] * cl.w - hi[3] * sl.w));
    ohi[0] = __floats2half2_rn(s * (hi[0] * ch.x + lo[0] * sh.x),
                               s * (hi[1] * ch.y + lo[1] * sh.y));
    ohi[1] = __floats2half2_rn(s * (hi[2] * ch.z + lo[2] * sh.z),
                               s * (hi[3] * ch.w + lo[3] * sh.w));
    *(uint2*)(row + d)        = *(uint2*)olo;
    *(uint2*)(row + d + HALF) = *(uint2*)ohi;
}

// ---------------------------------------------------------------------------
// fp16 flash attention, 4-warp blocks, BQ=64, REGISTER-RESIDENT P:
// the S-accumulator fragment packs directly into the PV A-operand fragment
// (S n-tiles {2ks,2ks+1} -> PV k-chunk ks), so exp2 outputs feed the PV mma
// from registers. No P smem strip, no STS/LDSM round-trip.
// ---------------------------------------------------------------------------
#define BQ      64
#define NWRP    4
#define NTHR    (NWRP * 32)          /* 128 */
#define BKT     64
#define NITER   (SEQ / BKT)
#define LDK_H   88
#define KBUF_H  (BKT * LDK_H)        /* 5632 */
#define ATTN_SMEM_BYTES (3 * KBUF_H * 2)   /* 33792 B */

__global__ __launch_bounds__(NTHR, 4)
void flash_attn_h_kernel(const __half* __restrict__ qkv,
                         __half* __restrict__ out)
{
    extern __shared__ __half hsm[];
    __half* Ks = hsm;                 // 2 x [BKT][LDK_H]
    __half* Vs = Ks + 2 * KBUF_H;     // 1 x [BKT][LDK_H]
    __half* Qs = Ks;                  // alias (64*88 = KBUF_H)

    const int tid  = threadIdx.x;
    const int w    = tid >> 5;
    const int lane = tid & 31;
    const int g    = lane >> 2;
    const int t    = lane & 3;
    const int frag_r = ((lane >> 3) & 1) * 8 + (lane & 7);
    const int frag_c = (lane >> 4) * 8;

    const uint32_t K_b = (uint32_t)__cvta_generic_to_shared(Ks);
    const uint32_t V_b = (uint32_t)__cvta_generic_to_shared(Vs);
    const uint32_t Q_b = K_b;

    const int q0 = blockIdx.x * BQ;
    const int h  = blockIdx.y & (HEADS - 1);
    const int b  = blockIdx.y >> 4;

    const __half* base = qkv + (size_t)(b * SEQ) * QKV_COLS;
    const __half* kb0  = base + HIDDEN + h * HDIM;
    const __half* vb0  = base + 2 * HIDDEN + h * HDIM;

    // ones-column B fragment: col 0 of an 8-col tile lives on lanes g==0
    const uint32_t ones_b = (g == 0) ? 0x3C003C00u : 0u;

    // ---- stage Q tile (64 rows), hoist fragments ----
    {
        const __half* qb = base + h * HDIM;
        #pragma unroll
        for (int j = 0; j < 5; j++) {
            int idx = tid + j * NTHR;
            int r = idx / 10, c = idx - r * 10;
            cp_async16(Qs + r * LDK_H + c * 8,
                       qb + (size_t)(q0 + r) * QKV_COLS + c * 8);
        }
        cp_commit();
        asm volatile("cp.async.wait_group 0;\n" ::: "memory");
        __syncthreads();
    }

    uint32_t qf[5][4];
    {
        const int row = w * 16 + frag_r;
        #pragma unroll
        for (int ks = 0; ks < 5; ks++)
            ldmx4(qf[ks], Q_b + (row * LDK_H + ks * 16 + frag_c) * 2);
    }
    __syncthreads();   // Qs dead -> K buffers free

    float of[10][4];
    #pragma unroll
    for (int i = 0; i < 10; i++)
        #pragma unroll
        for (int j = 0; j < 4; j++) of[i][j] = 0.f;
    float lacc[4] = {0.f, 0.f, 0.f, 0.f};
    float m1 = -INFINITY, m2 = -INFINITY;

    auto load_tile = [&](__half* dst, const __half* src) {
        #pragma unroll
        for (int j = 0; j < 5; j++) {
            int idx = tid + j * NTHR;
            int r = idx / 10, c = idx - r * 10;
            cp_async16(dst + r * LDK_H + c * 8, src + (size_t)r * QKV_COLS + c * 8);
        }
    };

    load_tile(Ks, kb0);
    cp_commit();

    for (int it = 0; it < NITER; it++) {
        load_tile(Vs, vb0 + (size_t)(it * BKT) * QKV_COLS);
        cp_commit();
        if (it + 1 < NITER)
            load_tile(Ks + ((it + 1) & 1) * KBUF_H,
                      kb0 + (size_t)((it + 1) * BKT) * QKV_COLS);
        cp_commit();

        asm volatile("cp.async.wait_group 1;\n" ::: "memory");
        __syncthreads();

        const uint32_t Kt = K_b + (it & 1) * KBUF_H * 2;

        // ---- S = Q x K^T ----
        float sacc[8][4];
        #pragma unroll
        for (int nt = 0; nt < 8; nt++)
            #pragma unroll
            for (int j = 0; j < 4; j++) sacc[nt][j] = 0.f;

        #pragma unroll
        for (int ks = 0; ks < 5; ks++) {
            const int col = ks * 16 + frag_c;
            #pragma unroll
            for (int np = 0; np < 4; np++) {
                uint32_t br[4];
                ldmx4(br, Kt + ((np * 16 + frag_r) * LDK_H + col) * 2);
                mma_f16(sacc[2 * np],     qf[ks], br[0], br[2], sacc[2 * np]);
                mma_f16(sacc[2 * np + 1], qf[ks], br[1], br[3], sacc[2 * np + 1]);
            }
        }

        // ---- online softmax (max in fp32; exp via fp16x2 MUFU) ----
        float mx1 = -INFINITY, mx2 = -INFINITY;
        #pragma unroll
        for (int nt = 0; nt < 8; nt++) {
            mx1 = fmaxf(mx1, fmaxf(sacc[nt][0], sacc[nt][1]));
            mx2 = fmaxf(mx2, fmaxf(sacc[nt][2], sacc[nt][3]));
        }
        mx1 = fmaxf(mx1, __shfl_xor_sync(0xffffffff, mx1, 1));
        mx1 = fmaxf(mx1, __shfl_xor_sync(0xffffffff, mx1, 2));
        mx2 = fmaxf(mx2, __shfl_xor_sync(0xffffffff, mx2, 1));
        mx2 = fmaxf(mx2, __shfl_xor_sync(0xffffffff, mx2, 2));

        float mn1 = fmaxf(m1, mx1);
        float mn2 = fmaxf(m2, mx2);
        float a1 = exp2f(m1 - mn1);
        float a2 = exp2f(m2 - mn2);
        m1 = mn1; m2 = mn2;

        // rescale O and l accumulators
        #pragma unroll
        for (int nt = 0; nt < 10; nt++) {
            of[nt][0] *= a1; of[nt][1] *= a1;
            of[nt][2] *= a2; of[nt][3] *= a2;
        }
        lacc[0] *= a1; lacc[1] *= a1;
        lacc[2] *= a2; lacc[3] *= a2;

        // ---- P = exp2(S - m) packed DIRECTLY into PV A-fragments ----
        // PV k-chunk ks <- S n-tiles 2ks (a0,a1) and 2ks+1 (a2,a3).
        uint32_t paf[4][4];
        #pragma unroll
        for (int ks = 0; ks < 4; ks++) {
            __half2 d0 = __floats2half2_rn(sacc[2 * ks][0] - mn1, sacc[2 * ks][1] - mn1);
            __half2 d1 = __floats2half2_rn(sacc[2 * ks][2] - mn2, sacc[2 * ks][3] - mn2);
            __half2 d2 = __floats2half2_rn(sacc[2 * ks + 1][0] - mn1, sacc[2 * ks + 1][1] - mn1);
            __half2 d3 = __floats2half2_rn(sacc[2 * ks + 1][2] - mn2, sacc[2 * ks + 1][3] - mn2);
            paf[ks][0] = h2exp2(*(uint32_t*)&d0);
            paf[ks][1] = h2exp2(*(uint32_t*)&d1);
            paf[ks][2] = h2exp2(*(uint32_t*)&d2);
            paf[ks][3] = h2exp2(*(uint32_t*)&d3);
        }

        // ---- O += P x V; l += P x 1 ----
        #pragma unroll
        for (int ks = 0; ks < 4; ks++) {
            const int vrow = ks * 16 + frag_r;
            #pragma unroll
            for (int vp = 0; vp < 5; vp++) {
                uint32_t br[4];
                ldmx4_t(br, V_b + (vrow * LDK_H + vp * 16 + frag_c) * 2);
                mma_f16(of[2 * vp],     paf[ks], br[0], br[1], of[2 * vp]);
                mma_f16(of[2 * vp + 1], paf[ks], br[2], br[3], of[2 * vp + 1]);
            }
            mma_f16(lacc, paf[ks], ones_b, ones_b, lacc);
        }
        __syncthreads();
    }

    // ---- epilogue: row sums live in col 0 lanes (t==0) ----
    float l1 = __shfl_sync(0xffffffff, lacc[0], lane & 28);
    float l2 = __shfl_sync(0xffffffff, lacc[2], lane & 28);
    const float inv1 = 1.f / l1;
    const float inv2 = 1.f / l2;
    const int r1 = q0 + w * 16 + g;
    __half* ob = out + (size_t)(b * SEQ) * HIDDEN + h * HDIM;
    #pragma unroll
    for (int nt = 0; nt < 10; nt++) {
        int c = nt * 8 + 2 * t;
        *(__half2*)(ob + (size_t)r1 * HIDDEN + c) =
            __floats2half2_rn(of[nt][0] * inv1, of[nt][1] * inv1);
        *(__half2*)(ob + (size_t)(r1 + 8) * HIDDEN + c) =
            __floats2half2_rn(of[nt][2] * inv2, of[nt][3] * inv2);
    }
}

// ---------------------------------------------------------------------------
extern "C" void kernel_launch(void* const* d_in, const int* in_sizes, int n_in,
                              void* d_out, int out_size)
{
    const float* x      = (const float*)d_in[0];
    const float* cosp   = (const float*)d_in[1];
    const float* sinp   = (const float*)d_in[2];
    const float* qkv_w  = (const float*)d_in[3];
    const float* qkv_b  = (const float*)d_in[4];
    const float* proj_w = (const float*)d_in[5];
    const float* proj_b = (const float*)d_in[6];
    float* out = (float*)d_out;

    __half *x_h, *qkv_h, *attn_h, *wqkvT_h, *wprojT_h;
    cudaGetSymbolAddress((void**)&x_h,      g_x_h);
    cudaGetSymbolAddress((void**)&qkv_h,    g_qkv_h);
    cudaGetSymbolAddress((void**)&attn_h,   g_attn_h);
    cudaGetSymbolAddress((void**)&wqkvT_h,  g_wqkvT_h);
    cudaGetSymbolAddress((void**)&wprojT_h, g_wprojT_h);

    static int attr_set = 0;
    if (!attr_set) {
        cudaFuncSetAttribute(gemm_h_kernel<true>,
                             cudaFuncAttributeMaxDynamicSharedMemorySize, GEMM_SMEM_BYTES);
        cudaFuncSetAttribute(gemm_h_kernel<false>,
                             cudaFuncAttributeMaxDynamicSharedMemorySize, GEMM_SMEM_BYTES);
        cudaFuncSetAttribute(flash_attn_h_kernel,
                             cudaFuncAttributeMaxDynamicSharedMemorySize, ATTN_SMEM_BYTES);
        attr_set = 1;
    }

    // 0) single fused pre-pass
    prepass_kernel<<<PRE_B, 256>>>(x, qkv_w, proj_w, x_h, wqkvT_h, wprojT_h);

    // 1) QKV GEMM
    {
        dim3 grid(QKV_COLS / 128, ROWS / 128);
        gemm_h_kernel<true><<<grid, 256, GEMM_SMEM_BYTES>>>(
            x_h, wqkvT_h, qkv_b, qkv_h, ROWS, QKV_COLS, HIDDEN);
    }

    // 2) RoPE
    {
        int total = BATCH * SEQ * 2 * HEADS * (HALF / 4);
        rope_h_kernel<<<(total + 255) / 256, 256>>>(qkv_h, cosp, sinp);
    }

    // 3) fp16 flash attention (register-resident P)
    {
        dim3 grid(SEQ / BQ, BATCH * HEADS);   // (32, 32)
        flash_attn_h_kernel<<<grid, NTHR, ATTN_SMEM_BYTES>>>(qkv_h, attn_h);
    }

    // 4) Proj GEMM -> fp32 out
    {
        dim3 grid(HIDDEN / 128, ROWS / 128);
        gemm_h_kernel<false><<<grid, 256, GEMM_SMEM_BYTES>>>(
            attn_h, wprojT_h, proj_b, out, ROWS, HIDDEN, HIDDEN);
    }
}